// round 3
// baseline (speedup 1.0000x reference)
#include <cuda_runtime.h>
#include <math.h>

// Problem constants: B=64, T=12, N=512, H=64, TD=32, ED=16, CHEB_K=3, D_HEADS=8
// BT = 768. Effective GCN channels = 64 (channel 0 is identically zero).

// -------------------- static device scratch --------------------------------
static __device__ float g_At [512*512];          // A^T  (At[m][n] = A[n][m])
static __device__ float g_S2t[512*512];          // (2A^2 - I)^T
static __device__ float g_kb [64*512*64];        // relu(k) per (b,n)
static __device__ float g_vb [64*512*64];        // relu(v) per (b,n)
static __device__ float g_xq [64*512*64];        // X @ Wq[32:96] (no bias/relu)
static __device__ float g_xw0[64*512*64];        // X @ ta_w[0]
static __device__ float g_aq [64*12*64];         // STE_Q @ Wq[0:32] + bq
static __device__ float g_ak [64*64];
static __device__ float g_av [64*64];
static __device__ float g_sm [64*512*12*8];      // softmax weights [b][n][t][d]
static __device__ float g_xg1[768*192*512];      // [bt][j][n], j: 0-63 de, 64-127 A@, 128-191 S2@
static __device__ float g_xg2[768*192*512];
static __device__ float g_W1 [768*192*128];      // per-bt GCN1 weights (packed, chan0 dropped)
static __device__ float g_W2 [768*192*64];
static __device__ float g_b1 [768*128];
static __device__ float g_b2 [768*64];
static __device__ float g_wp1[32*192*128];       // packed gwp
static __device__ float g_w1b[192*128];          // packed gw
static __device__ float g_wp2[32*192*64];
static __device__ float g_w2b[192*64];
static __device__ float g_zr [768*512*128];      // GCN1 out, pre-sigmoid  [bt][n][o]
static __device__ float g_hc [768*512*64];       // GCN2 out, pre-tanh     [bt][n][o]

// -------------------- adjacency: A^T ---------------------------------------
__global__ void k_A(const float* __restrict__ E, float* __restrict__ At)
{
    __shared__ float Es[512*16];
    __shared__ float red[512];
    const int tid = threadIdx.x;
    const int n   = blockIdx.x;
    for (int i = tid; i < 512*16; i += 512) Es[i] = E[i];
    __syncthreads();
    float acc = 0.f;
#pragma unroll
    for (int d = 0; d < 16; d++) acc += Es[n*16+d]*Es[tid*16+d];
    acc = fmaxf(acc, 0.f);
    red[tid] = acc; __syncthreads();
    for (int s = 256; s > 0; s >>= 1){ if (tid < s) red[tid] = fmaxf(red[tid], red[tid+s]); __syncthreads(); }
    float mx = red[0]; __syncthreads();
    float e = expf(acc - mx);
    red[tid] = e; __syncthreads();
    for (int s = 256; s > 0; s >>= 1){ if (tid < s) red[tid] += red[tid+s]; __syncthreads(); }
    At[tid*512 + n] = e / red[0];
}

__global__ void k_fixdiag(float* __restrict__ S)   // subtract identity
{
    int i = threadIdx.x;
    S[i*512 + i] -= 1.f;
}

// -------------------- generic SGEMM, A row-major ---------------------------
// C[M,N] = alpha * A[M,K] @ B[K,N] (+ colBias), batched via blockIdx.z strides
template<int BM,int BN,int BK,int TM,int TN,int NT>
__global__ void __launch_bounds__(NT) gemm_rr_k(
    const float* __restrict__ Abase, long aStr,
    const float* __restrict__ Bbase, long bStr,
    float* __restrict__ Cbase, long cStr,
    int lda, int ldb, int ldc, int K,
    const float* __restrict__ colBias, float alpha)
{
    __shared__ float As[BK][BM];
    __shared__ float Bs[BK][BN];
    const int tid = threadIdx.x;
    const int bz  = blockIdx.z;
    const int m0  = blockIdx.y*BM;
    const int n0  = blockIdx.x*BN;
    const float* A = Abase + (long)bz*aStr + (long)m0*lda;
    const float* B = Bbase + (long)bz*bStr + n0;
    float*       C = Cbase + (long)bz*cStr + (long)m0*ldc + n0;
    const int tx = tid % (BN/TN);
    const int ty = tid / (BN/TN);
    float acc[TM][TN];
#pragma unroll
    for (int i=0;i<TM;i++)
#pragma unroll
        for (int j=0;j<TN;j++) acc[i][j]=0.f;

    for (int k0 = 0; k0 < K; k0 += BK){
        for (int li = tid; li < BM*BK/4; li += NT){
            int m  = li/(BK/4), kv = li%(BK/4);
            float4 v = *(const float4*)(A + (long)m*lda + k0 + kv*4);
            As[kv*4+0][m]=v.x; As[kv*4+1][m]=v.y; As[kv*4+2][m]=v.z; As[kv*4+3][m]=v.w;
        }
        for (int li = tid; li < BN*BK/4; li += NT){
            int k  = li/(BN/4), nv = li%(BN/4);
            *(float4*)&Bs[k][nv*4] = *(const float4*)(B + (long)(k0+k)*ldb + nv*4);
        }
        __syncthreads();
#pragma unroll
        for (int kk = 0; kk < BK; kk++){
            float a[TM], bb[TN];
#pragma unroll
            for (int i=0;i<TM;i+=4) *(float4*)&a[i]  = *(const float4*)&As[kk][ty*TM+i];
#pragma unroll
            for (int j=0;j<TN;j+=4) *(float4*)&bb[j] = *(const float4*)&Bs[kk][tx*TN+j];
#pragma unroll
            for (int i=0;i<TM;i++)
#pragma unroll
                for (int j=0;j<TN;j++) acc[i][j] += a[i]*bb[j];
        }
        __syncthreads();
    }
#pragma unroll
    for (int i=0;i<TM;i++){
        float* crow = C + (long)(ty*TM+i)*ldc + tx*TN;
#pragma unroll
        for (int j=0;j<TN;j+=4){
            float4 v;
            v.x=acc[i][j+0]*alpha; v.y=acc[i][j+1]*alpha;
            v.z=acc[i][j+2]*alpha; v.w=acc[i][j+3]*alpha;
            if (colBias){
                const float* cb = colBias + n0 + tx*TN + j;
                v.x+=cb[0]; v.y+=cb[1]; v.z+=cb[2]; v.w+=cb[3];
            }
            *(float4*)(crow + j) = v;
        }
    }
}

// -------------------- generic SGEMM, A K-major (A[k][m]), per-batch bias ---
template<int BM,int BN,int BK,int TM,int TN,int NT>
__global__ void __launch_bounds__(NT) gemm_km_k(
    const float* __restrict__ Abase, long aStr,
    const float* __restrict__ Bbase, long bStr,
    float* __restrict__ Cbase, long cStr,
    int lda, int ldb, int ldc, int K,
    const float* __restrict__ bias, int biasStr)
{
    __shared__ float As[BK][BM];
    __shared__ float Bs[BK][BN];
    const int tid = threadIdx.x;
    const int bz  = blockIdx.z;
    const int m0  = blockIdx.y*BM;
    const int n0  = blockIdx.x*BN;
    const float* A = Abase + (long)bz*aStr + m0;
    const float* B = Bbase + (long)bz*bStr + n0;
    float*       C = Cbase + (long)bz*cStr + (long)m0*ldc + n0;
    const int tx = tid % (BN/TN);
    const int ty = tid / (BN/TN);
    float acc[TM][TN];
#pragma unroll
    for (int i=0;i<TM;i++)
#pragma unroll
        for (int j=0;j<TN;j++) acc[i][j]=0.f;

    for (int k0 = 0; k0 < K; k0 += BK){
        for (int li = tid; li < BM*BK/4; li += NT){
            int k = li/(BM/4), mv = li%(BM/4);
            *(float4*)&As[k][mv*4] = *(const float4*)(A + (long)(k0+k)*lda + mv*4);
        }
        for (int li = tid; li < BN*BK/4; li += NT){
            int k = li/(BN/4), nv = li%(BN/4);
            *(float4*)&Bs[k][nv*4] = *(const float4*)(B + (long)(k0+k)*ldb + nv*4);
        }
        __syncthreads();
#pragma unroll
        for (int kk = 0; kk < BK; kk++){
            float a[TM], bb[TN];
#pragma unroll
            for (int i=0;i<TM;i+=4) *(float4*)&a[i]  = *(const float4*)&As[kk][ty*TM+i];
#pragma unroll
            for (int j=0;j<TN;j+=4) *(float4*)&bb[j] = *(const float4*)&Bs[kk][tx*TN+j];
#pragma unroll
            for (int i=0;i<TM;i++)
#pragma unroll
                for (int j=0;j<TN;j++) acc[i][j] += a[i]*bb[j];
        }
        __syncthreads();
    }
#pragma unroll
    for (int i=0;i<TM;i++){
        float* crow = C + (long)(ty*TM+i)*ldc + tx*TN;
#pragma unroll
        for (int j=0;j<TN;j+=4){
            const float* cb = bias + (long)bz*biasStr + n0 + tx*TN + j;
            float4 v;
            v.x=acc[i][j+0]+cb[0]; v.y=acc[i][j+1]+cb[1];
            v.z=acc[i][j+2]+cb[2]; v.w=acc[i][j+3]+cb[3];
            *(float4*)(crow + j) = v;
        }
    }
}

// -------------------- pack gwp/uwp (drop channel 0) ------------------------
__global__ void k_pack(const float* __restrict__ wp, const float* __restrict__ w,
                       float* __restrict__ pwp, float* __restrict__ pw, int O)
{
    int idx = blockIdx.x*blockDim.x + threadIdx.x;
    if (blockIdx.y == 0){
        if (idx < 32*192*O){
            int o = idx % O; int r = idx / O;
            int c = r % 64;  int k = (r/64)%3; int d = r/192;
            pwp[idx] = wp[(((d*3 + k)*65) + (c+1))*O + o];
        }
    } else {
        if (idx < 192*O){
            int o = idx % O; int r = idx / O;
            int c = r % 64;  int k = r/64;
            pw[idx] = w[((k*65) + (c+1))*O + o];
        }
    }
}

// -------------------- bias vectors: temb@bp + b0 ---------------------------
__global__ void k_bvec(const float* __restrict__ temb, const float* __restrict__ bp,
                       const float* __restrict__ b0, float* __restrict__ out, int O)
{
    int bt = blockIdx.x; int o = threadIdx.x;
    float acc = b0[o];
#pragma unroll
    for (int d = 0; d < 32; d++) acc += temb[bt*32+d]*bp[d*O+o];
    out[bt*O+o] = acc;
}

// -------------------- small STE projections --------------------------------
__global__ void k_small(const float* __restrict__ ne1, const float* __restrict__ ne2,
                        const float* __restrict__ Wq, const float* __restrict__ bq,
                        const float* __restrict__ Wk, const float* __restrict__ bk,
                        const float* __restrict__ Wv, const float* __restrict__ bv,
                        float* __restrict__ aq, float* __restrict__ ak, float* __restrict__ av)
{
    int b = blockIdx.x, y = blockIdx.y, h = threadIdx.x;
    const float *src, *W, *bias; float* out;
    if (y < 12)      { src = ne2 + (b*12+y)*32;  W = Wq; bias = bq; out = aq + (b*12+y)*64; }
    else if (y == 12){ src = ne1 + (b*12+11)*32; W = Wk; bias = bk; out = ak + b*64; }
    else             { src = ne1 + (b*12+11)*32; W = Wv; bias = bv; out = av + b*64; }
    float acc = bias[h];
#pragma unroll
    for (int d = 0; d < 32; d++) acc += src[d]*W[d*64+h];
    out[h] = acc;
}

// -------------------- X projections (xq, k, v, xw0) ------------------------
__global__ void __launch_bounds__(256) k_proj(
    const float* __restrict__ X,
    const float* __restrict__ Wq, const float* __restrict__ Wk,
    const float* __restrict__ Wv, const float* __restrict__ taw,
    const float* __restrict__ ak, const float* __restrict__ av,
    float* __restrict__ xq, float* __restrict__ kb,
    float* __restrict__ vb, float* __restrict__ xw0)
{
    __shared__ float Xs[64][64];
    __shared__ float Ws[64][64];
    const int tid  = threadIdx.x;
    const int mode = blockIdx.y;
    const int m0   = blockIdx.x*64;
    const int b    = m0 >> 9;
    const float* W = (mode==0)? Wq+2048 : (mode==1)? Wk+2048 : (mode==2)? Wv+2048 : taw;
    for (int li = tid; li < 1024; li += 256){
        int m = li>>4, kv = li&15;
        float4 v = *(const float4*)(X + (long)(m0+m)*64 + kv*4);
        Xs[kv*4+0][m]=v.x; Xs[kv*4+1][m]=v.y; Xs[kv*4+2][m]=v.z; Xs[kv*4+3][m]=v.w;
        *(float4*)&Ws[m][kv*4] = *(const float4*)(W + m*64 + kv*4);
    }
    __syncthreads();
    const int tx = tid&15, ty = tid>>4;
    float acc[4][4];
#pragma unroll
    for (int i=0;i<4;i++)
#pragma unroll
        for (int j=0;j<4;j++) acc[i][j]=0.f;
#pragma unroll
    for (int kk = 0; kk < 64; kk++){
        float a[4], bb[4];
        *(float4*)a  = *(const float4*)&Xs[kk][ty*4];
        *(float4*)bb = *(const float4*)&Ws[kk][tx*4];
#pragma unroll
        for (int i=0;i<4;i++)
#pragma unroll
            for (int j=0;j<4;j++) acc[i][j] += a[i]*bb[j];
    }
    float* outp = (mode==0)? xq : (mode==1)? kb : (mode==2)? vb : xw0;
#pragma unroll
    for (int i=0;i<4;i++){
        int m = m0 + ty*4 + i;
        float4 r;
        if (mode==1 || mode==2){
            const float* bias = ((mode==1)? ak:av) + b*64 + tx*4;
            r.x=fmaxf(acc[i][0]+bias[0],0.f); r.y=fmaxf(acc[i][1]+bias[1],0.f);
            r.z=fmaxf(acc[i][2]+bias[2],0.f); r.w=fmaxf(acc[i][3]+bias[3],0.f);
        } else {
            r.x=acc[i][0]; r.y=acc[i][1]; r.z=acc[i][2]; r.w=acc[i][3];
        }
        *(float4*)(outp + (long)m*64 + tx*4) = r;
    }
}

// -------------------- attention scores + softmax ---------------------------
__global__ void __launch_bounds__(256) k_attn(
    const float* __restrict__ aq, const float* __restrict__ xq,
    const float* __restrict__ kb, float* __restrict__ sm_out)
{
    __shared__ float aq_s[768];
    const int b = blockIdx.y;
    const int tid = threadIdx.x, lane = tid&31, w = tid>>5;
    for (int i = tid; i < 768; i += 256) aq_s[i] = aq[b*768 + i];
    __syncthreads();
    const int n0 = blockIdx.x*32 + w*4;
    for (int j = 0; j < 4; j++){
        int bn = b*512 + n0 + j;
        float xq0 = xq[bn*64 + lane],      xq1 = xq[bn*64 + 32 + lane];
        float k0  = kb[bn*64 + lane],      k1  = kb[bn*64 + 32 + lane];
        float sc0[12], sc1[12];
#pragma unroll
        for (int t = 0; t < 12; t++){
            float q0 = fmaxf(aq_s[t*64 + lane] + xq0, 0.f);
            float q1 = fmaxf(aq_s[t*64 + 32 + lane] + xq1, 0.f);
            float p0 = q0*k0, p1 = q1*k1;
#pragma unroll
            for (int o = 1; o < 8; o <<= 1){
                p0 += __shfl_xor_sync(0xffffffffu, p0, o);
                p1 += __shfl_xor_sync(0xffffffffu, p1, o);
            }
            sc0[t] = p0; sc1[t] = p1;
        }
        float m0 = -1e30f, m1 = -1e30f;
#pragma unroll
        for (int t = 0; t < 12; t++){ m0 = fmaxf(m0, sc0[t]); m1 = fmaxf(m1, sc1[t]); }
        float s0 = 0.f, s1 = 0.f;
#pragma unroll
        for (int t = 0; t < 12; t++){ sc0[t] = expf(sc0[t]-m0); s0 += sc0[t];
                                      sc1[t] = expf(sc1[t]-m1); s1 += sc1[t]; }
        float r0 = 1.f/s0, r1 = 1.f/s1;
        if ((lane & 7) == 0){
            int d = lane >> 3;
#pragma unroll
            for (int t = 0; t < 12; t++){
                sm_out[bn*96 + t*8 + d]     = sc0[t]*r0;
                sm_out[bn*96 + t*8 + 4 + d] = sc1[t]*r1;
            }
        }
    }
}

// -------------------- build de (channel-major, into xg1 rows 0-63) ---------
__global__ void __launch_bounds__(256) k_debuild(
    const float* __restrict__ sm, const float* __restrict__ vb,
    const float* __restrict__ xw0, const float* __restrict__ taw,
    const float* __restrict__ tab, float* __restrict__ xg1)
{
    __shared__ float taw1s[64][64];
    __shared__ float wvT[64][33];
    __shared__ float xw0s[64][33];
    const int b = blockIdx.z, t = blockIdx.y, n0 = blockIdx.x*32;
    const int tid = threadIdx.x;
    for (int i = tid; i < 4096; i += 256)
        taw1s[i>>6][i&63] = taw[4096 + i];   // ta_w[1]
    for (int idx = tid; idx < 2048; idx += 256){
        int nl = idx >> 6, i = idx & 63;
        int bn = b*512 + n0 + nl;
        float s = sm[bn*96 + t*8 + (i>>3)];
        wvT[i][nl]  = s * vb[bn*64 + i];
        xw0s[i][nl] = xw0[bn*64 + i];        // here i plays the role of o
    }
    __syncthreads();
    const int tx = tid & 15, ty = tid >> 4;  // ty->o (x4), tx->n (x2)
    float acc[4][2] = {};
#pragma unroll
    for (int i = 0; i < 64; i++){
        float4 a = *(const float4*)&taw1s[i][ty*4];
        float b0 = wvT[i][tx*2], b1 = wvT[i][tx*2+1];
        acc[0][0]+=a.x*b0; acc[0][1]+=a.x*b1;
        acc[1][0]+=a.y*b0; acc[1][1]+=a.y*b1;
        acc[2][0]+=a.z*b0; acc[2][1]+=a.z*b1;
        acc[3][0]+=a.w*b0; acc[3][1]+=a.w*b1;
    }
    long base = (long)(b*12 + t)*98304;
#pragma unroll
    for (int oi = 0; oi < 4; oi++){
        int o = ty*4 + oi;
        float bias = tab[o];
        float2 v;
        v.x = acc[oi][0] + xw0s[o][tx*2]   + bias;
        v.y = acc[oi][1] + xw0s[o][tx*2+1] + bias;
        *(float2*)&xg1[base + (long)o*512 + n0 + tx*2] = v;
    }
}

// -------------------- gate: cand = sigmoid(z) * de (transposed write) ------
__global__ void k_gate(const float* __restrict__ zr, const float* __restrict__ xg1,
                       float* __restrict__ xg2)
{
    __shared__ float s[32][33];
    const int bt = blockIdx.y, n0 = blockIdx.x*32;
    const int tx = threadIdx.x, ty = threadIdx.y;
    for (int ch = 0; ch < 2; ch++){
        int c0 = ch*32;
        s[ty][tx] = zr[bt*65536 + (n0+ty)*128 + c0 + tx];
        __syncthreads();
        int c = c0 + ty;
        float z = 1.f/(1.f + expf(-s[tx][ty]));
        long idx = (long)bt*98304 + (long)c*512 + n0 + tx;
        xg2[idx] = z * xg1[idx];
        __syncthreads();
    }
}

// -------------------- final: state blend + output head ---------------------
__global__ void __launch_bounds__(256) k_final(
    const float* __restrict__ zr, const float* __restrict__ xg1,
    const float* __restrict__ hc, const float* __restrict__ out_w,
    const float* __restrict__ out_b, float* __restrict__ out)
{
    __shared__ float de_s[64][33];
    __shared__ float red[8][32];
    __shared__ float w_s[64];
    const int bt = blockIdx.y, n0 = blockIdx.x*32;
    const int tt = bt % 12;
    const int tid = threadIdx.x;
    if (tid < 64) w_s[tid] = out_w[tt*64 + tid];
    for (int i = tid; i < 2048; i += 256){
        int h = i >> 5, nl = i & 31;
        de_s[h][nl] = xg1[(long)bt*98304 + h*512 + n0 + nl];
    }
    __syncthreads();
    const int nl = tid & 31, hg = tid >> 5;
    const int rg_off = bt*65536 + (n0+nl)*128 + 64;
    const int hc_off = bt*32768 + (n0+nl)*64;
    float partial = 0.f;
#pragma unroll
    for (int j = 0; j < 8; j++){
        int h = hg*8 + j;
        float rg  = 1.f/(1.f + expf(-zr[rg_off + h]));
        float hcv = tanhf(hc[hc_off + h]);
        float st  = rg*de_s[h][nl] + (1.f-rg)*hcv;
        partial  += st * w_s[h];
    }
    red[hg][nl] = partial;
    __syncthreads();
    if (tid < 32){
        float sum = 0.f;
#pragma unroll
        for (int g = 0; g < 8; g++) sum += red[g][tid];
        out[bt*512 + n0 + tid] = sum + out_b[tt];
    }
}

// ===========================================================================
extern "C" void kernel_launch(void* const* d_in, const int* in_sizes, int n_in,
                              void* d_out, int out_size)
{
    const float* h_n  = (const float*)d_in[2];   // (1,64,512,64)
    const float* ne1  = (const float*)d_in[3];   // (64,12,32)
    const float* ne2  = (const float*)d_in[4];   // (64,12,32)
    const float* E    = (const float*)d_in[5];   // (512,16)
    const float* Wq   = (const float*)d_in[6];
    const float* bq   = (const float*)d_in[7];
    const float* Wk   = (const float*)d_in[8];
    const float* bk   = (const float*)d_in[9];
    const float* Wv   = (const float*)d_in[10];
    const float* bv   = (const float*)d_in[11];
    const float* taw  = (const float*)d_in[12];  // (2,64,64)
    const float* tab  = (const float*)d_in[13];
    const float* gwp  = (const float*)d_in[14];  // (32,3,65,128)
    const float* gw   = (const float*)d_in[15];
    const float* gbp  = (const float*)d_in[16];
    const float* gb   = (const float*)d_in[17];
    const float* uwp  = (const float*)d_in[18];  // (32,3,65,64)
    const float* uw   = (const float*)d_in[19];
    const float* ubp  = (const float*)d_in[20];
    const float* ub   = (const float*)d_in[21];
    const float* outw = (const float*)d_in[22];  // (12,64,1)
    const float* outb = (const float*)d_in[23];  // (12,1)
    float* out = (float*)d_out;

    float *At, *S2t, *kb2, *vb2, *xq, *xw0, *aq, *ak, *av, *sm;
    float *xg1, *xg2, *W1, *W2, *b1, *b2, *wp1, *w1b, *wp2, *w2b, *zr, *hc;
    cudaGetSymbolAddress((void**)&At,  g_At);
    cudaGetSymbolAddress((void**)&S2t, g_S2t);
    cudaGetSymbolAddress((void**)&kb2, g_kb);
    cudaGetSymbolAddress((void**)&vb2, g_vb);
    cudaGetSymbolAddress((void**)&xq,  g_xq);
    cudaGetSymbolAddress((void**)&xw0, g_xw0);
    cudaGetSymbolAddress((void**)&aq,  g_aq);
    cudaGetSymbolAddress((void**)&ak,  g_ak);
    cudaGetSymbolAddress((void**)&av,  g_av);
    cudaGetSymbolAddress((void**)&sm,  g_sm);
    cudaGetSymbolAddress((void**)&xg1, g_xg1);
    cudaGetSymbolAddress((void**)&xg2, g_xg2);
    cudaGetSymbolAddress((void**)&W1,  g_W1);
    cudaGetSymbolAddress((void**)&W2,  g_W2);
    cudaGetSymbolAddress((void**)&b1,  g_b1);
    cudaGetSymbolAddress((void**)&b2,  g_b2);
    cudaGetSymbolAddress((void**)&wp1, g_wp1);
    cudaGetSymbolAddress((void**)&w1b, g_w1b);
    cudaGetSymbolAddress((void**)&wp2, g_wp2);
    cudaGetSymbolAddress((void**)&w2b, g_w2b);
    cudaGetSymbolAddress((void**)&zr,  g_zr);
    cudaGetSymbolAddress((void**)&hc,  g_hc);

    // ---- adjacency & supports (shared across all bt) ----
    k_A<<<512, 512>>>(E, At);
    gemm_rr_k<64,64,16,4,4,256><<<dim3(8,8,1), 256>>>(
        At, 0, At, 0, S2t, 0, 512, 512, 512, 512, nullptr, 2.f);
    k_fixdiag<<<1, 512>>>(S2t);

    // ---- pack GCN weights, build per-bt W and bias ----
    k_pack<<<dim3(3072,2), 256>>>(gwp, gw, wp1, w1b, 128);
    k_pack<<<dim3(1536,2), 256>>>(uwp, uw, wp2, w2b, 64);
    k_bvec<<<768, 128>>>(ne2, gbp, gb, b1, 128);
    k_bvec<<<768, 64 >>>(ne2, ubp, ub, b2, 64);
    gemm_rr_k<64,64,16,4,4,256><<<dim3(384,12,1), 256>>>(   // W1 = temb @ wp1 + w1b
        ne2, 0, wp1, 0, W1, 0, 32, 24576, 24576, 32, w1b, 1.f);
    gemm_rr_k<64,64,16,4,4,256><<<dim3(192,12,1), 256>>>(   // W2 = temb @ wp2 + w2b
        ne2, 0, wp2, 0, W2, 0, 32, 12288, 12288, 32, w2b, 1.f);

    // ---- attention path ----
    k_small<<<dim3(64,14), 64>>>(ne1, ne2, Wq, bq, Wk, bk, Wv, bv, aq, ak, av);
    k_proj<<<dim3(512,4), 256>>>(h_n, Wq, Wk, Wv, taw, ak, av, xq, kb2, vb2, xw0);
    k_attn<<<dim3(16,64), 256>>>(aq, xq, kb2, sm);
    k_debuild<<<dim3(16,12,64), 256>>>(sm, vb2, xw0, taw, tab, xg1);  // de -> xg1 rows 0-63

    // ---- GCN1: supports + contraction ----
    gemm_rr_k<64,64,16,4,4,256><<<dim3(8,1,768), 256>>>(    // rows 64-127: x @ A^T
        xg1, 98304, At, 0, xg1 + 64*512, 98304, 512, 512, 512, 512, nullptr, 1.f);
    gemm_rr_k<64,64,16,4,4,256><<<dim3(8,1,768), 256>>>(    // rows 128-191: x @ S2^T
        xg1, 98304, S2t, 0, xg1 + 128*512, 98304, 512, 512, 512, 512, nullptr, 1.f);
    gemm_km_k<64,64,16,4,4,256><<<dim3(2,8,768), 256>>>(    // zr = xg1^T @ W1 + b1
        xg1, 98304, W1, 24576, zr, 65536, 512, 128, 128, 192, b1, 128);

    // ---- GCN2: gate, supports, contraction ----
    k_gate<<<dim3(16,768), dim3(32,32)>>>(zr, xg1, xg2);
    gemm_rr_k<64,64,16,4,4,256><<<dim3(8,1,768), 256>>>(
        xg2, 98304, At, 0, xg2 + 64*512, 98304, 512, 512, 512, 512, nullptr, 1.f);
    gemm_rr_k<64,64,16,4,4,256><<<dim3(8,1,768), 256>>>(
        xg2, 98304, S2t, 0, xg2 + 128*512, 98304, 512, 512, 512, 512, nullptr, 1.f);
    gemm_km_k<64,64,16,4,4,256><<<dim3(1,8,768), 256>>>(
        xg2, 98304, W2, 12288, hc, 32768, 512, 64, 64, 192, b2, 64);

    // ---- final blend + output head ----
    k_final<<<dim3(16,768), 256>>>(zr, xg1, hc, outw, outb, out);
}

// round 5
// speedup vs baseline: 2.4077x; 2.4077x over previous
#include <cuda_runtime.h>
#include <math.h>
#include <stdint.h>

// Problem constants: B=64, T=12, N=512, H=64, TD=32, ED=16, CHEB_K=3, D_HEADS=8
// BT = 768. Effective GCN channels = 64 (channel 0 is identically zero).

// -------------------- static device scratch --------------------------------
static __device__ float g_Arm[512*512];            // A row-major
static __device__ float g_S2 [512*512];            // 2A^2 - I row-major
static __device__ uint32_t g_Atf [512*512];        // tf32 copies
static __device__ uint32_t g_S2tf[512*512];
static __device__ float g_kb [64*512*64];
static __device__ float g_vb [64*512*64];
static __device__ float g_xq [64*512*64];
static __device__ float g_xw0[64*512*64];
static __device__ float g_aq [64*12*64];
static __device__ float g_ak [64*64];
static __device__ float g_av [64*64];
static __device__ float g_sm [64*512*12*8];
static __device__ float g_de [768*64*512];         // de f32 (channel-major)
static __device__ uint32_t g_xgtf1[768*192*512];   // tf32 [bt][j][n] j:0-63 de,64-127 A@,128-191 S2@
static __device__ uint32_t g_xgtf2[768*192*512];   // same for cand
static __device__ float g_W1 [768*192*128];
static __device__ float g_W2 [768*192*64];
static __device__ uint32_t g_W1tf[768*192*128];
static __device__ uint32_t g_W2tf[768*192*64];
static __device__ float g_b1 [768*128];
static __device__ float g_b2 [768*64];
static __device__ float g_wp1[32*192*128];
static __device__ float g_w1b[192*128];
static __device__ float g_wp2[32*192*64];
static __device__ float g_w2b[192*64];
static __device__ float g_zr [768*512*128];
static __device__ float g_hc [768*512*64];

// -------------------- helpers ----------------------------------------------
__device__ __forceinline__ uint32_t f2tf32(float f){
    uint32_t u; asm("cvt.rna.tf32.f32 %0, %1;" : "=r"(u) : "f"(f)); return u;
}
__device__ __forceinline__ void cp16(void* dst, const void* src){
    uint32_t d;
    asm("{ .reg .u64 t; cvta.to.shared.u64 t, %1; cvt.u32.u64 %0, t; }" : "=r"(d) : "l"(dst));
    asm volatile("cp.async.cg.shared.global [%0], [%1], 16;" :: "r"(d), "l"(src));
}
__device__ __forceinline__ void mma_tf32(float* c, const uint32_t* a, const uint32_t* b){
    asm volatile(
        "mma.sync.aligned.m16n8k8.row.col.f32.tf32.tf32.f32 "
        "{%0,%1,%2,%3}, {%4,%5,%6,%7}, {%8,%9}, {%0,%1,%2,%3};"
        : "+f"(c[0]),"+f"(c[1]),"+f"(c[2]),"+f"(c[3])
        : "r"(a[0]),"r"(a[1]),"r"(a[2]),"r"(a[3]), "r"(b[0]),"r"(b[1]));
}

// -------------------- support GEMM (mma.sync tf32) -------------------------
// grid (4 n-tiles, 384 bt-pairs), 256 threads.
// C[r][n] = sum_k x[r][k]*Badj[n][k];  r=0..127 -> bt=2p+(r>>6), c=r&63.
// x rows come from xgtf[bt][0..63][*]; output written tf32 to outp rows.
__global__ void __launch_bounds__(256) k_supp_mma(
    const uint32_t* __restrict__ xtf,   // g_xgtf base (rows 0-63 per bt used)
    const uint32_t* __restrict__ Btf,   // [512][512] tf32 row-major
    uint32_t* __restrict__ outp)        // xgtf + rowOffset*512
{
    constexpr int LD = 36;              // 32 + 4 pad
    extern __shared__ uint32_t sh[];
    uint32_t* As = sh;                  // [2][128*36]
    uint32_t* Bs = sh + 2*128*LD;       // [2][128*36]
    const int tid = threadIdx.x, wid = tid>>5, lane = tid&31;
    const int g = lane>>2, tg = lane&3;
    const int p = blockIdx.y, n0 = blockIdx.x*128;
    const int wm = wid & 1, wn = wid >> 1;
    const int mbase = wm*64, nbase = wn*32;

    float c[4][4][4];
#pragma unroll
    for (int i=0;i<4;i++)
#pragma unroll
        for (int j=0;j<4;j++)
#pragma unroll
            for (int q=0;q<4;q++) c[i][j][q]=0.f;

    auto load = [&](int ch, int sel){
        uint32_t* a = As + sel*128*LD;
        uint32_t* b = Bs + sel*128*LD;
        const int k0 = ch*32;
#pragma unroll
        for (int it = 0; it < 4; it++){
            int lin = tid + it*256;
            int r = lin >> 3, q = lin & 7;
            cp16(a + r*LD + q*4,
                 xtf + (size_t)(2*p + (r>>6))*98304 + (size_t)(r&63)*512 + k0 + q*4);
            cp16(b + r*LD + q*4,
                 Btf + (size_t)(n0 + r)*512 + k0 + q*4);
        }
        asm volatile("cp.async.commit_group;" ::: "memory");
    };

    load(0, 0);
    for (int i = 0; i < 16; i++){
        const int cur = i & 1;
        if (i + 1 < 16){
            load(i+1, cur^1);
            asm volatile("cp.async.wait_group 1;" ::: "memory");
        } else {
            asm volatile("cp.async.wait_group 0;" ::: "memory");
        }
        __syncthreads();
        const uint32_t* a = As + cur*128*LD;
        const uint32_t* b = Bs + cur*128*LD;
#pragma unroll
        for (int ks = 0; ks < 4; ks++){
            uint32_t af[4][4], bf[4][2];
#pragma unroll
            for (int mt = 0; mt < 4; mt++){
                int row = mbase + mt*16 + g;
                af[mt][0] = a[ row   *LD + ks*8 + tg    ];
                af[mt][1] = a[(row+8)*LD + ks*8 + tg    ];
                af[mt][2] = a[ row   *LD + ks*8 + tg + 4];
                af[mt][3] = a[(row+8)*LD + ks*8 + tg + 4];
            }
#pragma unroll
            for (int nt = 0; nt < 4; nt++){
                int nr = nbase + nt*8 + g;
                bf[nt][0] = b[nr*LD + ks*8 + tg    ];
                bf[nt][1] = b[nr*LD + ks*8 + tg + 4];
            }
#pragma unroll
            for (int mt = 0; mt < 4; mt++)
#pragma unroll
                for (int nt = 0; nt < 4; nt++)
                    mma_tf32(c[mt][nt], af[mt], bf[nt]);
        }
        __syncthreads();
    }

    // epilogue: convert to tf32, store
#pragma unroll
    for (int mt = 0; mt < 4; mt++){
        int r0 = mbase + mt*16 + g;
#pragma unroll
        for (int half = 0; half < 2; half++){
            int r = r0 + half*8;
            uint32_t* orow = outp + (size_t)(2*p + (r>>6))*98304 + (size_t)(r&63)*512 + n0 + nbase;
#pragma unroll
            for (int nt = 0; nt < 4; nt++){
                uint2 u;
                u.x = f2tf32(c[mt][nt][half*2+0]);
                u.y = f2tf32(c[mt][nt][half*2+1]);
                *(uint2*)(orow + nt*8 + tg*2) = u;
            }
        }
    }
}

// -------------------- contraction GEMM (mma.sync tf32) ---------------------
// C[n][o] = sum_k xg[k][n] * W[k][o] + bias[o];  per-bt batch.
// BN in {128,64}; warp tile = (MT*16) x (NTT*8); WARPS_M warps along m.
template<int BN, int MT, int NTT, int WARPS_M>
__global__ void __launch_bounds__(256) k_ctr_mma(
    const uint32_t* __restrict__ xtf,   // [768][192][512] tf32
    const uint32_t* __restrict__ Wtf,   // [768][192][BN] tf32
    const float* __restrict__ bias,     // [768][BN]
    float* __restrict__ outp)           // [768][512][BN]
{
    constexpr int LDA = 132;            // 128 + 4
    constexpr int LDB = BN + 4;
    constexpr int NC  = 6;              // K=192 / 32
    extern __shared__ uint32_t sh[];
    uint32_t* As = sh;                  // [2][32*LDA]
    uint32_t* Bs = sh + 2*32*LDA;       // [2][32*LDB]
    const int tid = threadIdx.x, wid = tid>>5, lane = tid&31;
    const int g = lane>>2, tg = lane&3;
    const int bt = blockIdx.y, m0 = blockIdx.x*128;
    const int wm = wid % WARPS_M, wn = wid / WARPS_M;
    const int mbase = wm*(MT*16), nbase = wn*(NTT*8);
    const uint32_t* Ab = xtf + (size_t)bt*98304 + m0;
    const uint32_t* Bb = Wtf + (size_t)bt*192*BN;

    float c[MT][NTT][4];
#pragma unroll
    for (int i=0;i<MT;i++)
#pragma unroll
        for (int j=0;j<NTT;j++)
#pragma unroll
            for (int q=0;q<4;q++) c[i][j][q]=0.f;

    auto load = [&](int ch, int sel){
        uint32_t* a = As + sel*32*LDA;
        uint32_t* b = Bs + sel*32*LDB;
        const int k0 = ch*32;
#pragma unroll
        for (int it = 0; it < 4; it++){
            int lin = tid + it*256;
            int kr = lin >> 5, q = lin & 31;
            cp16(a + kr*LDA + q*4, Ab + (size_t)(k0+kr)*512 + q*4);
        }
#pragma unroll
        for (int it = 0; it < 32*BN/4/256; it++){
            int lin = tid + it*256;
            int kr = lin / (BN/4), q = lin % (BN/4);
            cp16(b + kr*LDB + q*4, Bb + (size_t)(k0+kr)*BN + q*4);
        }
        asm volatile("cp.async.commit_group;" ::: "memory");
    };

    load(0, 0);
    for (int i = 0; i < NC; i++){
        const int cur = i & 1;
        if (i + 1 < NC){
            load(i+1, cur^1);
            asm volatile("cp.async.wait_group 1;" ::: "memory");
        } else {
            asm volatile("cp.async.wait_group 0;" ::: "memory");
        }
        __syncthreads();
        const uint32_t* a = As + cur*32*LDA;
        const uint32_t* b = Bs + cur*32*LDB;
#pragma unroll
        for (int ks = 0; ks < 4; ks++){
            uint32_t af[MT][4], bf[NTT][2];
#pragma unroll
            for (int mt = 0; mt < MT; mt++){
                int m = mbase + mt*16 + g;
                af[mt][0] = a[(ks*8+tg  )*LDA + m    ];
                af[mt][1] = a[(ks*8+tg  )*LDA + m + 8];
                af[mt][2] = a[(ks*8+tg+4)*LDA + m    ];
                af[mt][3] = a[(ks*8+tg+4)*LDA + m + 8];
            }
#pragma unroll
            for (int nt = 0; nt < NTT; nt++){
                int o = nbase + nt*8 + g;
                bf[nt][0] = b[(ks*8+tg  )*LDB + o];
                bf[nt][1] = b[(ks*8+tg+4)*LDB + o];
            }
#pragma unroll
            for (int mt = 0; mt < MT; mt++)
#pragma unroll
                for (int nt = 0; nt < NTT; nt++)
                    mma_tf32(c[mt][nt], af[mt], bf[nt]);
        }
        __syncthreads();
    }

#pragma unroll
    for (int mt = 0; mt < MT; mt++){
        int n_ = m0 + mbase + mt*16 + g;
#pragma unroll
        for (int half = 0; half < 2; half++){
            float* orow = outp + ((size_t)bt*512 + n_ + half*8)*BN;
#pragma unroll
            for (int nt = 0; nt < NTT; nt++){
                int o = nbase + nt*8 + tg*2;
                float2 v;
                v.x = c[mt][nt][half*2+0] + bias[bt*BN + o];
                v.y = c[mt][nt][half*2+1] + bias[bt*BN + o + 1];
                *(float2*)(orow + o) = v;
            }
        }
    }
}

// -------------------- adjacency: A row-major + tf32 ------------------------
__global__ void k_A(const float* __restrict__ E, float* __restrict__ Arm,
                    uint32_t* __restrict__ Atf)
{
    __shared__ float Es[512*16];
    __shared__ float red[512];
    const int tid = threadIdx.x;
    const int n   = blockIdx.x;
    for (int i = tid; i < 512*16; i += 512) Es[i] = E[i];
    __syncthreads();
    float acc = 0.f;
#pragma unroll
    for (int d = 0; d < 16; d++) acc += Es[n*16+d]*Es[tid*16+d];
    acc = fmaxf(acc, 0.f);
    red[tid] = acc; __syncthreads();
    for (int s = 256; s > 0; s >>= 1){ if (tid < s) red[tid] = fmaxf(red[tid], red[tid+s]); __syncthreads(); }
    float mx = red[0]; __syncthreads();
    float e = expf(acc - mx);
    red[tid] = e; __syncthreads();
    for (int s = 256; s > 0; s >>= 1){ if (tid < s) red[tid] += red[tid+s]; __syncthreads(); }
    float v = e / red[0];
    Arm[n*512 + tid] = v;
    Atf[n*512 + tid] = f2tf32(v);
}

__global__ void k_fixdiag(float* __restrict__ S)
{
    int i = threadIdx.x;
    S[i*512 + i] -= 1.f;
}

__global__ void k_cvt(const float* __restrict__ s, uint32_t* __restrict__ d, int n)
{
    int i = blockIdx.x*256 + threadIdx.x;
    if (i < n) d[i] = f2tf32(s[i]);
}

// -------------------- generic SGEMM, A row-major (setup only) --------------
template<int BM,int BN,int BK,int TM,int TN,int NT>
__global__ void __launch_bounds__(NT) gemm_rr_k(
    const float* __restrict__ Abase, long aStr,
    const float* __restrict__ Bbase, long bStr,
    float* __restrict__ Cbase, long cStr,
    int lda, int ldb, int ldc, int K,
    const float* __restrict__ colBias, float alpha)
{
    __shared__ float As[BK][BM];
    __shared__ float Bs[BK][BN];
    const int tid = threadIdx.x;
    const int bz  = blockIdx.z;
    const int m0  = blockIdx.y*BM;
    const int n0  = blockIdx.x*BN;
    const float* A = Abase + (long)bz*aStr + (long)m0*lda;
    const float* B = Bbase + (long)bz*bStr + n0;
    float*       C = Cbase + (long)bz*cStr + (long)m0*ldc + n0;
    const int tx = tid % (BN/TN);
    const int ty = tid / (BN/TN);
    float acc[TM][TN];
#pragma unroll
    for (int i=0;i<TM;i++)
#pragma unroll
        for (int j=0;j<TN;j++) acc[i][j]=0.f;

    for (int k0 = 0; k0 < K; k0 += BK){
        for (int li = tid; li < BM*BK/4; li += NT){
            int m  = li/(BK/4), kv = li%(BK/4);
            float4 v = *(const float4*)(A + (long)m*lda + k0 + kv*4);
            As[kv*4+0][m]=v.x; As[kv*4+1][m]=v.y; As[kv*4+2][m]=v.z; As[kv*4+3][m]=v.w;
        }
        for (int li = tid; li < BN*BK/4; li += NT){
            int k  = li/(BN/4), nv = li%(BN/4);
            *(float4*)&Bs[k][nv*4] = *(const float4*)(B + (long)(k0+k)*ldb + nv*4);
        }
        __syncthreads();
#pragma unroll
        for (int kk = 0; kk < BK; kk++){
            float a[TM], bb[TN];
#pragma unroll
            for (int i=0;i<TM;i+=4) *(float4*)&a[i]  = *(const float4*)&As[kk][ty*TM+i];
#pragma unroll
            for (int j=0;j<TN;j+=4) *(float4*)&bb[j] = *(const float4*)&Bs[kk][tx*TN+j];
#pragma unroll
            for (int i=0;i<TM;i++)
#pragma unroll
                for (int j=0;j<TN;j++) acc[i][j] += a[i]*bb[j];
        }
        __syncthreads();
    }
#pragma unroll
    for (int i=0;i<TM;i++){
        float* crow = C + (long)(ty*TM+i)*ldc + tx*TN;
#pragma unroll
        for (int j=0;j<TN;j+=4){
            float4 v;
            v.x=acc[i][j+0]*alpha; v.y=acc[i][j+1]*alpha;
            v.z=acc[i][j+2]*alpha; v.w=acc[i][j+3]*alpha;
            if (colBias){
                const float* cb = colBias + n0 + tx*TN + j;
                v.x+=cb[0]; v.y+=cb[1]; v.z+=cb[2]; v.w+=cb[3];
            }
            *(float4*)(crow + j) = v;
        }
    }
}

// -------------------- pack gwp/uwp (drop channel 0) ------------------------
__global__ void k_pack(const float* __restrict__ wp, const float* __restrict__ w,
                       float* __restrict__ pwp, float* __restrict__ pw, int O)
{
    int idx = blockIdx.x*blockDim.x + threadIdx.x;
    if (blockIdx.y == 0){
        if (idx < 32*192*O){
            int o = idx % O; int r = idx / O;
            int c = r % 64;  int k = (r/64)%3; int d = r/192;
            pwp[idx] = wp[(((d*3 + k)*65) + (c+1))*O + o];
        }
    } else {
        if (idx < 192*O){
            int o = idx % O; int r = idx / O;
            int c = r % 64;  int k = r/64;
            pw[idx] = w[((k*65) + (c+1))*O + o];
        }
    }
}

// -------------------- bias vectors: temb@bp + b0 ---------------------------
__global__ void k_bvec(const float* __restrict__ temb, const float* __restrict__ bp,
                       const float* __restrict__ b0, float* __restrict__ out, int O)
{
    int bt = blockIdx.x; int o = threadIdx.x;
    float acc = b0[o];
#pragma unroll
    for (int d = 0; d < 32; d++) acc += temb[bt*32+d]*bp[d*O+o];
    out[bt*O+o] = acc;
}

// -------------------- small STE projections --------------------------------
__global__ void k_small(const float* __restrict__ ne1, const float* __restrict__ ne2,
                        const float* __restrict__ Wq, const float* __restrict__ bq,
                        const float* __restrict__ Wk, const float* __restrict__ bk,
                        const float* __restrict__ Wv, const float* __restrict__ bv,
                        float* __restrict__ aq, float* __restrict__ ak, float* __restrict__ av)
{
    int b = blockIdx.x, y = blockIdx.y, h = threadIdx.x;
    const float *src, *W, *bias; float* out;
    if (y < 12)      { src = ne2 + (b*12+y)*32;  W = Wq; bias = bq; out = aq + (b*12+y)*64; }
    else if (y == 12){ src = ne1 + (b*12+11)*32; W = Wk; bias = bk; out = ak + b*64; }
    else             { src = ne1 + (b*12+11)*32; W = Wv; bias = bv; out = av + b*64; }
    float acc = bias[h];
#pragma unroll
    for (int d = 0; d < 32; d++) acc += src[d]*W[d*64+h];
    out[h] = acc;
}

// -------------------- X projections (xq, k, v, xw0) ------------------------
__global__ void __launch_bounds__(256) k_proj(
    const float* __restrict__ X,
    const float* __restrict__ Wq, const float* __restrict__ Wk,
    const float* __restrict__ Wv, const float* __restrict__ taw,
    const float* __restrict__ ak, const float* __restrict__ av,
    float* __restrict__ xq, float* __restrict__ kb,
    float* __restrict__ vb, float* __restrict__ xw0)
{
    __shared__ float Xs[64][64];
    __shared__ float Ws[64][64];
    const int tid  = threadIdx.x;
    const int mode = blockIdx.y;
    const int m0   = blockIdx.x*64;
    const int b    = m0 >> 9;
    const float* W = (mode==0)? Wq+2048 : (mode==1)? Wk+2048 : (mode==2)? Wv+2048 : taw;
    for (int li = tid; li < 1024; li += 256){
        int m = li>>4, kv = li&15;
        float4 v = *(const float4*)(X + (long)(m0+m)*64 + kv*4);
        Xs[kv*4+0][m]=v.x; Xs[kv*4+1][m]=v.y; Xs[kv*4+2][m]=v.z; Xs[kv*4+3][m]=v.w;
        *(float4*)&Ws[m][kv*4] = *(const float4*)(W + m*64 + kv*4);
    }
    __syncthreads();
    const int tx = tid&15, ty = tid>>4;
    float acc[4][4];
#pragma unroll
    for (int i=0;i<4;i++)
#pragma unroll
        for (int j=0;j<4;j++) acc[i][j]=0.f;
#pragma unroll
    for (int kk = 0; kk < 64; kk++){
        float a[4], bb[4];
        *(float4*)a  = *(const float4*)&Xs[kk][ty*4];
        *(float4*)bb = *(const float4*)&Ws[kk][tx*4];
#pragma unroll
        for (int i=0;i<4;i++)
#pragma unroll
            for (int j=0;j<4;j++) acc[i][j] += a[i]*bb[j];
    }
    float* outp = (mode==0)? xq : (mode==1)? kb : (mode==2)? vb : xw0;
#pragma unroll
    for (int i=0;i<4;i++){
        int m = m0 + ty*4 + i;
        float4 r;
        if (mode==1 || mode==2){
            const float* bias = ((mode==1)? ak:av) + b*64 + tx*4;
            r.x=fmaxf(acc[i][0]+bias[0],0.f); r.y=fmaxf(acc[i][1]+bias[1],0.f);
            r.z=fmaxf(acc[i][2]+bias[2],0.f); r.w=fmaxf(acc[i][3]+bias[3],0.f);
        } else {
            r.x=acc[i][0]; r.y=acc[i][1]; r.z=acc[i][2]; r.w=acc[i][3];
        }
        *(float4*)(outp + (long)m*64 + tx*4) = r;
    }
}

// -------------------- attention scores + softmax ---------------------------
__global__ void __launch_bounds__(256) k_attn(
    const float* __restrict__ aq, const float* __restrict__ xq,
    const float* __restrict__ kb, float* __restrict__ sm_out)
{
    __shared__ float aq_s[768];
    const int b = blockIdx.y;
    const int tid = threadIdx.x, lane = tid&31, w = tid>>5;
    for (int i = tid; i < 768; i += 256) aq_s[i] = aq[b*768 + i];
    __syncthreads();
    const int n0 = blockIdx.x*32 + w*4;
    for (int j = 0; j < 4; j++){
        int bn = b*512 + n0 + j;
        float xq0 = xq[bn*64 + lane],      xq1 = xq[bn*64 + 32 + lane];
        float k0  = kb[bn*64 + lane],      k1  = kb[bn*64 + 32 + lane];
        float sc0[12], sc1[12];
#pragma unroll
        for (int t = 0; t < 12; t++){
            float q0 = fmaxf(aq_s[t*64 + lane] + xq0, 0.f);
            float q1 = fmaxf(aq_s[t*64 + 32 + lane] + xq1, 0.f);
            float p0 = q0*k0, p1 = q1*k1;
#pragma unroll
            for (int o = 1; o < 8; o <<= 1){
                p0 += __shfl_xor_sync(0xffffffffu, p0, o);
                p1 += __shfl_xor_sync(0xffffffffu, p1, o);
            }
            sc0[t] = p0; sc1[t] = p1;
        }
        float m0 = -1e30f, m1 = -1e30f;
#pragma unroll
        for (int t = 0; t < 12; t++){ m0 = fmaxf(m0, sc0[t]); m1 = fmaxf(m1, sc1[t]); }
        float s0 = 0.f, s1 = 0.f;
#pragma unroll
        for (int t = 0; t < 12; t++){ sc0[t] = expf(sc0[t]-m0); s0 += sc0[t];
                                      sc1[t] = expf(sc1[t]-m1); s1 += sc1[t]; }
        float r0 = 1.f/s0, r1 = 1.f/s1;
        if ((lane & 7) == 0){
            int d = lane >> 3;
#pragma unroll
            for (int t = 0; t < 12; t++){
                sm_out[bn*96 + t*8 + d]     = sc0[t]*r0;
                sm_out[bn*96 + t*8 + 4 + d] = sc1[t]*r1;
            }
        }
    }
}

// -------------------- build de (f32 + tf32 copies) -------------------------
__global__ void __launch_bounds__(256) k_debuild(
    const float* __restrict__ sm, const float* __restrict__ vb,
    const float* __restrict__ xw0, const float* __restrict__ taw,
    const float* __restrict__ tab, float* __restrict__ de,
    uint32_t* __restrict__ detf)
{
    __shared__ float taw1s[64][64];
    __shared__ float wvT[64][33];
    __shared__ float xw0s[64][33];
    const int b = blockIdx.z, t = blockIdx.y, n0 = blockIdx.x*32;
    const int tid = threadIdx.x;
    for (int i = tid; i < 4096; i += 256)
        taw1s[i>>6][i&63] = taw[4096 + i];
    for (int idx = tid; idx < 2048; idx += 256){
        int nl = idx >> 6, i = idx & 63;
        int bn = b*512 + n0 + nl;
        float s = sm[bn*96 + t*8 + (i>>3)];
        wvT[i][nl]  = s * vb[bn*64 + i];
        xw0s[i][nl] = xw0[bn*64 + i];
    }
    __syncthreads();
    const int tx = tid & 15, ty = tid >> 4;
    float acc[4][2] = {};
#pragma unroll
    for (int i = 0; i < 64; i++){
        float4 a = *(const float4*)&taw1s[i][ty*4];
        float b0 = wvT[i][tx*2], b1 = wvT[i][tx*2+1];
        acc[0][0]+=a.x*b0; acc[0][1]+=a.x*b1;
        acc[1][0]+=a.y*b0; acc[1][1]+=a.y*b1;
        acc[2][0]+=a.z*b0; acc[2][1]+=a.z*b1;
        acc[3][0]+=a.w*b0; acc[3][1]+=a.w*b1;
    }
    const int bt = b*12 + t;
    long baseD = (long)bt*32768;
    long baseT = (long)bt*98304;
#pragma unroll
    for (int oi = 0; oi < 4; oi++){
        int o = ty*4 + oi;
        float bias = tab[o];
        float2 v;
        v.x = acc[oi][0] + xw0s[o][tx*2]   + bias;
        v.y = acc[oi][1] + xw0s[o][tx*2+1] + bias;
        *(float2*)&de[baseD + (long)o*512 + n0 + tx*2] = v;
        uint2 u; u.x = f2tf32(v.x); u.y = f2tf32(v.y);
        *(uint2*)&detf[baseT + (long)o*512 + n0 + tx*2] = u;
    }
}

// -------------------- gate: cand = sigmoid(z) * de (tf32 out) --------------
__global__ void k_gate(const float* __restrict__ zr, const float* __restrict__ de,
                       uint32_t* __restrict__ ctf)
{
    __shared__ float s[32][33];
    const int bt = blockIdx.y, n0 = blockIdx.x*32;
    const int tx = threadIdx.x, ty = threadIdx.y;
    for (int ch = 0; ch < 2; ch++){
        int c0 = ch*32;
        s[ty][tx] = zr[bt*65536 + (n0+ty)*128 + c0 + tx];
        __syncthreads();
        int c = c0 + ty;
        float z = 1.f/(1.f + expf(-s[tx][ty]));
        float val = z * de[(long)bt*32768 + (long)c*512 + n0 + tx];
        ctf[(long)bt*98304 + (long)c*512 + n0 + tx] = f2tf32(val);
        __syncthreads();
    }
}

// -------------------- final: state blend + output head ---------------------
__global__ void __launch_bounds__(256) k_final(
    const float* __restrict__ zr, const float* __restrict__ de,
    const float* __restrict__ hc, const float* __restrict__ out_w,
    const float* __restrict__ out_b, float* __restrict__ out)
{
    __shared__ float de_s[64][33];
    __shared__ float red[8][32];
    __shared__ float w_s[64];
    const int bt = blockIdx.y, n0 = blockIdx.x*32;
    const int tt = bt % 12;
    const int tid = threadIdx.x;
    if (tid < 64) w_s[tid] = out_w[tt*64 + tid];
    for (int i = tid; i < 2048; i += 256){
        int h = i >> 5, nl = i & 31;
        de_s[h][nl] = de[(long)bt*32768 + h*512 + n0 + nl];
    }
    __syncthreads();
    const int nl = tid & 31, hg = tid >> 5;
    const int rg_off = bt*65536 + (n0+nl)*128 + 64;
    const int hc_off = bt*32768 + (n0+nl)*64;
    float partial = 0.f;
#pragma unroll
    for (int j = 0; j < 8; j++){
        int h = hg*8 + j;
        float rg  = 1.f/(1.f + expf(-zr[rg_off + h]));
        float hcv = tanhf(hc[hc_off + h]);
        float st  = rg*de_s[h][nl] + (1.f-rg)*hcv;
        partial  += st * w_s[h];
    }
    red[hg][nl] = partial;
    __syncthreads();
    if (tid < 32){
        float sum = 0.f;
#pragma unroll
        for (int g = 0; g < 8; g++) sum += red[g][tid];
        out[bt*512 + n0 + tid] = sum + out_b[tt];
    }
}

// ===========================================================================
extern "C" void kernel_launch(void* const* d_in, const int* in_sizes, int n_in,
                              void* d_out, int out_size)
{
    const float* h_n  = (const float*)d_in[2];
    const float* ne1  = (const float*)d_in[3];
    const float* ne2  = (const float*)d_in[4];
    const float* E    = (const float*)d_in[5];
    const float* Wq   = (const float*)d_in[6];
    const float* bq   = (const float*)d_in[7];
    const float* Wk   = (const float*)d_in[8];
    const float* bk   = (const float*)d_in[9];
    const float* Wv   = (const float*)d_in[10];
    const float* bv   = (const float*)d_in[11];
    const float* taw  = (const float*)d_in[12];
    const float* tab  = (const float*)d_in[13];
    const float* gwp  = (const float*)d_in[14];
    const float* gw   = (const float*)d_in[15];
    const float* gbp  = (const float*)d_in[16];
    const float* gb   = (const float*)d_in[17];
    const float* uwp  = (const float*)d_in[18];
    const float* uw   = (const float*)d_in[19];
    const float* ubp  = (const float*)d_in[20];
    const float* ub   = (const float*)d_in[21];
    const float* outw = (const float*)d_in[22];
    const float* outb = (const float*)d_in[23];
    float* out = (float*)d_out;

    float *Arm, *S2, *kb2, *vb2, *xq, *xw0, *aq, *ak, *av, *sm, *de;
    float *W1, *W2, *b1, *b2, *wp1, *w1b, *wp2, *w2b, *zr, *hc;
    uint32_t *Atf, *S2tf, *xgtf1, *xgtf2, *W1tf, *W2tf;
    cudaGetSymbolAddress((void**)&Arm,  g_Arm);
    cudaGetSymbolAddress((void**)&S2,   g_S2);
    cudaGetSymbolAddress((void**)&Atf,  g_Atf);
    cudaGetSymbolAddress((void**)&S2tf, g_S2tf);
    cudaGetSymbolAddress((void**)&kb2,  g_kb);
    cudaGetSymbolAddress((void**)&vb2,  g_vb);
    cudaGetSymbolAddress((void**)&xq,   g_xq);
    cudaGetSymbolAddress((void**)&xw0,  g_xw0);
    cudaGetSymbolAddress((void**)&aq,   g_aq);
    cudaGetSymbolAddress((void**)&ak,   g_ak);
    cudaGetSymbolAddress((void**)&av,   g_av);
    cudaGetSymbolAddress((void**)&sm,   g_sm);
    cudaGetSymbolAddress((void**)&de,   g_de);
    cudaGetSymbolAddress((void**)&xgtf1,g_xgtf1);
    cudaGetSymbolAddress((void**)&xgtf2,g_xgtf2);
    cudaGetSymbolAddress((void**)&W1,   g_W1);
    cudaGetSymbolAddress((void**)&W2,   g_W2);
    cudaGetSymbolAddress((void**)&W1tf, g_W1tf);
    cudaGetSymbolAddress((void**)&W2tf, g_W2tf);
    cudaGetSymbolAddress((void**)&b1,   g_b1);
    cudaGetSymbolAddress((void**)&b2,   g_b2);
    cudaGetSymbolAddress((void**)&wp1,  g_wp1);
    cudaGetSymbolAddress((void**)&w1b,  g_w1b);
    cudaGetSymbolAddress((void**)&wp2,  g_wp2);
    cudaGetSymbolAddress((void**)&w2b,  g_w2b);
    cudaGetSymbolAddress((void**)&zr,   g_zr);
    cudaGetSymbolAddress((void**)&hc,   g_hc);

    const int SUPP_SMEM = 2*128*36*4*2;                 // 73728
    const int CTR1_SMEM = (2*32*132 + 2*32*132)*4;      // 67584
    const int CTR2_SMEM = (2*32*132 + 2*32*68)*4;       // 51200
    cudaFuncSetAttribute(k_supp_mma, cudaFuncAttributeMaxDynamicSharedMemorySize, SUPP_SMEM);
    cudaFuncSetAttribute(k_ctr_mma<128,4,4,2>, cudaFuncAttributeMaxDynamicSharedMemorySize, CTR1_SMEM);
    cudaFuncSetAttribute(k_ctr_mma<64,2,4,4>,  cudaFuncAttributeMaxDynamicSharedMemorySize, CTR2_SMEM);

    // ---- adjacency & supports ----
    k_A<<<512, 512>>>(E, Arm, Atf);
    gemm_rr_k<64,64,16,4,4,256><<<dim3(8,8,1), 256>>>(        // S2 = 2*A@A
        Arm, 0, Arm, 0, S2, 0, 512, 512, 512, 512, nullptr, 2.f);
    k_fixdiag<<<1, 512>>>(S2);
    k_cvt<<<1024, 256>>>(S2, S2tf, 512*512);

    // ---- pack GCN weights, build per-bt W (f32) + tf32 copies + bias ----
    k_pack<<<dim3(3072,2), 256>>>(gwp, gw, wp1, w1b, 128);
    k_pack<<<dim3(1536,2), 256>>>(uwp, uw, wp2, w2b, 64);
    k_bvec<<<768, 128>>>(ne2, gbp, gb, b1, 128);
    k_bvec<<<768, 64 >>>(ne2, ubp, ub, b2, 64);
    gemm_rr_k<64,64,16,4,4,256><<<dim3(384,12,1), 256>>>(
        ne2, 0, wp1, 0, W1, 0, 32, 24576, 24576, 32, w1b, 1.f);
    gemm_rr_k<64,64,16,4,4,256><<<dim3(192,12,1), 256>>>(
        ne2, 0, wp2, 0, W2, 0, 32, 12288, 12288, 32, w2b, 1.f);
    k_cvt<<<(768*192*128+255)/256, 256>>>(W1, W1tf, 768*192*128);
    k_cvt<<<(768*192*64 +255)/256, 256>>>(W2, W2tf, 768*192*64);

    // ---- attention path ----
    k_small<<<dim3(64,14), 64>>>(ne1, ne2, Wq, bq, Wk, bk, Wv, bv, aq, ak, av);
    k_proj<<<dim3(512,4), 256>>>(h_n, Wq, Wk, Wv, taw, ak, av, xq, kb2, vb2, xw0);
    k_attn<<<dim3(16,64), 256>>>(aq, xq, kb2, sm);
    k_debuild<<<dim3(16,12,64), 256>>>(sm, vb2, xw0, taw, tab, de, xgtf1);

    // ---- GCN1: tensor-core supports + contraction ----
    k_supp_mma<<<dim3(4,384), 256, SUPP_SMEM>>>(xgtf1, Atf,  xgtf1 + 64*512);
    k_supp_mma<<<dim3(4,384), 256, SUPP_SMEM>>>(xgtf1, S2tf, xgtf1 + 128*512);
    k_ctr_mma<128,4,4,2><<<dim3(4,768), 256, CTR1_SMEM>>>(xgtf1, W1tf, b1, zr);

    // ---- GCN2 ----
    k_gate<<<dim3(16,768), dim3(32,32)>>>(zr, de, xgtf2);
    k_supp_mma<<<dim3(4,384), 256, SUPP_SMEM>>>(xgtf2, Atf,  xgtf2 + 64*512);
    k_supp_mma<<<dim3(4,384), 256, SUPP_SMEM>>>(xgtf2, S2tf, xgtf2 + 128*512);
    k_ctr_mma<64,2,4,4><<<dim3(4,768), 256, CTR2_SMEM>>>(xgtf2, W2tf, b2, hc);

    // ---- final blend + output head ----
    k_final<<<dim3(16,768), 256>>>(zr, de, hc, outw, outb, out);
}

// round 6
// speedup vs baseline: 2.5199x; 1.0466x over previous
#include <cuda_runtime.h>
#include <math.h>
#include <stdint.h>

// Problem constants: B=64, T=12, N=512, H=64, TD=32, ED=16, CHEB_K=3, D_HEADS=8
// BT = 768. Effective GCN channels = 64 (channel 0 is identically zero).

// -------------------- static device scratch --------------------------------
static __device__ float g_Arm[512*512];            // A row-major
static __device__ float g_S2 [512*512];            // 2A^2 - I row-major
static __device__ uint32_t g_Atf [512*512];        // tf32 copies
static __device__ uint32_t g_S2tf[512*512];
static __device__ float g_kb [64*512*64];
static __device__ float g_vb [64*512*64];
static __device__ float g_xq [64*512*64];
static __device__ float g_xw0[64*512*64];
static __device__ float g_aq [64*12*64];
static __device__ float g_ak [64*64];
static __device__ float g_av [64*64];
static __device__ float g_sm [64*512*12*8];
static __device__ float g_de [768*64*512];         // de f32 (channel-major)
static __device__ uint32_t g_xgtf1[768*192*512];   // tf32 [bt][j][n] j:0-63 de,64-127 A@,128-191 S2@
static __device__ uint32_t g_xgtf2[768*192*512];   // same for cand
static __device__ uint32_t g_W1tf[768*192*128];
static __device__ uint32_t g_W2tf[768*192*64];
static __device__ float g_b1 [768*128];
static __device__ float g_b2 [768*64];
static __device__ float g_wp1[32*192*128];
static __device__ float g_w1b[192*128];
static __device__ float g_wp2[32*192*64];
static __device__ float g_w2b[192*64];
static __device__ float g_zr [768*512*128];
static __device__ float g_hc [768*512*64];

// -------------------- helpers ----------------------------------------------
__device__ __forceinline__ uint32_t f2tf32(float f){
    uint32_t u; asm("cvt.rna.tf32.f32 %0, %1;" : "=r"(u) : "f"(f)); return u;
}
__device__ __forceinline__ void cp16(void* dst, const void* src){
    uint32_t d;
    asm("{ .reg .u64 t; cvta.to.shared.u64 t, %1; cvt.u32.u64 %0, t; }" : "=r"(d) : "l"(dst));
    asm volatile("cp.async.cg.shared.global [%0], [%1], 16;" :: "r"(d), "l"(src));
}
__device__ __forceinline__ void mma_tf32(float* c, const uint32_t* a, const uint32_t* b){
    asm volatile(
        "mma.sync.aligned.m16n8k8.row.col.f32.tf32.tf32.f32 "
        "{%0,%1,%2,%3}, {%4,%5,%6,%7}, {%8,%9}, {%0,%1,%2,%3};"
        : "+f"(c[0]),"+f"(c[1]),"+f"(c[2]),"+f"(c[3])
        : "r"(a[0]),"r"(a[1]),"r"(a[2]),"r"(a[3]), "r"(b[0]),"r"(b[1]));
}

// -------------------- fused dual support GEMM (mma.sync tf32) --------------
// grid (4 n-tiles, 384 bt-pairs), 256 threads.
// For both Bm in {A, S2}: C[r][n] = sum_k x[r][k]*Bm[n][k];
// r=0..127 -> bt=2p+(r>>6), c=r&63.  x rows = xgtf[bt][0..63][*].
// Outputs written tf32 into rows 64-127 (A) and 128-191 (S2) of xgtf.
__global__ void __launch_bounds__(256) k_supp2_mma(
    const uint32_t* __restrict__ xtf,
    const uint32_t* __restrict__ B1tf,  // A     [512][512] tf32 row-major
    const uint32_t* __restrict__ B2tf,  // S2    [512][512] tf32 row-major
    uint32_t* __restrict__ out1,        // xgtf + 64*512
    uint32_t* __restrict__ out2)        // xgtf + 128*512
{
    constexpr int LD = 36;              // 32 + 4 pad
    extern __shared__ uint32_t sh[];
    uint32_t* As  = sh;                 // [2][128*36]
    uint32_t* B1s = sh + 2*128*LD;      // [2][128*36]
    uint32_t* B2s = sh + 4*128*LD;      // [2][128*36]
    const int tid = threadIdx.x, wid = tid>>5, lane = tid&31;
    const int g = lane>>2, tg = lane&3;
    const int p = blockIdx.y, n0 = blockIdx.x*128;
    const int wm = wid & 1, wn = wid >> 1;
    const int mbase = wm*64, nbase = wn*32;

    float c[2][4][4][4];
#pragma unroll
    for (int s=0;s<2;s++)
#pragma unroll
        for (int i=0;i<4;i++)
#pragma unroll
            for (int j=0;j<4;j++)
#pragma unroll
                for (int q=0;q<4;q++) c[s][i][j][q]=0.f;

    auto load = [&](int ch, int sel){
        uint32_t* a  = As  + sel*128*LD;
        uint32_t* b1 = B1s + sel*128*LD;
        uint32_t* b2 = B2s + sel*128*LD;
        const int k0 = ch*32;
#pragma unroll
        for (int it = 0; it < 4; it++){
            int lin = tid + it*256;
            int r = lin >> 3, q = lin & 7;
            cp16(a  + r*LD + q*4,
                 xtf + (size_t)(2*p + (r>>6))*98304 + (size_t)(r&63)*512 + k0 + q*4);
            cp16(b1 + r*LD + q*4, B1tf + (size_t)(n0 + r)*512 + k0 + q*4);
            cp16(b2 + r*LD + q*4, B2tf + (size_t)(n0 + r)*512 + k0 + q*4);
        }
        asm volatile("cp.async.commit_group;" ::: "memory");
    };

    load(0, 0);
    for (int i = 0; i < 16; i++){
        const int cur = i & 1;
        if (i + 1 < 16){
            load(i+1, cur^1);
            asm volatile("cp.async.wait_group 1;" ::: "memory");
        } else {
            asm volatile("cp.async.wait_group 0;" ::: "memory");
        }
        __syncthreads();
        const uint32_t* a  = As  + cur*128*LD;
        const uint32_t* b1 = B1s + cur*128*LD;
        const uint32_t* b2 = B2s + cur*128*LD;
#pragma unroll
        for (int ks = 0; ks < 4; ks++){
            uint32_t af[4][4], bf1[4][2], bf2[4][2];
#pragma unroll
            for (int mt = 0; mt < 4; mt++){
                int row = mbase + mt*16 + g;
                af[mt][0] = a[ row   *LD + ks*8 + tg    ];
                af[mt][1] = a[(row+8)*LD + ks*8 + tg    ];
                af[mt][2] = a[ row   *LD + ks*8 + tg + 4];
                af[mt][3] = a[(row+8)*LD + ks*8 + tg + 4];
            }
#pragma unroll
            for (int nt = 0; nt < 4; nt++){
                int nr = nbase + nt*8 + g;
                bf1[nt][0] = b1[nr*LD + ks*8 + tg    ];
                bf1[nt][1] = b1[nr*LD + ks*8 + tg + 4];
                bf2[nt][0] = b2[nr*LD + ks*8 + tg    ];
                bf2[nt][1] = b2[nr*LD + ks*8 + tg + 4];
            }
#pragma unroll
            for (int mt = 0; mt < 4; mt++)
#pragma unroll
                for (int nt = 0; nt < 4; nt++){
                    mma_tf32(c[0][mt][nt], af[mt], bf1[nt]);
                    mma_tf32(c[1][mt][nt], af[mt], bf2[nt]);
                }
        }
        __syncthreads();
    }

    // epilogue: convert to tf32, store both outputs
#pragma unroll
    for (int s = 0; s < 2; s++){
        uint32_t* outp = s ? out2 : out1;
#pragma unroll
        for (int mt = 0; mt < 4; mt++){
            int r0 = mbase + mt*16 + g;
#pragma unroll
            for (int half = 0; half < 2; half++){
                int r = r0 + half*8;
                uint32_t* orow = outp + (size_t)(2*p + (r>>6))*98304
                               + (size_t)(r&63)*512 + n0 + nbase;
#pragma unroll
                for (int nt = 0; nt < 4; nt++){
                    uint2 u;
                    u.x = f2tf32(c[s][mt][nt][half*2+0]);
                    u.y = f2tf32(c[s][mt][nt][half*2+1]);
                    *(uint2*)(orow + nt*8 + tg*2) = u;
                }
            }
        }
    }
}

// -------------------- contraction GEMM (mma.sync tf32) ---------------------
// C[n][o] = sum_k xg[k][n] * W[k][o] + bias[o];  per-bt batch.
template<int BN, int MT, int NTT, int WARPS_M>
__global__ void __launch_bounds__(256) k_ctr_mma(
    const uint32_t* __restrict__ xtf,   // [768][192][512] tf32
    const uint32_t* __restrict__ Wtf,   // [768][192][BN] tf32
    const float* __restrict__ bias,     // [768][BN]
    float* __restrict__ outp)           // [768][512][BN]
{
    constexpr int LDA = 132;            // 128 + 4
    constexpr int LDB = BN + 4;
    constexpr int NC  = 6;              // K=192 / 32
    extern __shared__ uint32_t sh[];
    uint32_t* As = sh;                  // [2][32*LDA]
    uint32_t* Bs = sh + 2*32*LDA;       // [2][32*LDB]
    const int tid = threadIdx.x, wid = tid>>5, lane = tid&31;
    const int g = lane>>2, tg = lane&3;
    const int bt = blockIdx.y, m0 = blockIdx.x*128;
    const int wm = wid % WARPS_M, wn = wid / WARPS_M;
    const int mbase = wm*(MT*16), nbase = wn*(NTT*8);
    const uint32_t* Ab = xtf + (size_t)bt*98304 + m0;
    const uint32_t* Bb = Wtf + (size_t)bt*192*BN;

    float c[MT][NTT][4];
#pragma unroll
    for (int i=0;i<MT;i++)
#pragma unroll
        for (int j=0;j<NTT;j++)
#pragma unroll
            for (int q=0;q<4;q++) c[i][j][q]=0.f;

    auto load = [&](int ch, int sel){
        uint32_t* a = As + sel*32*LDA;
        uint32_t* b = Bs + sel*32*LDB;
        const int k0 = ch*32;
#pragma unroll
        for (int it = 0; it < 4; it++){
            int lin = tid + it*256;
            int kr = lin >> 5, q = lin & 31;
            cp16(a + kr*LDA + q*4, Ab + (size_t)(k0+kr)*512 + q*4);
        }
#pragma unroll
        for (int it = 0; it < 32*BN/4/256; it++){
            int lin = tid + it*256;
            int kr = lin / (BN/4), q = lin % (BN/4);
            cp16(b + kr*LDB + q*4, Bb + (size_t)(k0+kr)*BN + q*4);
        }
        asm volatile("cp.async.commit_group;" ::: "memory");
    };

    load(0, 0);
    for (int i = 0; i < NC; i++){
        const int cur = i & 1;
        if (i + 1 < NC){
            load(i+1, cur^1);
            asm volatile("cp.async.wait_group 1;" ::: "memory");
        } else {
            asm volatile("cp.async.wait_group 0;" ::: "memory");
        }
        __syncthreads();
        const uint32_t* a = As + cur*32*LDA;
        const uint32_t* b = Bs + cur*32*LDB;
#pragma unroll
        for (int ks = 0; ks < 4; ks++){
            uint32_t af[MT][4], bf[NTT][2];
#pragma unroll
            for (int mt = 0; mt < MT; mt++){
                int m = mbase + mt*16 + g;
                af[mt][0] = a[(ks*8+tg  )*LDA + m    ];
                af[mt][1] = a[(ks*8+tg  )*LDA + m + 8];
                af[mt][2] = a[(ks*8+tg+4)*LDA + m    ];
                af[mt][3] = a[(ks*8+tg+4)*LDA + m + 8];
            }
#pragma unroll
            for (int nt = 0; nt < NTT; nt++){
                int o = nbase + nt*8 + g;
                bf[nt][0] = b[(ks*8+tg  )*LDB + o];
                bf[nt][1] = b[(ks*8+tg+4)*LDB + o];
            }
#pragma unroll
            for (int mt = 0; mt < MT; mt++)
#pragma unroll
                for (int nt = 0; nt < NTT; nt++)
                    mma_tf32(c[mt][nt], af[mt], bf[nt]);
        }
        __syncthreads();
    }

#pragma unroll
    for (int mt = 0; mt < MT; mt++){
        int n_ = m0 + mbase + mt*16 + g;
#pragma unroll
        for (int half = 0; half < 2; half++){
            float* orow = outp + ((size_t)bt*512 + n_ + half*8)*BN;
#pragma unroll
            for (int nt = 0; nt < NTT; nt++){
                int o = nbase + nt*8 + tg*2;
                float2 v;
                v.x = c[mt][nt][half*2+0] + bias[bt*BN + o];
                v.y = c[mt][nt][half*2+1] + bias[bt*BN + o + 1];
                *(float2*)(orow + o) = v;
            }
        }
    }
}

// -------------------- adjacency: A row-major + tf32 ------------------------
__global__ void k_A(const float* __restrict__ E, float* __restrict__ Arm,
                    uint32_t* __restrict__ Atf)
{
    __shared__ float Es[512*16];
    __shared__ float red[512];
    const int tid = threadIdx.x;
    const int n   = blockIdx.x;
    for (int i = tid; i < 512*16; i += 512) Es[i] = E[i];
    __syncthreads();
    float acc = 0.f;
#pragma unroll
    for (int d = 0; d < 16; d++) acc += Es[n*16+d]*Es[tid*16+d];
    acc = fmaxf(acc, 0.f);
    red[tid] = acc; __syncthreads();
    for (int s = 256; s > 0; s >>= 1){ if (tid < s) red[tid] = fmaxf(red[tid], red[tid+s]); __syncthreads(); }
    float mx = red[0]; __syncthreads();
    float e = expf(acc - mx);
    red[tid] = e; __syncthreads();
    for (int s = 256; s > 0; s >>= 1){ if (tid < s) red[tid] += red[tid+s]; __syncthreads(); }
    float v = e / red[0];
    Arm[n*512 + tid] = v;
    Atf[n*512 + tid] = f2tf32(v);
}

__global__ void k_fixdiag(float* __restrict__ S)
{
    int i = threadIdx.x;
    S[i*512 + i] -= 1.f;
}

__global__ void k_cvt(const float* __restrict__ s, uint32_t* __restrict__ d, int n)
{
    int i = blockIdx.x*256 + threadIdx.x;
    if (i < n) d[i] = f2tf32(s[i]);
}

// -------------------- generic SGEMM, A row-major ---------------------------
// OUTMODE: 0 = f32 out, 1 = tf32 (uint) out
template<int BM,int BN,int BK,int TM,int TN,int NT,int OUTMODE>
__global__ void __launch_bounds__(NT) gemm_rr_k(
    const float* __restrict__ Abase, long aStr,
    const float* __restrict__ Bbase, long bStr,
    void* __restrict__ Cbase, long cStr,
    int lda, int ldb, int ldc, int K,
    const float* __restrict__ colBias, float alpha)
{
    __shared__ float As[BK][BM];
    __shared__ float Bs[BK][BN];
    const int tid = threadIdx.x;
    const int bz  = blockIdx.z;
    const int m0  = blockIdx.y*BM;
    const int n0  = blockIdx.x*BN;
    const float* A = Abase + (long)bz*aStr + (long)m0*lda;
    const float* B = Bbase + (long)bz*bStr + n0;
    const int tx = tid % (BN/TN);
    const int ty = tid / (BN/TN);
    float acc[TM][TN];
#pragma unroll
    for (int i=0;i<TM;i++)
#pragma unroll
        for (int j=0;j<TN;j++) acc[i][j]=0.f;

    for (int k0 = 0; k0 < K; k0 += BK){
        for (int li = tid; li < BM*BK/4; li += NT){
            int m  = li/(BK/4), kv = li%(BK/4);
            float4 v = *(const float4*)(A + (long)m*lda + k0 + kv*4);
            As[kv*4+0][m]=v.x; As[kv*4+1][m]=v.y; As[kv*4+2][m]=v.z; As[kv*4+3][m]=v.w;
        }
        for (int li = tid; li < BN*BK/4; li += NT){
            int k  = li/(BN/4), nv = li%(BN/4);
            *(float4*)&Bs[k][nv*4] = *(const float4*)(B + (long)(k0+k)*ldb + nv*4);
        }
        __syncthreads();
#pragma unroll
        for (int kk = 0; kk < BK; kk++){
            float a[TM], bb[TN];
#pragma unroll
            for (int i=0;i<TM;i+=4) *(float4*)&a[i]  = *(const float4*)&As[kk][ty*TM+i];
#pragma unroll
            for (int j=0;j<TN;j+=4) *(float4*)&bb[j] = *(const float4*)&Bs[kk][tx*TN+j];
#pragma unroll
            for (int i=0;i<TM;i++)
#pragma unroll
                for (int j=0;j<TN;j++) acc[i][j] += a[i]*bb[j];
        }
        __syncthreads();
    }
#pragma unroll
    for (int i=0;i<TM;i++){
#pragma unroll
        for (int j=0;j<TN;j+=4){
            float4 v;
            v.x=acc[i][j+0]*alpha; v.y=acc[i][j+1]*alpha;
            v.z=acc[i][j+2]*alpha; v.w=acc[i][j+3]*alpha;
            if (colBias){
                const float* cb = colBias + n0 + tx*TN + j;
                v.x+=cb[0]; v.y+=cb[1]; v.z+=cb[2]; v.w+=cb[3];
            }
            long coff = (long)bz*cStr + (long)(m0+ty*TM+i)*ldc + n0 + tx*TN + j;
            if (OUTMODE == 0){
                *(float4*)((float*)Cbase + coff) = v;
            } else {
                uint4 u;
                u.x=f2tf32(v.x); u.y=f2tf32(v.y); u.z=f2tf32(v.z); u.w=f2tf32(v.w);
                *(uint4*)((uint32_t*)Cbase + coff) = u;
            }
        }
    }
}

// -------------------- pack gwp/uwp (drop channel 0) ------------------------
__global__ void k_pack(const float* __restrict__ wp, const float* __restrict__ w,
                       float* __restrict__ pwp, float* __restrict__ pw, int O)
{
    int idx = blockIdx.x*blockDim.x + threadIdx.x;
    if (blockIdx.y == 0){
        if (idx < 32*192*O){
            int o = idx % O; int r = idx / O;
            int c = r % 64;  int k = (r/64)%3; int d = r/192;
            pwp[idx] = wp[(((d*3 + k)*65) + (c+1))*O + o];
        }
    } else {
        if (idx < 192*O){
            int o = idx % O; int r = idx / O;
            int c = r % 64;  int k = r/64;
            pw[idx] = w[((k*65) + (c+1))*O + o];
        }
    }
}

// -------------------- bias vectors: temb@bp + b0 ---------------------------
__global__ void k_bvec(const float* __restrict__ temb, const float* __restrict__ bp,
                       const float* __restrict__ b0, float* __restrict__ out, int O)
{
    int bt = blockIdx.x; int o = threadIdx.x;
    float acc = b0[o];
#pragma unroll
    for (int d = 0; d < 32; d++) acc += temb[bt*32+d]*bp[d*O+o];
    out[bt*O+o] = acc;
}

// -------------------- small STE projections --------------------------------
__global__ void k_small(const float* __restrict__ ne1, const float* __restrict__ ne2,
                        const float* __restrict__ Wq, const float* __restrict__ bq,
                        const float* __restrict__ Wk, const float* __restrict__ bk,
                        const float* __restrict__ Wv, const float* __restrict__ bv,
                        float* __restrict__ aq, float* __restrict__ ak, float* __restrict__ av)
{
    int b = blockIdx.x, y = blockIdx.y, h = threadIdx.x;
    const float *src, *W, *bias; float* out;
    if (y < 12)      { src = ne2 + (b*12+y)*32;  W = Wq; bias = bq; out = aq + (b*12+y)*64; }
    else if (y == 12){ src = ne1 + (b*12+11)*32; W = Wk; bias = bk; out = ak + b*64; }
    else             { src = ne1 + (b*12+11)*32; W = Wv; bias = bv; out = av + b*64; }
    float acc = bias[h];
#pragma unroll
    for (int d = 0; d < 32; d++) acc += src[d]*W[d*64+h];
    out[h] = acc;
}

// -------------------- X projections (xq, k, v, xw0) ------------------------
__global__ void __launch_bounds__(256) k_proj(
    const float* __restrict__ X,
    const float* __restrict__ Wq, const float* __restrict__ Wk,
    const float* __restrict__ Wv, const float* __restrict__ taw,
    const float* __restrict__ ak, const float* __restrict__ av,
    float* __restrict__ xq, float* __restrict__ kb,
    float* __restrict__ vb, float* __restrict__ xw0)
{
    __shared__ float Xs[64][64];
    __shared__ float Ws[64][64];
    const int tid  = threadIdx.x;
    const int mode = blockIdx.y;
    const int m0   = blockIdx.x*64;
    const int b    = m0 >> 9;
    const float* W = (mode==0)? Wq+2048 : (mode==1)? Wk+2048 : (mode==2)? Wv+2048 : taw;
    for (int li = tid; li < 1024; li += 256){
        int m = li>>4, kv = li&15;
        float4 v = *(const float4*)(X + (long)(m0+m)*64 + kv*4);
        Xs[kv*4+0][m]=v.x; Xs[kv*4+1][m]=v.y; Xs[kv*4+2][m]=v.z; Xs[kv*4+3][m]=v.w;
        *(float4*)&Ws[m][kv*4] = *(const float4*)(W + m*64 + kv*4);
    }
    __syncthreads();
    const int tx = tid&15, ty = tid>>4;
    float acc[4][4];
#pragma unroll
    for (int i=0;i<4;i++)
#pragma unroll
        for (int j=0;j<4;j++) acc[i][j]=0.f;
#pragma unroll
    for (int kk = 0; kk < 64; kk++){
        float a[4], bb[4];
        *(float4*)a  = *(const float4*)&Xs[kk][ty*4];
        *(float4*)bb = *(const float4*)&Ws[kk][tx*4];
#pragma unroll
        for (int i=0;i<4;i++)
#pragma unroll
            for (int j=0;j<4;j++) acc[i][j] += a[i]*bb[j];
    }
    float* outp = (mode==0)? xq : (mode==1)? kb : (mode==2)? vb : xw0;
#pragma unroll
    for (int i=0;i<4;i++){
        int m = m0 + ty*4 + i;
        float4 r;
        if (mode==1 || mode==2){
            const float* bias = ((mode==1)? ak:av) + b*64 + tx*4;
            r.x=fmaxf(acc[i][0]+bias[0],0.f); r.y=fmaxf(acc[i][1]+bias[1],0.f);
            r.z=fmaxf(acc[i][2]+bias[2],0.f); r.w=fmaxf(acc[i][3]+bias[3],0.f);
        } else {
            r.x=acc[i][0]; r.y=acc[i][1]; r.z=acc[i][2]; r.w=acc[i][3];
        }
        *(float4*)(outp + (long)m*64 + tx*4) = r;
    }
}

// -------------------- attention scores + softmax ---------------------------
__global__ void __launch_bounds__(256) k_attn(
    const float* __restrict__ aq, const float* __restrict__ xq,
    const float* __restrict__ kb, float* __restrict__ sm_out)
{
    __shared__ float aq_s[768];
    const int b = blockIdx.y;
    const int tid = threadIdx.x, lane = tid&31, w = tid>>5;
    for (int i = tid; i < 768; i += 256) aq_s[i] = aq[b*768 + i];
    __syncthreads();
    const int n0 = blockIdx.x*32 + w*4;
    for (int j = 0; j < 4; j++){
        int bn = b*512 + n0 + j;
        float xq0 = xq[bn*64 + lane],      xq1 = xq[bn*64 + 32 + lane];
        float k0  = kb[bn*64 + lane],      k1  = kb[bn*64 + 32 + lane];
        float sc0[12], sc1[12];
#pragma unroll
        for (int t = 0; t < 12; t++){
            float q0 = fmaxf(aq_s[t*64 + lane] + xq0, 0.f);
            float q1 = fmaxf(aq_s[t*64 + 32 + lane] + xq1, 0.f);
            float p0 = q0*k0, p1 = q1*k1;
#pragma unroll
            for (int o = 1; o < 8; o <<= 1){
                p0 += __shfl_xor_sync(0xffffffffu, p0, o);
                p1 += __shfl_xor_sync(0xffffffffu, p1, o);
            }
            sc0[t] = p0; sc1[t] = p1;
        }
        float m0 = -1e30f, m1 = -1e30f;
#pragma unroll
        for (int t = 0; t < 12; t++){ m0 = fmaxf(m0, sc0[t]); m1 = fmaxf(m1, sc1[t]); }
        float s0 = 0.f, s1 = 0.f;
#pragma unroll
        for (int t = 0; t < 12; t++){ sc0[t] = expf(sc0[t]-m0); s0 += sc0[t];
                                      sc1[t] = expf(sc1[t]-m1); s1 += sc1[t]; }
        float r0 = 1.f/s0, r1 = 1.f/s1;
        if ((lane & 7) == 0){
            int d = lane >> 3;
#pragma unroll
            for (int t = 0; t < 12; t++){
                sm_out[bn*96 + t*8 + d]     = sc0[t]*r0;
                sm_out[bn*96 + t*8 + 4 + d] = sc1[t]*r1;
            }
        }
    }
}

// -------------------- build de (f32 + tf32 copies) -------------------------
__global__ void __launch_bounds__(256) k_debuild(
    const float* __restrict__ sm, const float* __restrict__ vb,
    const float* __restrict__ xw0, const float* __restrict__ taw,
    const float* __restrict__ tab, float* __restrict__ de,
    uint32_t* __restrict__ detf)
{
    __shared__ float taw1s[64][64];
    __shared__ float wvT[64][33];
    __shared__ float xw0s[64][33];
    const int b = blockIdx.z, t = blockIdx.y, n0 = blockIdx.x*32;
    const int tid = threadIdx.x;
    for (int i = tid; i < 4096; i += 256)
        taw1s[i>>6][i&63] = taw[4096 + i];
    for (int idx = tid; idx < 2048; idx += 256){
        int nl = idx >> 6, i = idx & 63;
        int bn = b*512 + n0 + nl;
        float s = sm[bn*96 + t*8 + (i>>3)];
        wvT[i][nl]  = s * vb[bn*64 + i];
        xw0s[i][nl] = xw0[bn*64 + i];
    }
    __syncthreads();
    const int tx = tid & 15, ty = tid >> 4;
    float acc[4][2] = {};
#pragma unroll
    for (int i = 0; i < 64; i++){
        float4 a = *(const float4*)&taw1s[i][ty*4];
        float b0 = wvT[i][tx*2], b1 = wvT[i][tx*2+1];
        acc[0][0]+=a.x*b0; acc[0][1]+=a.x*b1;
        acc[1][0]+=a.y*b0; acc[1][1]+=a.y*b1;
        acc[2][0]+=a.z*b0; acc[2][1]+=a.z*b1;
        acc[3][0]+=a.w*b0; acc[3][1]+=a.w*b1;
    }
    const int bt = b*12 + t;
    long baseD = (long)bt*32768;
    long baseT = (long)bt*98304;
#pragma unroll
    for (int oi = 0; oi < 4; oi++){
        int o = ty*4 + oi;
        float bias = tab[o];
        float2 v;
        v.x = acc[oi][0] + xw0s[o][tx*2]   + bias;
        v.y = acc[oi][1] + xw0s[o][tx*2+1] + bias;
        *(float2*)&de[baseD + (long)o*512 + n0 + tx*2] = v;
        uint2 u; u.x = f2tf32(v.x); u.y = f2tf32(v.y);
        *(uint2*)&detf[baseT + (long)o*512 + n0 + tx*2] = u;
    }
}

// -------------------- gate: cand = sigmoid(z) * de (tf32 out) --------------
__global__ void k_gate(const float* __restrict__ zr, const float* __restrict__ de,
                       uint32_t* __restrict__ ctf)
{
    __shared__ float s[32][33];
    const int bt = blockIdx.y, n0 = blockIdx.x*32;
    const int tx = threadIdx.x, ty = threadIdx.y;
    for (int ch = 0; ch < 2; ch++){
        int c0 = ch*32;
        s[ty][tx] = zr[bt*65536 + (n0+ty)*128 + c0 + tx];
        __syncthreads();
        int c = c0 + ty;
        float z = 1.f/(1.f + expf(-s[tx][ty]));
        float val = z * de[(long)bt*32768 + (long)c*512 + n0 + tx];
        ctf[(long)bt*98304 + (long)c*512 + n0 + tx] = f2tf32(val);
        __syncthreads();
    }
}

// -------------------- final: state blend + output head ---------------------
__global__ void __launch_bounds__(256) k_final(
    const float* __restrict__ zr, const float* __restrict__ de,
    const float* __restrict__ hc, const float* __restrict__ out_w,
    const float* __restrict__ out_b, float* __restrict__ out)
{
    __shared__ float de_s[64][33];
    __shared__ float red[8][32];
    __shared__ float w_s[64];
    const int bt = blockIdx.y, n0 = blockIdx.x*32;
    const int tt = bt % 12;
    const int tid = threadIdx.x;
    if (tid < 64) w_s[tid] = out_w[tt*64 + tid];
    for (int i = tid; i < 2048; i += 256){
        int h = i >> 5, nl = i & 31;
        de_s[h][nl] = de[(long)bt*32768 + h*512 + n0 + nl];
    }
    __syncthreads();
    const int nl = tid & 31, hg = tid >> 5;
    const int rg_off = bt*65536 + (n0+nl)*128 + 64;
    const int hc_off = bt*32768 + (n0+nl)*64;
    float partial = 0.f;
#pragma unroll
    for (int j = 0; j < 8; j++){
        int h = hg*8 + j;
        float rg  = 1.f/(1.f + expf(-zr[rg_off + h]));
        float hcv = tanhf(hc[hc_off + h]);
        float st  = rg*de_s[h][nl] + (1.f-rg)*hcv;
        partial  += st * w_s[h];
    }
    red[hg][nl] = partial;
    __syncthreads();
    if (tid < 32){
        float sum = 0.f;
#pragma unroll
        for (int g = 0; g < 8; g++) sum += red[g][tid];
        out[bt*512 + n0 + tid] = sum + out_b[tt];
    }
}

// ===========================================================================
extern "C" void kernel_launch(void* const* d_in, const int* in_sizes, int n_in,
                              void* d_out, int out_size)
{
    const float* h_n  = (const float*)d_in[2];
    const float* ne1  = (const float*)d_in[3];
    const float* ne2  = (const float*)d_in[4];
    const float* E    = (const float*)d_in[5];
    const float* Wq   = (const float*)d_in[6];
    const float* bq   = (const float*)d_in[7];
    const float* Wk   = (const float*)d_in[8];
    const float* bk   = (const float*)d_in[9];
    const float* Wv   = (const float*)d_in[10];
    const float* bv   = (const float*)d_in[11];
    const float* taw  = (const float*)d_in[12];
    const float* tab  = (const float*)d_in[13];
    const float* gwp  = (const float*)d_in[14];
    const float* gw   = (const float*)d_in[15];
    const float* gbp  = (const float*)d_in[16];
    const float* gb   = (const float*)d_in[17];
    const float* uwp  = (const float*)d_in[18];
    const float* uw   = (const float*)d_in[19];
    const float* ubp  = (const float*)d_in[20];
    const float* ub   = (const float*)d_in[21];
    const float* outw = (const float*)d_in[22];
    const float* outb = (const float*)d_in[23];
    float* out = (float*)d_out;

    float *Arm, *S2, *kb2, *vb2, *xq, *xw0, *aq, *ak, *av, *sm, *de;
    float *b1, *b2, *wp1, *w1b, *wp2, *w2b, *zr, *hc;
    uint32_t *Atf, *S2tf, *xgtf1, *xgtf2, *W1tf, *W2tf;
    cudaGetSymbolAddress((void**)&Arm,  g_Arm);
    cudaGetSymbolAddress((void**)&S2,   g_S2);
    cudaGetSymbolAddress((void**)&Atf,  g_Atf);
    cudaGetSymbolAddress((void**)&S2tf, g_S2tf);
    cudaGetSymbolAddress((void**)&kb2,  g_kb);
    cudaGetSymbolAddress((void**)&vb2,  g_vb);
    cudaGetSymbolAddress((void**)&xq,   g_xq);
    cudaGetSymbolAddress((void**)&xw0,  g_xw0);
    cudaGetSymbolAddress((void**)&aq,   g_aq);
    cudaGetSymbolAddress((void**)&ak,   g_ak);
    cudaGetSymbolAddress((void**)&av,   g_av);
    cudaGetSymbolAddress((void**)&sm,   g_sm);
    cudaGetSymbolAddress((void**)&de,   g_de);
    cudaGetSymbolAddress((void**)&xgtf1,g_xgtf1);
    cudaGetSymbolAddress((void**)&xgtf2,g_xgtf2);
    cudaGetSymbolAddress((void**)&W1tf, g_W1tf);
    cudaGetSymbolAddress((void**)&W2tf, g_W2tf);
    cudaGetSymbolAddress((void**)&b1,   g_b1);
    cudaGetSymbolAddress((void**)&b2,   g_b2);
    cudaGetSymbolAddress((void**)&wp1,  g_wp1);
    cudaGetSymbolAddress((void**)&w1b,  g_w1b);
    cudaGetSymbolAddress((void**)&wp2,  g_wp2);
    cudaGetSymbolAddress((void**)&w2b,  g_w2b);
    cudaGetSymbolAddress((void**)&zr,   g_zr);
    cudaGetSymbolAddress((void**)&hc,   g_hc);

    const int SUPP2_SMEM = 6*128*36*4;                  // 110592
    const int CTR1_SMEM = (2*32*132 + 2*32*132)*4;      // 67584
    const int CTR2_SMEM = (2*32*132 + 2*32*68)*4;       // 51200
    cudaFuncSetAttribute(k_supp2_mma, cudaFuncAttributeMaxDynamicSharedMemorySize, SUPP2_SMEM);
    cudaFuncSetAttribute(k_ctr_mma<128,4,4,2>, cudaFuncAttributeMaxDynamicSharedMemorySize, CTR1_SMEM);
    cudaFuncSetAttribute(k_ctr_mma<64,2,4,4>,  cudaFuncAttributeMaxDynamicSharedMemorySize, CTR2_SMEM);

    // ---- adjacency & supports ----
    k_A<<<512, 512>>>(E, Arm, Atf);
    gemm_rr_k<64,64,16,4,4,256,0><<<dim3(8,8,1), 256>>>(      // S2 = 2*A@A
        Arm, 0, Arm, 0, S2, 0, 512, 512, 512, 512, nullptr, 2.f);
    k_fixdiag<<<1, 512>>>(S2);
    k_cvt<<<1024, 256>>>(S2, S2tf, 512*512);

    // ---- pack GCN weights, build per-bt W (tf32 direct) + bias ----
    k_pack<<<dim3(3072,2), 256>>>(gwp, gw, wp1, w1b, 128);
    k_pack<<<dim3(1536,2), 256>>>(uwp, uw, wp2, w2b, 64);
    k_bvec<<<768, 128>>>(ne2, gbp, gb, b1, 128);
    k_bvec<<<768, 64 >>>(ne2, ubp, ub, b2, 64);
    gemm_rr_k<64,64,16,4,4,256,1><<<dim3(384,12,1), 256>>>(
        ne2, 0, wp1, 0, W1tf, 0, 32, 24576, 24576, 32, w1b, 1.f);
    gemm_rr_k<64,64,16,4,4,256,1><<<dim3(192,12,1), 256>>>(
        ne2, 0, wp2, 0, W2tf, 0, 32, 12288, 12288, 32, w2b, 1.f);

    // ---- attention path ----
    k_small<<<dim3(64,14), 64>>>(ne1, ne2, Wq, bq, Wk, bk, Wv, bv, aq, ak, av);
    k_proj<<<dim3(512,4), 256>>>(h_n, Wq, Wk, Wv, taw, ak, av, xq, kb2, vb2, xw0);
    k_attn<<<dim3(16,64), 256>>>(aq, xq, kb2, sm);
    k_debuild<<<dim3(16,12,64), 256>>>(sm, vb2, xw0, taw, tab, de, xgtf1);

    // ---- GCN1: fused dual-support + contraction ----
    k_supp2_mma<<<dim3(4,384), 256, SUPP2_SMEM>>>(xgtf1, Atf, S2tf,
                                                  xgtf1 + 64*512, xgtf1 + 128*512);
    k_ctr_mma<128,4,4,2><<<dim3(4,768), 256, CTR1_SMEM>>>(xgtf1, W1tf, b1, zr);

    // ---- GCN2 ----
    k_gate<<<dim3(16,768), dim3(32,32)>>>(zr, de, xgtf2);
    k_supp2_mma<<<dim3(4,384), 256, SUPP2_SMEM>>>(xgtf2, Atf, S2tf,
                                                  xgtf2 + 64*512, xgtf2 + 128*512);
    k_ctr_mma<64,2,4,4><<<dim3(4,768), 256, CTR2_SMEM>>>(xgtf2, W2tf, b2, hc);

    // ---- final blend + output head ----
    k_final<<<dim3(16,768), 256>>>(zr, de, hc, outw, outb, out);
}

// round 8
// speedup vs baseline: 2.9082x; 1.1541x over previous
#include <cuda_runtime.h>
#include <cuda_fp16.h>
#include <math.h>
#include <stdint.h>

// Problem constants: B=64, T=12, N=512, H=64, TD=32, ED=16, CHEB_K=3, D_HEADS=8
// BT = 768. Effective GCN channels = 64 (channel 0 is identically zero).

// -------------------- static device scratch --------------------------------
static __device__ float g_Arm[512*512];            // A row-major
static __device__ float g_S2 [512*512];            // 2A^2 - I row-major
static __device__ __half g_Ahf [512*512];          // fp16 copies (support B operands)
static __device__ __half g_S2hf[512*512];
static __device__ float g_kb [64*512*64];
static __device__ float g_vb [64*512*64];
static __device__ float g_xq [64*512*64];
static __device__ float g_xw0[64*512*64];
static __device__ float g_aq [64*12*64];
static __device__ float g_ak [64*64];
static __device__ float g_av [64*64];
static __device__ float g_sm [64*512*12*8];
static __device__ float g_de [768*64*512];         // de f32 (channel-major)
static __device__ __half g_dehf[768*64*512];       // de fp16 (support A operand)
static __device__ __half g_chf [768*64*512];       // cand fp16
static __device__ uint32_t g_xgtf1[768*192*512];   // tf32 [bt][j][n] (contraction A)
static __device__ uint32_t g_xgtf2[768*192*512];
static __device__ uint32_t g_W1tf[768*192*128];
static __device__ uint32_t g_W2tf[768*192*64];
static __device__ float g_b1 [768*128];
static __device__ float g_b2 [768*64];
static __device__ float g_wp1[32*192*128];
static __device__ float g_w1b[192*128];
static __device__ float g_wp2[32*192*64];
static __device__ float g_w2b[192*64];
static __device__ float g_zr [768*512*128];
static __device__ float g_hc [768*512*64];

// -------------------- helpers ----------------------------------------------
__device__ __forceinline__ uint32_t f2tf32(float f){
    uint32_t u; asm("cvt.rna.tf32.f32 %0, %1;" : "=r"(u) : "f"(f)); return u;
}
__device__ __forceinline__ void cp16(void* dst, const void* src){
    uint32_t d;
    asm("{ .reg .u64 t; cvta.to.shared.u64 t, %1; cvt.u32.u64 %0, t; }" : "=r"(d) : "l"(dst));
    asm volatile("cp.async.cg.shared.global [%0], [%1], 16;" :: "r"(d), "l"(src));
}
__device__ __forceinline__ void mma_tf32(float* c, const uint32_t* a, const uint32_t* b){
    asm volatile(
        "mma.sync.aligned.m16n8k8.row.col.f32.tf32.tf32.f32 "
        "{%0,%1,%2,%3}, {%4,%5,%6,%7}, {%8,%9}, {%0,%1,%2,%3};"
        : "+f"(c[0]),"+f"(c[1]),"+f"(c[2]),"+f"(c[3])
        : "r"(a[0]),"r"(a[1]),"r"(a[2]),"r"(a[3]), "r"(b[0]),"r"(b[1]));
}
__device__ __forceinline__ void mma_f16(float* c, const uint32_t* a, const uint32_t* b){
    asm volatile(
        "mma.sync.aligned.m16n8k16.row.col.f32.f16.f16.f32 "
        "{%0,%1,%2,%3}, {%4,%5,%6,%7}, {%8,%9}, {%0,%1,%2,%3};"
        : "+f"(c[0]),"+f"(c[1]),"+f"(c[2]),"+f"(c[3])
        : "r"(a[0]),"r"(a[1]),"r"(a[2]),"r"(a[3]), "r"(b[0]),"r"(b[1]));
}

// -------------------- fused dual support GEMM (fp16 HMMA) ------------------
// grid (4 n-tiles, 384 bt-pairs), 256 threads.
// For both Bm in {A, S2}: C[r][n] = sum_k x[r][k]*Bm[n][k];
// r=0..127 -> bt=2p+(r>>6), c=r&63.  x rows = dehf/chf [bt][c][*] fp16.
// Outputs written tf32 into rows 64-127 (A) and 128-191 (S2) of xgtf.
__global__ void __launch_bounds__(256) k_supp2_hmma(
    const __half* __restrict__ xhf,
    const __half* __restrict__ B1hf,    // A   [512][512] fp16 row-major
    const __half* __restrict__ B2hf,    // S2  [512][512] fp16 row-major
    uint32_t* __restrict__ out1,        // xgtf + 64*512
    uint32_t* __restrict__ out2)        // xgtf + 128*512
{
    constexpr int LD = 20;              // 16 uints (32 halves) + 4 pad
    extern __shared__ uint32_t sh[];
    uint32_t* As  = sh;                 // [2][128*20]
    uint32_t* B1s = sh + 2*128*LD;
    uint32_t* B2s = sh + 4*128*LD;
    const int tid = threadIdx.x, wid = tid>>5, lane = tid&31;
    const int g = lane>>2, tg = lane&3;
    const int p = blockIdx.y, n0 = blockIdx.x*128;
    const int wm = wid & 1, wn = wid >> 1;
    const int mbase = wm*64, nbase = wn*32;

    float c[2][4][4][4];
#pragma unroll
    for (int s=0;s<2;s++)
#pragma unroll
        for (int i=0;i<4;i++)
#pragma unroll
            for (int j=0;j<4;j++)
#pragma unroll
                for (int q=0;q<4;q++) c[s][i][j][q]=0.f;

    auto load = [&](int ch, int sel){
        uint32_t* a  = As  + sel*128*LD;
        uint32_t* b1 = B1s + sel*128*LD;
        uint32_t* b2 = B2s + sel*128*LD;
        const int k0 = ch*32;           // in halves
#pragma unroll
        for (int it = 0; it < 2; it++){
            int lin = tid + it*256;
            int r = lin >> 2, q = lin & 3;
            cp16(a  + r*LD + q*4,
                 xhf + (size_t)(2*p + (r>>6))*32768 + (size_t)(r&63)*512 + k0 + q*8);
            cp16(b1 + r*LD + q*4, B1hf + (size_t)(n0 + r)*512 + k0 + q*8);
            cp16(b2 + r*LD + q*4, B2hf + (size_t)(n0 + r)*512 + k0 + q*8);
        }
        asm volatile("cp.async.commit_group;" ::: "memory");
    };

    load(0, 0);
    for (int i = 0; i < 16; i++){
        const int cur = i & 1;
        if (i + 1 < 16){
            load(i+1, cur^1);
            asm volatile("cp.async.wait_group 1;" ::: "memory");
        } else {
            asm volatile("cp.async.wait_group 0;" ::: "memory");
        }
        __syncthreads();
        const uint32_t* a  = As  + cur*128*LD;
        const uint32_t* b1 = B1s + cur*128*LD;
        const uint32_t* b2 = B2s + cur*128*LD;
#pragma unroll
        for (int ks = 0; ks < 2; ks++){     // 2 x k16 per 32-half chunk
            uint32_t af[4][4], bf1[4][2], bf2[4][2];
#pragma unroll
            for (int mt = 0; mt < 4; mt++){
                int row = mbase + mt*16 + g;
                af[mt][0] = a[ row   *LD + ks*8 + tg    ];
                af[mt][1] = a[(row+8)*LD + ks*8 + tg    ];
                af[mt][2] = a[ row   *LD + ks*8 + tg + 4];
                af[mt][3] = a[(row+8)*LD + ks*8 + tg + 4];
            }
#pragma unroll
            for (int nt = 0; nt < 4; nt++){
                int nr = nbase + nt*8 + g;
                bf1[nt][0] = b1[nr*LD + ks*8 + tg    ];
                bf1[nt][1] = b1[nr*LD + ks*8 + tg + 4];
                bf2[nt][0] = b2[nr*LD + ks*8 + tg    ];
                bf2[nt][1] = b2[nr*LD + ks*8 + tg + 4];
            }
#pragma unroll
            for (int mt = 0; mt < 4; mt++)
#pragma unroll
                for (int nt = 0; nt < 4; nt++){
                    mma_f16(c[0][mt][nt], af[mt], bf1[nt]);
                    mma_f16(c[1][mt][nt], af[mt], bf2[nt]);
                }
        }
        __syncthreads();
    }

    // epilogue: convert to tf32, store both outputs
#pragma unroll
    for (int s = 0; s < 2; s++){
        uint32_t* outp = s ? out2 : out1;
#pragma unroll
        for (int mt = 0; mt < 4; mt++){
            int r0 = mbase + mt*16 + g;
#pragma unroll
            for (int half = 0; half < 2; half++){
                int r = r0 + half*8;
                uint32_t* orow = outp + (size_t)(2*p + (r>>6))*98304
                               + (size_t)(r&63)*512 + n0 + nbase;
#pragma unroll
                for (int nt = 0; nt < 4; nt++){
                    uint2 u;
                    u.x = f2tf32(c[s][mt][nt][half*2+0]);
                    u.y = f2tf32(c[s][mt][nt][half*2+1]);
                    *(uint2*)(orow + nt*8 + tg*2) = u;
                }
            }
        }
    }
}

// -------------------- contraction GEMM (mma.sync tf32) ---------------------
// C[n][o] = sum_k xg[k][n] * W[k][o] + bias[o];  per-bt batch.
template<int BN, int MT, int NTT, int WARPS_M>
__global__ void __launch_bounds__(256) k_ctr_mma(
    const uint32_t* __restrict__ xtf,   // [768][192][512] tf32
    const uint32_t* __restrict__ Wtf,   // [768][192][BN] tf32
    const float* __restrict__ bias,     // [768][BN]
    float* __restrict__ outp)           // [768][512][BN]
{
    constexpr int LDA = 132;            // 128 + 4
    constexpr int LDB = BN + 4;
    constexpr int NC  = 6;              // K=192 / 32
    extern __shared__ uint32_t sh[];
    uint32_t* As = sh;                  // [2][32*LDA]
    uint32_t* Bs = sh + 2*32*LDA;       // [2][32*LDB]
    const int tid = threadIdx.x, wid = tid>>5, lane = tid&31;
    const int g = lane>>2, tg = lane&3;
    const int bt = blockIdx.y, m0 = blockIdx.x*128;
    const int wm = wid % WARPS_M, wn = wid / WARPS_M;
    const int mbase = wm*(MT*16), nbase = wn*(NTT*8);
    const uint32_t* Ab = xtf + (size_t)bt*98304 + m0;
    const uint32_t* Bb = Wtf + (size_t)bt*192*BN;

    float c[MT][NTT][4];
#pragma unroll
    for (int i=0;i<MT;i++)
#pragma unroll
        for (int j=0;j<NTT;j++)
#pragma unroll
            for (int q=0;q<4;q++) c[i][j][q]=0.f;

    auto load = [&](int ch, int sel){
        uint32_t* a = As + sel*32*LDA;
        uint32_t* b = Bs + sel*32*LDB;
        const int k0 = ch*32;
#pragma unroll
        for (int it = 0; it < 4; it++){
            int lin = tid + it*256;
            int kr = lin >> 5, q = lin & 31;
            cp16(a + kr*LDA + q*4, Ab + (size_t)(k0+kr)*512 + q*4);
        }
#pragma unroll
        for (int it = 0; it < 32*BN/4/256; it++){
            int lin = tid + it*256;
            int kr = lin / (BN/4), q = lin % (BN/4);
            cp16(b + kr*LDB + q*4, Bb + (size_t)(k0+kr)*BN + q*4);
        }
        asm volatile("cp.async.commit_group;" ::: "memory");
    };

    load(0, 0);
    for (int i = 0; i < NC; i++){
        const int cur = i & 1;
        if (i + 1 < NC){
            load(i+1, cur^1);
            asm volatile("cp.async.wait_group 1;" ::: "memory");
        } else {
            asm volatile("cp.async.wait_group 0;" ::: "memory");
        }
        __syncthreads();
        const uint32_t* a = As + cur*32*LDA;
        const uint32_t* b = Bs + cur*32*LDB;
#pragma unroll
        for (int ks = 0; ks < 4; ks++){
            uint32_t af[MT][4], bf[NTT][2];
#pragma unroll
            for (int mt = 0; mt < MT; mt++){
                int m = mbase + mt*16 + g;
                af[mt][0] = a[(ks*8+tg  )*LDA + m    ];
                af[mt][1] = a[(ks*8+tg  )*LDA + m + 8];
                af[mt][2] = a[(ks*8+tg+4)*LDA + m    ];
                af[mt][3] = a[(ks*8+tg+4)*LDA + m + 8];
            }
#pragma unroll
            for (int nt = 0; nt < NTT; nt++){
                int o = nbase + nt*8 + g;
                bf[nt][0] = b[(ks*8+tg  )*LDB + o];
                bf[nt][1] = b[(ks*8+tg+4)*LDB + o];
            }
#pragma unroll
            for (int mt = 0; mt < MT; mt++)
#pragma unroll
                for (int nt = 0; nt < NTT; nt++)
                    mma_tf32(c[mt][nt], af[mt], bf[nt]);
        }
        __syncthreads();
    }

#pragma unroll
    for (int mt = 0; mt < MT; mt++){
        int n_ = m0 + mbase + mt*16 + g;
#pragma unroll
        for (int half = 0; half < 2; half++){
            float* orow = outp + ((size_t)bt*512 + n_ + half*8)*BN;
#pragma unroll
            for (int nt = 0; nt < NTT; nt++){
                int o = nbase + nt*8 + tg*2;
                float2 v;
                v.x = c[mt][nt][half*2+0] + bias[bt*BN + o];
                v.y = c[mt][nt][half*2+1] + bias[bt*BN + o + 1];
                *(float2*)(orow + o) = v;
            }
        }
    }
}

// -------------------- adjacency: A row-major + fp16 ------------------------
__global__ void k_A(const float* __restrict__ E, float* __restrict__ Arm,
                    __half* __restrict__ Ahf)
{
    __shared__ float Es[512*16];
    __shared__ float red[512];
    const int tid = threadIdx.x;
    const int n   = blockIdx.x;
    for (int i = tid; i < 512*16; i += 512) Es[i] = E[i];
    __syncthreads();
    float acc = 0.f;
#pragma unroll
    for (int d = 0; d < 16; d++) acc += Es[n*16+d]*Es[tid*16+d];
    acc = fmaxf(acc, 0.f);
    red[tid] = acc; __syncthreads();
    for (int s = 256; s > 0; s >>= 1){ if (tid < s) red[tid] = fmaxf(red[tid], red[tid+s]); __syncthreads(); }
    float mx = red[0]; __syncthreads();
    float e = expf(acc - mx);
    red[tid] = e; __syncthreads();
    for (int s = 256; s > 0; s >>= 1){ if (tid < s) red[tid] += red[tid+s]; __syncthreads(); }
    float v = e / red[0];
    Arm[n*512 + tid] = v;
    Ahf[n*512 + tid] = __float2half(v);
}

__global__ void k_fixdiag(float* __restrict__ S)
{
    int i = threadIdx.x;
    S[i*512 + i] -= 1.f;
}

__global__ void k_cvt_h(const float* __restrict__ s, __half* __restrict__ d, int n)
{
    int i = blockIdx.x*256 + threadIdx.x;
    if (i < n) d[i] = __float2half(s[i]);
}

// -------------------- generic SGEMM, A row-major ---------------------------
// OUTMODE: 0 = f32 out, 1 = tf32 (uint) out
template<int BM,int BN,int BK,int TM,int TN,int NT,int OUTMODE>
__global__ void __launch_bounds__(NT) gemm_rr_k(
    const float* __restrict__ Abase, long aStr,
    const float* __restrict__ Bbase, long bStr,
    void* __restrict__ Cbase, long cStr,
    int lda, int ldb, int ldc, int K,
    const float* __restrict__ colBias, float alpha)
{
    __shared__ float As[BK][BM];
    __shared__ float Bs[BK][BN];
    const int tid = threadIdx.x;
    const int bz  = blockIdx.z;
    const int m0  = blockIdx.y*BM;
    const int n0  = blockIdx.x*BN;
    const float* A = Abase + (long)bz*aStr + (long)m0*lda;
    const float* B = Bbase + (long)bz*bStr + n0;
    const int tx = tid % (BN/TN);
    const int ty = tid / (BN/TN);
    float acc[TM][TN];
#pragma unroll
    for (int i=0;i<TM;i++)
#pragma unroll
        for (int j=0;j<TN;j++) acc[i][j]=0.f;

    for (int k0 = 0; k0 < K; k0 += BK){
        for (int li = tid; li < BM*BK/4; li += NT){
            int m  = li/(BK/4), kv = li%(BK/4);
            float4 v = *(const float4*)(A + (long)m*lda + k0 + kv*4);
            As[kv*4+0][m]=v.x; As[kv*4+1][m]=v.y; As[kv*4+2][m]=v.z; As[kv*4+3][m]=v.w;
        }
        for (int li = tid; li < BN*BK/4; li += NT){
            int k  = li/(BN/4), nv = li%(BN/4);
            *(float4*)&Bs[k][nv*4] = *(const float4*)(B + (long)(k0+k)*ldb + nv*4);
        }
        __syncthreads();
#pragma unroll
        for (int kk = 0; kk < BK; kk++){
            float a[TM], bb[TN];
#pragma unroll
            for (int i=0;i<TM;i+=4) *(float4*)&a[i]  = *(const float4*)&As[kk][ty*TM+i];
#pragma unroll
            for (int j=0;j<TN;j+=4) *(float4*)&bb[j] = *(const float4*)&Bs[kk][tx*TN+j];
#pragma unroll
            for (int i=0;i<TM;i++)
#pragma unroll
                for (int j=0;j<TN;j++) acc[i][j] += a[i]*bb[j];
        }
        __syncthreads();
    }
#pragma unroll
    for (int i=0;i<TM;i++){
#pragma unroll
        for (int j=0;j<TN;j+=4){
            float4 v;
            v.x=acc[i][j+0]*alpha; v.y=acc[i][j+1]*alpha;
            v.z=acc[i][j+2]*alpha; v.w=acc[i][j+3]*alpha;
            if (colBias){
                const float* cb = colBias + n0 + tx*TN + j;
                v.x+=cb[0]; v.y+=cb[1]; v.z+=cb[2]; v.w+=cb[3];
            }
            long coff = (long)bz*cStr + (long)(m0+ty*TM+i)*ldc + n0 + tx*TN + j;
            if (OUTMODE == 0){
                *(float4*)((float*)Cbase + coff) = v;
            } else {
                uint4 u;
                u.x=f2tf32(v.x); u.y=f2tf32(v.y); u.z=f2tf32(v.z); u.w=f2tf32(v.w);
                *(uint4*)((uint32_t*)Cbase + coff) = u;
            }
        }
    }
}

// -------------------- pack gwp/uwp (drop channel 0) ------------------------
__global__ void k_pack(const float* __restrict__ wp, const float* __restrict__ w,
                       float* __restrict__ pwp, float* __restrict__ pw, int O)
{
    int idx = blockIdx.x*blockDim.x + threadIdx.x;
    if (blockIdx.y == 0){
        if (idx < 32*192*O){
            int o = idx % O; int r = idx / O;
            int c = r % 64;  int k = (r/64)%3; int d = r/192;
            pwp[idx] = wp[(((d*3 + k)*65) + (c+1))*O + o];
        }
    } else {
        if (idx < 192*O){
            int o = idx % O; int r = idx / O;
            int c = r % 64;  int k = r/64;
            pw[idx] = w[((k*65) + (c+1))*O + o];
        }
    }
}

// -------------------- bias vectors: temb@bp + b0 ---------------------------
__global__ void k_bvec(const float* __restrict__ temb, const float* __restrict__ bp,
                       const float* __restrict__ b0, float* __restrict__ out, int O)
{
    int bt = blockIdx.x; int o = threadIdx.x;
    float acc = b0[o];
#pragma unroll
    for (int d = 0; d < 32; d++) acc += temb[bt*32+d]*bp[d*O+o];
    out[bt*O+o] = acc;
}

// -------------------- small STE projections --------------------------------
__global__ void k_small(const float* __restrict__ ne1, const float* __restrict__ ne2,
                        const float* __restrict__ Wq, const float* __restrict__ bq,
                        const float* __restrict__ Wk, const float* __restrict__ bk,
                        const float* __restrict__ Wv, const float* __restrict__ bv,
                        float* __restrict__ aq, float* __restrict__ ak, float* __restrict__ av)
{
    int b = blockIdx.x, y = blockIdx.y, h = threadIdx.x;
    const float *src, *W, *bias; float* out;
    if (y < 12)      { src = ne2 + (b*12+y)*32;  W = Wq; bias = bq; out = aq + (b*12+y)*64; }
    else if (y == 12){ src = ne1 + (b*12+11)*32; W = Wk; bias = bk; out = ak + b*64; }
    else             { src = ne1 + (b*12+11)*32; W = Wv; bias = bv; out = av + b*64; }
    float acc = bias[h];
#pragma unroll
    for (int d = 0; d < 32; d++) acc += src[d]*W[d*64+h];
    out[h] = acc;
}

// -------------------- X projections (xq, k, v, xw0) ------------------------
__global__ void __launch_bounds__(256) k_proj(
    const float* __restrict__ X,
    const float* __restrict__ Wq, const float* __restrict__ Wk,
    const float* __restrict__ Wv, const float* __restrict__ taw,
    const float* __restrict__ ak, const float* __restrict__ av,
    float* __restrict__ xq, float* __restrict__ kb,
    float* __restrict__ vb, float* __restrict__ xw0)
{
    __shared__ float Xs[64][64];
    __shared__ float Ws[64][64];
    const int tid  = threadIdx.x;
    const int mode = blockIdx.y;
    const int m0   = blockIdx.x*64;
    const int b    = m0 >> 9;
    const float* W = (mode==0)? Wq+2048 : (mode==1)? Wk+2048 : (mode==2)? Wv+2048 : taw;
    for (int li = tid; li < 1024; li += 256){
        int m = li>>4, kv = li&15;
        float4 v = *(const float4*)(X + (long)(m0+m)*64 + kv*4);
        Xs[kv*4+0][m]=v.x; Xs[kv*4+1][m]=v.y; Xs[kv*4+2][m]=v.z; Xs[kv*4+3][m]=v.w;
        *(float4*)&Ws[m][kv*4] = *(const float4*)(W + m*64 + kv*4);
    }
    __syncthreads();
    const int tx = tid&15, ty = tid>>4;
    float acc[4][4];
#pragma unroll
    for (int i=0;i<4;i++)
#pragma unroll
        for (int j=0;j<4;j++) acc[i][j]=0.f;
#pragma unroll
    for (int kk = 0; kk < 64; kk++){
        float a[4], bb[4];
        *(float4*)a  = *(const float4*)&Xs[kk][ty*4];
        *(float4*)bb = *(const float4*)&Ws[kk][tx*4];
#pragma unroll
        for (int i=0;i<4;i++)
#pragma unroll
            for (int j=0;j<4;j++) acc[i][j] += a[i]*bb[j];
    }
    float* outp = (mode==0)? xq : (mode==1)? kb : (mode==2)? vb : xw0;
#pragma unroll
    for (int i=0;i<4;i++){
        int m = m0 + ty*4 + i;
        float4 r;
        if (mode==1 || mode==2){
            const float* bias = ((mode==1)? ak:av) + b*64 + tx*4;
            r.x=fmaxf(acc[i][0]+bias[0],0.f); r.y=fmaxf(acc[i][1]+bias[1],0.f);
            r.z=fmaxf(acc[i][2]+bias[2],0.f); r.w=fmaxf(acc[i][3]+bias[3],0.f);
        } else {
            r.x=acc[i][0]; r.y=acc[i][1]; r.z=acc[i][2]; r.w=acc[i][3];
        }
        *(float4*)(outp + (long)m*64 + tx*4) = r;
    }
}

// -------------------- attention scores + softmax ---------------------------
__global__ void __launch_bounds__(256) k_attn(
    const float* __restrict__ aq, const float* __restrict__ xq,
    const float* __restrict__ kb, float* __restrict__ sm_out)
{
    __shared__ float aq_s[768];
    const int b = blockIdx.y;
    const int tid = threadIdx.x, lane = tid&31, w = tid>>5;
    for (int i = tid; i < 768; i += 256) aq_s[i] = aq[b*768 + i];
    __syncthreads();
    const int n0 = blockIdx.x*32 + w*4;
    for (int j = 0; j < 4; j++){
        int bn = b*512 + n0 + j;
        float xq0 = xq[bn*64 + lane],      xq1 = xq[bn*64 + 32 + lane];
        float k0  = kb[bn*64 + lane],      k1  = kb[bn*64 + 32 + lane];
        float sc0[12], sc1[12];
#pragma unroll
        for (int t = 0; t < 12; t++){
            float q0 = fmaxf(aq_s[t*64 + lane] + xq0, 0.f);
            float q1 = fmaxf(aq_s[t*64 + 32 + lane] + xq1, 0.f);
            float p0 = q0*k0, p1 = q1*k1;
#pragma unroll
            for (int o = 1; o < 8; o <<= 1){
                p0 += __shfl_xor_sync(0xffffffffu, p0, o);
                p1 += __shfl_xor_sync(0xffffffffu, p1, o);
            }
            sc0[t] = p0; sc1[t] = p1;
        }
        float m0 = -1e30f, m1 = -1e30f;
#pragma unroll
        for (int t = 0; t < 12; t++){ m0 = fmaxf(m0, sc0[t]); m1 = fmaxf(m1, sc1[t]); }
        float s0 = 0.f, s1 = 0.f;
#pragma unroll
        for (int t = 0; t < 12; t++){ sc0[t] = expf(sc0[t]-m0); s0 += sc0[t];
                                      sc1[t] = expf(sc1[t]-m1); s1 += sc1[t]; }
        float r0 = 1.f/s0, r1 = 1.f/s1;
        if ((lane & 7) == 0){
            int d = lane >> 3;
#pragma unroll
            for (int t = 0; t < 12; t++){
                sm_out[bn*96 + t*8 + d]     = sc0[t]*r0;
                sm_out[bn*96 + t*8 + 4 + d] = sc1[t]*r1;
            }
        }
    }
}

// -------------------- build de (f32 + tf32 + fp16 copies) ------------------
__global__ void __launch_bounds__(256) k_debuild(
    const float* __restrict__ sm, const float* __restrict__ vb,
    const float* __restrict__ xw0, const float* __restrict__ taw,
    const float* __restrict__ tab, float* __restrict__ de,
    uint32_t* __restrict__ detf, __half* __restrict__ dehf)
{
    __shared__ float taw1s[64][64];
    __shared__ float wvT[64][33];
    __shared__ float xw0s[64][33];
    const int b = blockIdx.z, t = blockIdx.y, n0 = blockIdx.x*32;
    const int tid = threadIdx.x;
    for (int i = tid; i < 4096; i += 256)
        taw1s[i>>6][i&63] = taw[4096 + i];
    for (int idx = tid; idx < 2048; idx += 256){
        int nl = idx >> 6, i = idx & 63;
        int bn = b*512 + n0 + nl;
        float s = sm[bn*96 + t*8 + (i>>3)];
        wvT[i][nl]  = s * vb[bn*64 + i];
        xw0s[i][nl] = xw0[bn*64 + i];
    }
    __syncthreads();
    const int tx = tid & 15, ty = tid >> 4;
    float acc[4][2] = {};
#pragma unroll
    for (int i = 0; i < 64; i++){
        float4 a = *(const float4*)&taw1s[i][ty*4];
        float b0 = wvT[i][tx*2], b1 = wvT[i][tx*2+1];
        acc[0][0]+=a.x*b0; acc[0][1]+=a.x*b1;
        acc[1][0]+=a.y*b0; acc[1][1]+=a.y*b1;
        acc[2][0]+=a.z*b0; acc[2][1]+=a.z*b1;
        acc[3][0]+=a.w*b0; acc[3][1]+=a.w*b1;
    }
    const int bt = b*12 + t;
    long baseD = (long)bt*32768;
    long baseT = (long)bt*98304;
#pragma unroll
    for (int oi = 0; oi < 4; oi++){
        int o = ty*4 + oi;
        float bias = tab[o];
        float2 v;
        v.x = acc[oi][0] + xw0s[o][tx*2]   + bias;
        v.y = acc[oi][1] + xw0s[o][tx*2+1] + bias;
        *(float2*)&de[baseD + (long)o*512 + n0 + tx*2] = v;
        uint2 u; u.x = f2tf32(v.x); u.y = f2tf32(v.y);
        *(uint2*)&detf[baseT + (long)o*512 + n0 + tx*2] = u;
        __half2 h2 = __floats2half2_rn(v.x, v.y);
        *(__half2*)&dehf[baseD + (long)o*512 + n0 + tx*2] = h2;
    }
}

// -------------------- gate: cand = sigmoid(z)*de (tf32 + fp16 out) ---------
__global__ void k_gate(const float* __restrict__ zr, const float* __restrict__ de,
                       uint32_t* __restrict__ ctf, __half* __restrict__ chf)
{
    __shared__ float s[32][33];
    const int bt = blockIdx.y, n0 = blockIdx.x*32;
    const int tx = threadIdx.x, ty = threadIdx.y;
    for (int ch = 0; ch < 2; ch++){
        int c0 = ch*32;
        s[ty][tx] = zr[bt*65536 + (n0+ty)*128 + c0 + tx];
        __syncthreads();
        int c = c0 + ty;
        float z = 1.f/(1.f + expf(-s[tx][ty]));
        float val = z * de[(long)bt*32768 + (long)c*512 + n0 + tx];
        ctf[(long)bt*98304 + (long)c*512 + n0 + tx] = f2tf32(val);
        chf[(long)bt*32768 + (long)c*512 + n0 + tx] = __float2half(val);
        __syncthreads();
    }
}

// -------------------- final: state blend + output head ---------------------
__global__ void __launch_bounds__(256) k_final(
    const float* __restrict__ zr, const float* __restrict__ de,
    const float* __restrict__ hc, const float* __restrict__ out_w,
    const float* __restrict__ out_b, float* __restrict__ out)
{
    __shared__ float de_s[64][33];
    __shared__ float red[8][32];
    __shared__ float w_s[64];
    const int bt = blockIdx.y, n0 = blockIdx.x*32;
    const int tt = bt % 12;
    const int tid = threadIdx.x;
    if (tid < 64) w_s[tid] = out_w[tt*64 + tid];
    for (int i = tid; i < 2048; i += 256){
        int h = i >> 5, nl = i & 31;
        de_s[h][nl] = de[(long)bt*32768 + h*512 + n0 + nl];
    }
    __syncthreads();
    const int nl = tid & 31, hg = tid >> 5;
    const int rg_off = bt*65536 + (n0+nl)*128 + 64;
    const int hc_off = bt*32768 + (n0+nl)*64;
    float partial = 0.f;
#pragma unroll
    for (int j = 0; j < 8; j++){
        int h = hg*8 + j;
        float rg  = 1.f/(1.f + expf(-zr[rg_off + h]));
        float hcv = tanhf(hc[hc_off + h]);
        float st  = rg*de_s[h][nl] + (1.f-rg)*hcv;
        partial  += st * w_s[h];
    }
    red[hg][nl] = partial;
    __syncthreads();
    if (tid < 32){
        float sum = 0.f;
#pragma unroll
        for (int g = 0; g < 8; g++) sum += red[g][tid];
        out[bt*512 + n0 + tid] = sum + out_b[tt];
    }
}

// ===========================================================================
extern "C" void kernel_launch(void* const* d_in, const int* in_sizes, int n_in,
                              void* d_out, int out_size)
{
    const float* h_n  = (const float*)d_in[2];
    const float* ne1  = (const float*)d_in[3];
    const float* ne2  = (const float*)d_in[4];
    const float* E    = (const float*)d_in[5];
    const float* Wq   = (const float*)d_in[6];
    const float* bq   = (const float*)d_in[7];
    const float* Wk   = (const float*)d_in[8];
    const float* bk   = (const float*)d_in[9];
    const float* Wv   = (const float*)d_in[10];
    const float* bv   = (const float*)d_in[11];
    const float* taw  = (const float*)d_in[12];
    const float* tab  = (const float*)d_in[13];
    const float* gwp  = (const float*)d_in[14];
    const float* gw   = (const float*)d_in[15];
    const float* gbp  = (const float*)d_in[16];
    const float* gb   = (const float*)d_in[17];
    const float* uwp  = (const float*)d_in[18];
    const float* uw   = (const float*)d_in[19];
    const float* ubp  = (const float*)d_in[20];
    const float* ub   = (const float*)d_in[21];
    const float* outw = (const float*)d_in[22];
    const float* outb = (const float*)d_in[23];
    float* out = (float*)d_out;

    float *Arm, *S2, *kb2, *vb2, *xq, *xw0, *aq, *ak, *av, *sm, *de;
    float *b1, *b2, *wp1, *w1b, *wp2, *w2b, *zr, *hc;
    uint32_t *xgtf1, *xgtf2, *W1tf, *W2tf;
    __half *Ahf, *S2hf, *dehf, *chf;
    cudaGetSymbolAddress((void**)&Arm,  g_Arm);
    cudaGetSymbolAddress((void**)&S2,   g_S2);
    cudaGetSymbolAddress((void**)&Ahf,  g_Ahf);
    cudaGetSymbolAddress((void**)&S2hf, g_S2hf);
    cudaGetSymbolAddress((void**)&kb2,  g_kb);
    cudaGetSymbolAddress((void**)&vb2,  g_vb);
    cudaGetSymbolAddress((void**)&xq,   g_xq);
    cudaGetSymbolAddress((void**)&xw0,  g_xw0);
    cudaGetSymbolAddress((void**)&aq,   g_aq);
    cudaGetSymbolAddress((void**)&ak,   g_ak);
    cudaGetSymbolAddress((void**)&av,   g_av);
    cudaGetSymbolAddress((void**)&sm,   g_sm);
    cudaGetSymbolAddress((void**)&de,   g_de);
    cudaGetSymbolAddress((void**)&dehf, g_dehf);
    cudaGetSymbolAddress((void**)&chf,  g_chf);
    cudaGetSymbolAddress((void**)&xgtf1,g_xgtf1);
    cudaGetSymbolAddress((void**)&xgtf2,g_xgtf2);
    cudaGetSymbolAddress((void**)&W1tf, g_W1tf);
    cudaGetSymbolAddress((void**)&W2tf, g_W2tf);
    cudaGetSymbolAddress((void**)&b1,   g_b1);
    cudaGetSymbolAddress((void**)&b2,   g_b2);
    cudaGetSymbolAddress((void**)&wp1,  g_wp1);
    cudaGetSymbolAddress((void**)&w1b,  g_w1b);
    cudaGetSymbolAddress((void**)&wp2,  g_wp2);
    cudaGetSymbolAddress((void**)&w2b,  g_w2b);
    cudaGetSymbolAddress((void**)&zr,   g_zr);
    cudaGetSymbolAddress((void**)&hc,   g_hc);

    const int SUPP2_SMEM = 6*128*20*4;                  // 61440
    const int CTR1_SMEM = (2*32*132 + 2*32*132)*4;      // 67584
    const int CTR2_SMEM = (2*32*132 + 2*32*68)*4;       // 51200
    cudaFuncSetAttribute(k_supp2_hmma, cudaFuncAttributeMaxDynamicSharedMemorySize, SUPP2_SMEM);
    cudaFuncSetAttribute(k_ctr_mma<128,4,4,2>, cudaFuncAttributeMaxDynamicSharedMemorySize, CTR1_SMEM);
    cudaFuncSetAttribute(k_ctr_mma<64,2,4,4>,  cudaFuncAttributeMaxDynamicSharedMemorySize, CTR2_SMEM);

    // ---- adjacency & supports ----
    k_A<<<512, 512>>>(E, Arm, Ahf);
    gemm_rr_k<64,64,16,4,4,256,0><<<dim3(8,8,1), 256>>>(      // S2 = 2*A@A
        Arm, 0, Arm, 0, S2, 0, 512, 512, 512, 512, nullptr, 2.f);
    k_fixdiag<<<1, 512>>>(S2);
    k_cvt_h<<<1024, 256>>>(S2, S2hf, 512*512);

    // ---- pack GCN weights, build per-bt W (tf32 direct) + bias ----
    k_pack<<<dim3(3072,2), 256>>>(gwp, gw, wp1, w1b, 128);
    k_pack<<<dim3(1536,2), 256>>>(uwp, uw, wp2, w2b, 64);
    k_bvec<<<768, 128>>>(ne2, gbp, gb, b1, 128);
    k_bvec<<<768, 64 >>>(ne2, ubp, ub, b2, 64);
    gemm_rr_k<64,64,16,4,4,256,1><<<dim3(384,12,1), 256>>>(
        ne2, 0, wp1, 0, W1tf, 0, 32, 24576, 24576, 32, w1b, 1.f);
    gemm_rr_k<64,64,16,4,4,256,1><<<dim3(192,12,1), 256>>>(
        ne2, 0, wp2, 0, W2tf, 0, 32, 12288, 12288, 32, w2b, 1.f);

    // ---- attention path ----
    k_small<<<dim3(64,14), 64>>>(ne1, ne2, Wq, bq, Wk, bk, Wv, bv, aq, ak, av);
    k_proj<<<dim3(512,4), 256>>>(h_n, Wq, Wk, Wv, taw, ak, av, xq, kb2, vb2, xw0);
    k_attn<<<dim3(16,64), 256>>>(aq, xq, kb2, sm);
    k_debuild<<<dim3(16,12,64), 256>>>(sm, vb2, xw0, taw, tab, de, xgtf1, dehf);

    // ---- GCN1: fp16 dual-support + tf32 contraction ----
    k_supp2_hmma<<<dim3(4,384), 256, SUPP2_SMEM>>>(dehf, Ahf, S2hf,
                                                   xgtf1 + 64*512, xgtf1 + 128*512);
    k_ctr_mma<128,4,4,2><<<dim3(4,768), 256, CTR1_SMEM>>>(xgtf1, W1tf, b1, zr);

    // ---- GCN2 ----
    k_gate<<<dim3(16,768), dim3(32,32)>>>(zr, de, xgtf2, chf);
    k_supp2_hmma<<<dim3(4,384), 256, SUPP2_SMEM>>>(chf, Ahf, S2hf,
                                                   xgtf2 + 64*512, xgtf2 + 128*512);
    k_ctr_mma<64,2,4,4><<<dim3(4,768), 256, CTR2_SMEM>>>(xgtf2, W2tf, b2, hc);

    // ---- final blend + output head ----
    k_final<<<dim3(16,768), 256>>>(zr, de, hc, outw, outb, out);
}

// round 11
// speedup vs baseline: 3.2374x; 1.1132x over previous
#include <cuda_runtime.h>
#include <cuda_fp16.h>
#include <math.h>
#include <stdint.h>

// Problem constants: B=64, T=12, N=512, H=64, TD=32, ED=16, CHEB_K=3, D_HEADS=8
// BT = 768. Effective GCN channels = 64 (channel 0 is identically zero).

// -------------------- static device scratch --------------------------------
static __device__ float g_Arm[512*512];            // A row-major
static __device__ float g_S2 [512*512];            // 2A^2 - I row-major
static __device__ __half g_Ahf [512*512];          // fp16 support B operands
static __device__ __half g_S2hf[512*512];
static __device__ float g_kb [64*512*64];
static __device__ float g_vb [64*512*64];
static __device__ float g_xq [64*512*64];
static __device__ float g_xw0[64*512*64];
static __device__ float g_aq [64*12*64];
static __device__ float g_ak [64*64];
static __device__ float g_av [64*64];
static __device__ float g_sm [64*512*12*8];
static __device__ float g_de [768*64*512];         // de f32 (channel-major)
static __device__ __half g_xg1[768*192*512];       // fp16 [bt][j][n] j:0-63 de,64-127 A@,128-191 S2@
static __device__ __half g_xg2[768*192*512];       // same for cand
static __device__ __half g_W1hf[768*128*192];      // W' [bt][o][k] fp16
static __device__ __half g_W2hf[768*64*192];
static __device__ float g_b1 [768*128];
static __device__ float g_b2 [768*64];
static __device__ float g_wp1[32*128*192];         // packed [d][o][k]
static __device__ float g_w1b[128*192];
static __device__ float g_wp2[32*64*192];
static __device__ float g_w2b[64*192];
static __device__ float g_zr [768*512*128];
static __device__ float g_hc [768*512*64];

// -------------------- helpers ----------------------------------------------
__device__ __forceinline__ uint32_t smem_u32p(const void* p){
    uint32_t a;
    asm("{ .reg .u64 t; cvta.to.shared.u64 t, %1; cvt.u32.u64 %0, t; }" : "=r"(a) : "l"(p));
    return a;
}
__device__ __forceinline__ void cp16(void* dst, const void* src){
    uint32_t d = smem_u32p(dst);
    asm volatile("cp.async.cg.shared.global [%0], [%1], 16;" :: "r"(d), "l"(src));
}
__device__ __forceinline__ void mma_f16(float* c, const uint32_t* a, const uint32_t* b){
    asm volatile(
        "mma.sync.aligned.m16n8k16.row.col.f32.f16.f16.f32 "
        "{%0,%1,%2,%3}, {%4,%5,%6,%7}, {%8,%9}, {%0,%1,%2,%3};"
        : "+f"(c[0]),"+f"(c[1]),"+f"(c[2]),"+f"(c[3])
        : "r"(a[0]),"r"(a[1]),"r"(a[2]),"r"(a[3]), "r"(b[0]),"r"(b[1]));
}
__device__ __forceinline__ void ldmx4t(uint32_t* r, uint32_t addr){
    asm volatile("ldmatrix.sync.aligned.m8n8.x4.trans.shared.b16 {%0,%1,%2,%3}, [%4];"
        : "=r"(r[0]),"=r"(r[1]),"=r"(r[2]),"=r"(r[3]) : "r"(addr));
}
__device__ __forceinline__ uint32_t packh2(float x, float y){
    __half2 h = __floats2half2_rn(x, y);
    return *(uint32_t*)&h;
}

// -------------------- fused dual support GEMM (fp16 HMMA) ------------------
// grid (4 n-tiles, 384 bt-pairs), 256 threads.
// For both Bm in {A, S2}: C[r][n] = sum_k x[r][k]*Bm[n][k];
// r=0..127 -> bt=2p+(r>>6), c=r&63.  x rows = xg[bt][0..63][*] fp16.
// Outputs written fp16 into rows 64-127 (A) and 128-191 (S2) of xg.
__global__ void __launch_bounds__(256) k_supp2_hmma(
    const __half* __restrict__ xhf,     // xg base (rows 0-63 used)
    const __half* __restrict__ B1hf,    // A   [512][512] fp16 row-major
    const __half* __restrict__ B2hf,    // S2  [512][512] fp16 row-major
    __half* __restrict__ out1,          // xg + 64*512
    __half* __restrict__ out2)          // xg + 128*512
{
    constexpr int LD = 20;              // 16 uints (32 halves) + 4 pad
    extern __shared__ uint32_t sh[];
    uint32_t* As  = sh;                 // [2][128*20]
    uint32_t* B1s = sh + 2*128*LD;
    uint32_t* B2s = sh + 4*128*LD;
    const int tid = threadIdx.x, wid = tid>>5, lane = tid&31;
    const int g = lane>>2, tg = lane&3;
    const int p = blockIdx.y, n0 = blockIdx.x*128;
    const int wm = wid & 1, wn = wid >> 1;
    const int mbase = wm*64, nbase = wn*32;

    float c[2][4][4][4];
#pragma unroll
    for (int s=0;s<2;s++)
#pragma unroll
        for (int i=0;i<4;i++)
#pragma unroll
            for (int j=0;j<4;j++)
#pragma unroll
                for (int q=0;q<4;q++) c[s][i][j][q]=0.f;

    auto load = [&](int ch, int sel){
        uint32_t* a  = As  + sel*128*LD;
        uint32_t* b1 = B1s + sel*128*LD;
        uint32_t* b2 = B2s + sel*128*LD;
        const int k0 = ch*32;           // in halves
#pragma unroll
        for (int it = 0; it < 2; it++){
            int lin = tid + it*256;
            int r = lin >> 2, q = lin & 3;
            cp16(a  + r*LD + q*4,
                 xhf + (size_t)(2*p + (r>>6))*98304 + (size_t)(r&63)*512 + k0 + q*8);
            cp16(b1 + r*LD + q*4, B1hf + (size_t)(n0 + r)*512 + k0 + q*8);
            cp16(b2 + r*LD + q*4, B2hf + (size_t)(n0 + r)*512 + k0 + q*8);
        }
        asm volatile("cp.async.commit_group;" ::: "memory");
    };

    load(0, 0);
    for (int i = 0; i < 16; i++){
        const int cur = i & 1;
        if (i + 1 < 16){
            load(i+1, cur^1);
            asm volatile("cp.async.wait_group 1;" ::: "memory");
        } else {
            asm volatile("cp.async.wait_group 0;" ::: "memory");
        }
        __syncthreads();
        const uint32_t* a  = As  + cur*128*LD;
        const uint32_t* b1 = B1s + cur*128*LD;
        const uint32_t* b2 = B2s + cur*128*LD;
#pragma unroll
        for (int ks = 0; ks < 2; ks++){     // 2 x k16 per 32-half chunk
            uint32_t af[4][4], bf1[4][2], bf2[4][2];
#pragma unroll
            for (int mt = 0; mt < 4; mt++){
                int row = mbase + mt*16 + g;
                af[mt][0] = a[ row   *LD + ks*8 + tg    ];
                af[mt][1] = a[(row+8)*LD + ks*8 + tg    ];
                af[mt][2] = a[ row   *LD + ks*8 + tg + 4];
                af[mt][3] = a[(row+8)*LD + ks*8 + tg + 4];
            }
#pragma unroll
            for (int nt = 0; nt < 4; nt++){
                int nr = nbase + nt*8 + g;
                bf1[nt][0] = b1[nr*LD + ks*8 + tg    ];
                bf1[nt][1] = b1[nr*LD + ks*8 + tg + 4];
                bf2[nt][0] = b2[nr*LD + ks*8 + tg    ];
                bf2[nt][1] = b2[nr*LD + ks*8 + tg + 4];
            }
#pragma unroll
            for (int mt = 0; mt < 4; mt++)
#pragma unroll
                for (int nt = 0; nt < 4; nt++){
                    mma_f16(c[0][mt][nt], af[mt], bf1[nt]);
                    mma_f16(c[1][mt][nt], af[mt], bf2[nt]);
                }
        }
        __syncthreads();
    }

    // epilogue: convert to fp16, store both outputs
#pragma unroll
    for (int s = 0; s < 2; s++){
        __half* outp = s ? out2 : out1;
#pragma unroll
        for (int mt = 0; mt < 4; mt++){
            int r0 = mbase + mt*16 + g;
#pragma unroll
            for (int half = 0; half < 2; half++){
                int r = r0 + half*8;
                __half* orow = outp + (size_t)(2*p + (r>>6))*98304
                             + (size_t)(r&63)*512 + n0 + nbase;
#pragma unroll
                for (int nt = 0; nt < 4; nt++){
                    uint32_t u = packh2(c[s][mt][nt][half*2+0], c[s][mt][nt][half*2+1]);
                    *(uint32_t*)(orow + nt*8 + tg*2) = u;
                }
            }
        }
    }
}

// -------------------- contraction GEMM (fp16 HMMA + ldmatrix.trans) --------
// C[n][o] = sum_k xg[k][n] * W'[o][k] + bias[o];  per-bt batch.
template<int BN, int MT, int NTT, int WARPS_M>
__global__ void __launch_bounds__(256) k_ctr_hmma(
    const __half* __restrict__ xhf,     // [768][192][512] fp16
    const __half* __restrict__ Whf,     // [768][BN][192] fp16 (o-major)
    const float* __restrict__ bias,     // [768][BN]
    float* __restrict__ outp)           // [768][512][BN]
{
    constexpr int LDA = 136;            // halves per A smem row (128 + 8)
    constexpr int LDB = 200;            // halves per B smem row (192 + 8)
    constexpr int NC  = 6;              // K=192 / 32
    extern __shared__ __half shh[];
    __half* Bs = shh;                   // [BN][200]
    __half* As = shh + BN*LDB;          // [2][32][136]
    const int tid = threadIdx.x, wid = tid>>5, lane = tid&31;
    const int g = lane>>2, tg = lane&3;
    const int bt = blockIdx.y, m0 = blockIdx.x*128;
    const int wm = wid % WARPS_M, wn = wid / WARPS_M;
    const int mbase = wm*(MT*16), nbase = wn*(NTT*8);
    const __half* Ab = xhf + (size_t)bt*98304 + m0;
    const __half* Bb = Whf + (size_t)bt*BN*192;

    const uint32_t sbase = smem_u32p(shh);
    const uint32_t aBase = sbase + (uint32_t)(BN*LDB*2);

    float c[MT][NTT][4];
#pragma unroll
    for (int i=0;i<MT;i++)
#pragma unroll
        for (int j=0;j<NTT;j++)
#pragma unroll
            for (int q=0;q<4;q++) c[i][j][q]=0.f;

    // ---- load B once (all 192 k) ----
    {
        const int nch = BN*24;          // 16B chunks (24 per o-row)
#pragma unroll
        for (int it = 0; it < nch/256; it++){
            int lin = tid + it*256;
            int o = lin / 24, q = lin % 24;
            cp16(Bs + o*LDB + q*8, Bb + (size_t)o*192 + q*8);
        }
        asm volatile("cp.async.commit_group;" ::: "memory");
    }
    auto loadA = [&](int ch, int sel){
        __half* a = As + sel*32*LDA;
        const int k0 = ch*32;
#pragma unroll
        for (int it = 0; it < 2; it++){
            int lin = tid + it*256;
            int kr = lin >> 4, q = lin & 15;
            cp16(a + kr*LDA + q*8, Ab + (size_t)(k0+kr)*512 + q*8);
        }
        asm volatile("cp.async.commit_group;" ::: "memory");
    };

    loadA(0, 0);
    for (int i = 0; i < NC; i++){
        const int cur = i & 1;
        if (i + 1 < NC){
            loadA(i+1, cur^1);
            asm volatile("cp.async.wait_group 1;" ::: "memory");
        } else {
            asm volatile("cp.async.wait_group 0;" ::: "memory");
        }
        __syncthreads();
        const uint32_t aBuf = aBase + (uint32_t)(cur*32*LDA*2);
        const int kabs = i*32;
#pragma unroll
        for (int ks = 0; ks < 2; ks++){
            uint32_t af[MT][4], bf[NTT][2];
            const int krow = ks*16 + ((lane>>4)&1)*8 + (lane&7);
            const int cof  = ((lane>>3)&1)*8;
#pragma unroll
            for (int mt = 0; mt < MT; mt++){
                uint32_t addr = aBuf + (uint32_t)((krow*LDA + mbase + mt*16 + cof)*2);
                ldmx4t(af[mt], addr);
            }
#pragma unroll
            for (int nt = 0; nt < NTT; nt++){
                const __half* brow = Bs + (size_t)(nbase + nt*8 + g)*LDB + kabs + ks*16;
                bf[nt][0] = *(const uint32_t*)(brow + tg*2);
                bf[nt][1] = *(const uint32_t*)(brow + 8 + tg*2);
            }
#pragma unroll
            for (int mt = 0; mt < MT; mt++)
#pragma unroll
                for (int nt = 0; nt < NTT; nt++)
                    mma_f16(c[mt][nt], af[mt], bf[nt]);
        }
        __syncthreads();
    }

#pragma unroll
    for (int mt = 0; mt < MT; mt++){
        int n_ = m0 + mbase + mt*16 + g;
#pragma unroll
        for (int half = 0; half < 2; half++){
            float* orow = outp + ((size_t)bt*512 + n_ + half*8)*BN;
#pragma unroll
            for (int nt = 0; nt < NTT; nt++){
                int o = nbase + nt*8 + tg*2;
                float2 v;
                v.x = c[mt][nt][half*2+0] + bias[bt*BN + o];
                v.y = c[mt][nt][half*2+1] + bias[bt*BN + o + 1];
                *(float2*)(orow + o) = v;
            }
        }
    }
}

// -------------------- adjacency: A row-major + fp16 ------------------------
__global__ void k_A(const float* __restrict__ E, float* __restrict__ Arm,
                    __half* __restrict__ Ahf)
{
    __shared__ float Es[512*16];
    __shared__ float red[512];
    const int tid = threadIdx.x;
    const int n   = blockIdx.x;
    for (int i = tid; i < 512*16; i += 512) Es[i] = E[i];
    __syncthreads();
    float acc = 0.f;
#pragma unroll
    for (int d = 0; d < 16; d++) acc += Es[n*16+d]*Es[tid*16+d];
    acc = fmaxf(acc, 0.f);
    red[tid] = acc; __syncthreads();
    for (int s = 256; s > 0; s >>= 1){ if (tid < s) red[tid] = fmaxf(red[tid], red[tid+s]); __syncthreads(); }
    float mx = red[0]; __syncthreads();
    float e = expf(acc - mx);
    red[tid] = e; __syncthreads();
    for (int s = 256; s > 0; s >>= 1){ if (tid < s) red[tid] += red[tid+s]; __syncthreads(); }
    float v = e / red[0];
    Arm[n*512 + tid] = v;
    Ahf[n*512 + tid] = __float2half(v);
}

__global__ void k_fixdiag(float* __restrict__ S)
{
    int i = threadIdx.x;
    S[i*512 + i] -= 1.f;
}

__global__ void k_cvt_h(const float* __restrict__ s, __half* __restrict__ d, int n)
{
    int i = blockIdx.x*256 + threadIdx.x;
    if (i < n) d[i] = __float2half(s[i]);
}

// -------------------- generic SGEMM, A row-major ---------------------------
// OUTMODE: 0 = f32 out, 2 = fp16 out
template<int BM,int BN,int BK,int TM,int TN,int NT,int OUTMODE>
__global__ void __launch_bounds__(NT) gemm_rr_k(
    const float* __restrict__ Abase, long aStr,
    const float* __restrict__ Bbase, long bStr,
    void* __restrict__ Cbase, long cStr,
    int lda, int ldb, int ldc, int K,
    const float* __restrict__ colBias, float alpha)
{
    __shared__ float As[BK][BM];
    __shared__ float Bs[BK][BN];
    const int tid = threadIdx.x;
    const int bz  = blockIdx.z;
    const int m0  = blockIdx.y*BM;
    const int n0  = blockIdx.x*BN;
    const float* A = Abase + (long)bz*aStr + (long)m0*lda;
    const float* B = Bbase + (long)bz*bStr + n0;
    const int tx = tid % (BN/TN);
    const int ty = tid / (BN/TN);
    float acc[TM][TN];
#pragma unroll
    for (int i=0;i<TM;i++)
#pragma unroll
        for (int j=0;j<TN;j++) acc[i][j]=0.f;

    for (int k0 = 0; k0 < K; k0 += BK){
        for (int li = tid; li < BM*BK/4; li += NT){
            int m  = li/(BK/4), kv = li%(BK/4);
            float4 v = *(const float4*)(A + (long)m*lda + k0 + kv*4);
            As[kv*4+0][m]=v.x; As[kv*4+1][m]=v.y; As[kv*4+2][m]=v.z; As[kv*4+3][m]=v.w;
        }
        for (int li = tid; li < BN*BK/4; li += NT){
            int k  = li/(BN/4), nv = li%(BN/4);
            *(float4*)&Bs[k][nv*4] = *(const float4*)(B + (long)(k0+k)*ldb + nv*4);
        }
        __syncthreads();
#pragma unroll
        for (int kk = 0; kk < BK; kk++){
            float a[TM], bb[TN];
#pragma unroll
            for (int i=0;i<TM;i+=4) *(float4*)&a[i]  = *(const float4*)&As[kk][ty*TM+i];
#pragma unroll
            for (int j=0;j<TN;j+=4) *(float4*)&bb[j] = *(const float4*)&Bs[kk][tx*TN+j];
#pragma unroll
            for (int i=0;i<TM;i++)
#pragma unroll
                for (int j=0;j<TN;j++) acc[i][j] += a[i]*bb[j];
        }
        __syncthreads();
    }
#pragma unroll
    for (int i=0;i<TM;i++){
#pragma unroll
        for (int j=0;j<TN;j+=4){
            float4 v;
            v.x=acc[i][j+0]*alpha; v.y=acc[i][j+1]*alpha;
            v.z=acc[i][j+2]*alpha; v.w=acc[i][j+3]*alpha;
            if (colBias){
                const float* cb = colBias + n0 + tx*TN + j;
                v.x+=cb[0]; v.y+=cb[1]; v.z+=cb[2]; v.w+=cb[3];
            }
            long coff = (long)bz*cStr + (long)(m0+ty*TM+i)*ldc + n0 + tx*TN + j;
            if (OUTMODE == 0){
                *(float4*)((float*)Cbase + coff) = v;
            } else {
                uint2 u;
                u.x = packh2(v.x, v.y);
                u.y = packh2(v.z, v.w);
                *(uint2*)((__half*)Cbase + coff) = u;
            }
        }
    }
}

// -------------------- pack gwp/uwp (drop channel 0, [d][o][k] layout) ------
__global__ void k_pack(const float* __restrict__ wp, const float* __restrict__ w,
                       float* __restrict__ pwp, float* __restrict__ pw, int O)
{
    int idx = blockIdx.x*blockDim.x + threadIdx.x;
    if (blockIdx.y == 0){
        if (idx < 32*192*O){
            int r = idx % 192;          // r = k*64 + c
            int rem = idx / 192;
            int o = rem % O, d = rem / O;
            int c = r % 64, k = r / 64;
            pwp[idx] = wp[(((d*3 + k)*65) + (c+1))*O + o];
        }
    } else {
        if (idx < 192*O){
            int r = idx % 192;
            int o = idx / 192;
            int c = r % 64, k = r / 64;
            pw[idx] = w[((k*65) + (c+1))*O + o];
        }
    }
}

// -------------------- bias vectors: temb@bp + b0 ---------------------------
__global__ void k_bvec(const float* __restrict__ temb, const float* __restrict__ bp,
                       const float* __restrict__ b0, float* __restrict__ out, int O)
{
    int bt = blockIdx.x; int o = threadIdx.x;
    float acc = b0[o];
#pragma unroll
    for (int d = 0; d < 32; d++) acc += temb[bt*32+d]*bp[d*O+o];
    out[bt*O+o] = acc;
}

// -------------------- small STE projections --------------------------------
__global__ void k_small(const float* __restrict__ ne1, const float* __restrict__ ne2,
                        const float* __restrict__ Wq, const float* __restrict__ bq,
                        const float* __restrict__ Wk, const float* __restrict__ bk,
                        const float* __restrict__ Wv, const float* __restrict__ bv,
                        float* __restrict__ aq, float* __restrict__ ak, float* __restrict__ av)
{
    int b = blockIdx.x, y = blockIdx.y, h = threadIdx.x;
    const float *src, *W, *bias; float* out;
    if (y < 12)      { src = ne2 + (b*12+y)*32;  W = Wq; bias = bq; out = aq + (b*12+y)*64; }
    else if (y == 12){ src = ne1 + (b*12+11)*32; W = Wk; bias = bk; out = ak + b*64; }
    else             { src = ne1 + (b*12+11)*32; W = Wv; bias = bv; out = av + b*64; }
    float acc = bias[h];
#pragma unroll
    for (int d = 0; d < 32; d++) acc += src[d]*W[d*64+h];
    out[h] = acc;
}

// -------------------- X projections (xq, k, v, xw0) ------------------------
__global__ void __launch_bounds__(256) k_proj(
    const float* __restrict__ X,
    const float* __restrict__ Wq, const float* __restrict__ Wk,
    const float* __restrict__ Wv, const float* __restrict__ taw,
    const float* __restrict__ ak, const float* __restrict__ av,
    float* __restrict__ xq, float* __restrict__ kb,
    float* __restrict__ vb, float* __restrict__ xw0)
{
    __shared__ float Xs[64][64];
    __shared__ float Ws[64][64];
    const int tid  = threadIdx.x;
    const int mode = blockIdx.y;
    const int m0   = blockIdx.x*64;
    const int b    = m0 >> 9;
    const float* W = (mode==0)? Wq+2048 : (mode==1)? Wk+2048 : (mode==2)? Wv+2048 : taw;
    for (int li = tid; li < 1024; li += 256){
        int m = li>>4, kv = li&15;
        float4 v = *(const float4*)(X + (long)(m0+m)*64 + kv*4);
        Xs[kv*4+0][m]=v.x; Xs[kv*4+1][m]=v.y; Xs[kv*4+2][m]=v.z; Xs[kv*4+3][m]=v.w;
        *(float4*)&Ws[m][kv*4] = *(const float4*)(W + m*64 + kv*4);
    }
    __syncthreads();
    const int tx = tid&15, ty = tid>>4;
    float acc[4][4];
#pragma unroll
    for (int i=0;i<4;i++)
#pragma unroll
        for (int j=0;j<4;j++) acc[i][j]=0.f;
#pragma unroll
    for (int kk = 0; kk < 64; kk++){
        float a[4], bb[4];
        *(float4*)a  = *(const float4*)&Xs[kk][ty*4];
        *(float4*)bb = *(const float4*)&Ws[kk][tx*4];
#pragma unroll
        for (int i=0;i<4;i++)
#pragma unroll
            for (int j=0;j<4;j++) acc[i][j] += a[i]*bb[j];
    }
    float* outp = (mode==0)? xq : (mode==1)? kb : (mode==2)? vb : xw0;
#pragma unroll
    for (int i=0;i<4;i++){
        int m = m0 + ty*4 + i;
        float4 r;
        if (mode==1 || mode==2){
            const float* bias = ((mode==1)? ak:av) + b*64 + tx*4;
            r.x=fmaxf(acc[i][0]+bias[0],0.f); r.y=fmaxf(acc[i][1]+bias[1],0.f);
            r.z=fmaxf(acc[i][2]+bias[2],0.f); r.w=fmaxf(acc[i][3]+bias[3],0.f);
        } else {
            r.x=acc[i][0]; r.y=acc[i][1]; r.z=acc[i][2]; r.w=acc[i][3];
        }
        *(float4*)(outp + (long)m*64 + tx*4) = r;
    }
}

// -------------------- attention scores + softmax ---------------------------
__global__ void __launch_bounds__(256) k_attn(
    const float* __restrict__ aq, const float* __restrict__ xq,
    const float* __restrict__ kb, float* __restrict__ sm_out)
{
    __shared__ float aq_s[768];
    const int b = blockIdx.y;
    const int tid = threadIdx.x, lane = tid&31, w = tid>>5;
    for (int i = tid; i < 768; i += 256) aq_s[i] = aq[b*768 + i];
    __syncthreads();
    const int n0 = blockIdx.x*32 + w*4;
    for (int j = 0; j < 4; j++){
        int bn = b*512 + n0 + j;
        float xq0 = xq[bn*64 + lane],      xq1 = xq[bn*64 + 32 + lane];
        float k0  = kb[bn*64 + lane],      k1  = kb[bn*64 + 32 + lane];
        float sc0[12], sc1[12];
#pragma unroll
        for (int t = 0; t < 12; t++){
            float q0 = fmaxf(aq_s[t*64 + lane] + xq0, 0.f);
            float q1 = fmaxf(aq_s[t*64 + 32 + lane] + xq1, 0.f);
            float p0 = q0*k0, p1 = q1*k1;
#pragma unroll
            for (int o = 1; o < 8; o <<= 1){
                p0 += __shfl_xor_sync(0xffffffffu, p0, o);
                p1 += __shfl_xor_sync(0xffffffffu, p1, o);
            }
            sc0[t] = p0; sc1[t] = p1;
        }
        float m0 = -1e30f, m1 = -1e30f;
#pragma unroll
        for (int t = 0; t < 12; t++){ m0 = fmaxf(m0, sc0[t]); m1 = fmaxf(m1, sc1[t]); }
        float s0 = 0.f, s1 = 0.f;
#pragma unroll
        for (int t = 0; t < 12; t++){ sc0[t] = expf(sc0[t]-m0); s0 += sc0[t];
                                      sc1[t] = expf(sc1[t]-m1); s1 += sc1[t]; }
        float r0 = 1.f/s0, r1 = 1.f/s1;
        if ((lane & 7) == 0){
            int d = lane >> 3;
#pragma unroll
            for (int t = 0; t < 12; t++){
                sm_out[bn*96 + t*8 + d]     = sc0[t]*r0;
                sm_out[bn*96 + t*8 + 4 + d] = sc1[t]*r1;
            }
        }
    }
}

// -------------------- build de (f32 + fp16 into xg rows 0-63) --------------
__global__ void __launch_bounds__(256) k_debuild(
    const float* __restrict__ sm, const float* __restrict__ vb,
    const float* __restrict__ xw0, const float* __restrict__ taw,
    const float* __restrict__ tab, float* __restrict__ de,
    __half* __restrict__ dehf)          // = xg1 base
{
    __shared__ float taw1s[64][64];
    __shared__ float wvT[64][33];
    __shared__ float xw0s[64][33];
    const int b = blockIdx.z, t = blockIdx.y, n0 = blockIdx.x*32;
    const int tid = threadIdx.x;
    for (int i = tid; i < 4096; i += 256)
        taw1s[i>>6][i&63] = taw[4096 + i];
    for (int idx = tid; idx < 2048; idx += 256){
        int nl = idx >> 6, i = idx & 63;
        int bn = b*512 + n0 + nl;
        float s = sm[bn*96 + t*8 + (i>>3)];
        wvT[i][nl]  = s * vb[bn*64 + i];
        xw0s[i][nl] = xw0[bn*64 + i];
    }
    __syncthreads();
    const int tx = tid & 15, ty = tid >> 4;
    float acc[4][2] = {};
#pragma unroll
    for (int i = 0; i < 64; i++){
        float4 a = *(const float4*)&taw1s[i][ty*4];
        float b0 = wvT[i][tx*2], b1 = wvT[i][tx*2+1];
        acc[0][0]+=a.x*b0; acc[0][1]+=a.x*b1;
        acc[1][0]+=a.y*b0; acc[1][1]+=a.y*b1;
        acc[2][0]+=a.z*b0; acc[2][1]+=a.z*b1;
        acc[3][0]+=a.w*b0; acc[3][1]+=a.w*b1;
    }
    const int bt = b*12 + t;
    long baseD = (long)bt*32768;
    long baseH = (long)bt*98304;
#pragma unroll
    for (int oi = 0; oi < 4; oi++){
        int o = ty*4 + oi;
        float bias = tab[o];
        float2 v;
        v.x = acc[oi][0] + xw0s[o][tx*2]   + bias;
        v.y = acc[oi][1] + xw0s[o][tx*2+1] + bias;
        *(float2*)&de[baseD + (long)o*512 + n0 + tx*2] = v;
        uint32_t u = packh2(v.x, v.y);
        *(uint32_t*)&dehf[baseH + (long)o*512 + n0 + tx*2] = u;
    }
}

// -------------------- gate: cand = sigmoid(z)*de (fp16 into xg2) -----------
__global__ void k_gate(const float* __restrict__ zr, const float* __restrict__ de,
                       __half* __restrict__ chf)   // = xg2 base
{
    __shared__ float s[32][33];
    const int bt = blockIdx.y, n0 = blockIdx.x*32;
    const int tx = threadIdx.x, ty = threadIdx.y;
    for (int ch = 0; ch < 2; ch++){
        int c0 = ch*32;
        s[ty][tx] = zr[bt*65536 + (n0+ty)*128 + c0 + tx];
        __syncthreads();
        int c = c0 + ty;
        float z = 1.f/(1.f + expf(-s[tx][ty]));
        float val = z * de[(long)bt*32768 + (long)c*512 + n0 + tx];
        chf[(long)bt*98304 + (long)c*512 + n0 + tx] = __float2half(val);
        __syncthreads();
    }
}

// -------------------- final: state blend + output head ---------------------
__global__ void __launch_bounds__(256) k_final(
    const float* __restrict__ zr, const float* __restrict__ de,
    const float* __restrict__ hc, const float* __restrict__ out_w,
    const float* __restrict__ out_b, float* __restrict__ out)
{
    __shared__ float de_s[64][33];
    __shared__ float red[8][32];
    __shared__ float w_s[64];
    const int bt = blockIdx.y, n0 = blockIdx.x*32;
    const int tt = bt % 12;
    const int tid = threadIdx.x;
    if (tid < 64) w_s[tid] = out_w[tt*64 + tid];
    for (int i = tid; i < 2048; i += 256){
        int h = i >> 5, nl = i & 31;
        de_s[h][nl] = de[(long)bt*32768 + h*512 + n0 + nl];
    }
    __syncthreads();
    const int nl = tid & 31, hg = tid >> 5;
    const int rg_off = bt*65536 + (n0+nl)*128 + 64;
    const int hc_off = bt*32768 + (n0+nl)*64;
    float partial = 0.f;
#pragma unroll
    for (int j = 0; j < 8; j++){
        int h = hg*8 + j;
        float rg  = 1.f/(1.f + expf(-zr[rg_off + h]));
        float hcv = tanhf(hc[hc_off + h]);
        float st  = rg*de_s[h][nl] + (1.f-rg)*hcv;
        partial  += st * w_s[h];
    }
    red[hg][nl] = partial;
    __syncthreads();
    if (tid < 32){
        float sum = 0.f;
#pragma unroll
        for (int g = 0; g < 8; g++) sum += red[g][tid];
        out[bt*512 + n0 + tid] = sum + out_b[tt];
    }
}

// ===========================================================================
extern "C" void kernel_launch(void* const* d_in, const int* in_sizes, int n_in,
                              void* d_out, int out_size)
{
    const float* h_n  = (const float*)d_in[2];
    const float* ne1  = (const float*)d_in[3];
    const float* ne2  = (const float*)d_in[4];
    const float* E    = (const float*)d_in[5];
    const float* Wq   = (const float*)d_in[6];
    const float* bq   = (const float*)d_in[7];
    const float* Wk   = (const float*)d_in[8];
    const float* bk   = (const float*)d_in[9];
    const float* Wv   = (const float*)d_in[10];
    const float* bv   = (const float*)d_in[11];
    const float* taw  = (const float*)d_in[12];
    const float* tab  = (const float*)d_in[13];
    const float* gwp  = (const float*)d_in[14];
    const float* gw   = (const float*)d_in[15];
    const float* gbp  = (const float*)d_in[16];
    const float* gb   = (const float*)d_in[17];
    const float* uwp  = (const float*)d_in[18];
    const float* uw   = (const float*)d_in[19];
    const float* ubp  = (const float*)d_in[20];
    const float* ub   = (const float*)d_in[21];
    const float* outw = (const float*)d_in[22];
    const float* outb = (const float*)d_in[23];
    float* out = (float*)d_out;

    float *Arm, *S2, *kb2, *vb2, *xq, *xw0, *aq, *ak, *av, *sm, *de;
    float *b1, *b2, *wp1, *w1b, *wp2, *w2b, *zr, *hc;
    __half *Ahf, *S2hf, *xg1, *xg2, *W1hf, *W2hf;
    cudaGetSymbolAddress((void**)&Arm,  g_Arm);
    cudaGetSymbolAddress((void**)&S2,   g_S2);
    cudaGetSymbolAddress((void**)&Ahf,  g_Ahf);
    cudaGetSymbolAddress((void**)&S2hf, g_S2hf);
    cudaGetSymbolAddress((void**)&kb2,  g_kb);
    cudaGetSymbolAddress((void**)&vb2,  g_vb);
    cudaGetSymbolAddress((void**)&xq,   g_xq);
    cudaGetSymbolAddress((void**)&xw0,  g_xw0);
    cudaGetSymbolAddress((void**)&aq,   g_aq);
    cudaGetSymbolAddress((void**)&ak,   g_ak);
    cudaGetSymbolAddress((void**)&av,   g_av);
    cudaGetSymbolAddress((void**)&sm,   g_sm);
    cudaGetSymbolAddress((void**)&de,   g_de);
    cudaGetSymbolAddress((void**)&xg1,  g_xg1);
    cudaGetSymbolAddress((void**)&xg2,  g_xg2);
    cudaGetSymbolAddress((void**)&W1hf, g_W1hf);
    cudaGetSymbolAddress((void**)&W2hf, g_W2hf);
    cudaGetSymbolAddress((void**)&b1,   g_b1);
    cudaGetSymbolAddress((void**)&b2,   g_b2);
    cudaGetSymbolAddress((void**)&wp1,  g_wp1);
    cudaGetSymbolAddress((void**)&w1b,  g_w1b);
    cudaGetSymbolAddress((void**)&wp2,  g_wp2);
    cudaGetSymbolAddress((void**)&w2b,  g_w2b);
    cudaGetSymbolAddress((void**)&zr,   g_zr);
    cudaGetSymbolAddress((void**)&hc,   g_hc);

    const int SUPP2_SMEM = 6*128*20*4;                       // 61440
    const int CTR1_SMEM  = 128*200*2 + 2*32*136*2;           // 68608
    const int CTR2_SMEM  = 64*200*2  + 2*32*136*2;           // 43008
    cudaFuncSetAttribute(k_supp2_hmma, cudaFuncAttributeMaxDynamicSharedMemorySize, SUPP2_SMEM);
    cudaFuncSetAttribute(k_ctr_hmma<128,4,4,2>, cudaFuncAttributeMaxDynamicSharedMemorySize, CTR1_SMEM);
    cudaFuncSetAttribute(k_ctr_hmma<64,2,4,4>,  cudaFuncAttributeMaxDynamicSharedMemorySize, CTR2_SMEM);

    // ---- adjacency & supports ----
    k_A<<<512, 512>>>(E, Arm, Ahf);
    gemm_rr_k<64,64,16,4,4,256,0><<<dim3(8,8,1), 256>>>(      // S2 = 2*A@A
        Arm, 0, Arm, 0, S2, 0, 512, 512, 512, 512, nullptr, 2.f);
    k_fixdiag<<<1, 512>>>(S2);
    k_cvt_h<<<1024, 256>>>(S2, S2hf, 512*512);

    // ---- pack GCN weights ([d][o][k]), build per-bt W' fp16 + bias ----
    k_pack<<<dim3(3072,2), 256>>>(gwp, gw, wp1, w1b, 128);
    k_pack<<<dim3(1536,2), 256>>>(uwp, uw, wp2, w2b, 64);
    k_bvec<<<768, 128>>>(ne2, gbp, gb, b1, 128);
    k_bvec<<<768, 64 >>>(ne2, ubp, ub, b2, 64);
    gemm_rr_k<64,64,16,4,4,256,2><<<dim3(384,12,1), 256>>>(   // W1' fp16 [bt][o][k]
        ne2, 0, wp1, 0, W1hf, 0, 32, 24576, 24576, 32, w1b, 1.f);
    gemm_rr_k<64,64,16,4,4,256,2><<<dim3(192,12,1), 256>>>(   // W2' fp16
        ne2, 0, wp2, 0, W2hf, 0, 32, 12288, 12288, 32, w2b, 1.f);

    // ---- attention path ----
    k_small<<<dim3(64,14), 64>>>(ne1, ne2, Wq, bq, Wk, bk, Wv, bv, aq, ak, av);
    k_proj<<<dim3(512,4), 256>>>(h_n, Wq, Wk, Wv, taw, ak, av, xq, kb2, vb2, xw0);
    k_attn<<<dim3(16,64), 256>>>(aq, xq, kb2, sm);
    k_debuild<<<dim3(16,12,64), 256>>>(sm, vb2, xw0, taw, tab, de, xg1);

    // ---- GCN1: fp16 dual-support + fp16 contraction ----
    k_supp2_hmma<<<dim3(4,384), 256, SUPP2_SMEM>>>(xg1, Ahf, S2hf,
                                                   xg1 + 64*512, xg1 + 128*512);
    k_ctr_hmma<128,4,4,2><<<dim3(4,768), 256, CTR1_SMEM>>>(xg1, W1hf, b1, zr);

    // ---- GCN2 ----
    k_gate<<<dim3(16,768), dim3(32,32)>>>(zr, de, xg2);
    k_supp2_hmma<<<dim3(4,384), 256, SUPP2_SMEM>>>(xg2, Ahf, S2hf,
                                                   xg2 + 64*512, xg2 + 128*512);
    k_ctr_hmma<64,2,4,4><<<dim3(4,768), 256, CTR2_SMEM>>>(xg2, W2hf, b2, hc);

    // ---- final blend + output head ----
    k_final<<<dim3(16,768), 256>>>(zr, de, hc, outw, outb, out);
}

// round 13
// speedup vs baseline: 3.8103x; 1.1769x over previous
#include <cuda_runtime.h>
#include <cuda_fp16.h>
#include <math.h>
#include <stdint.h>

// Problem constants: B=64, T=12, N=512, H=64, TD=32, ED=16, CHEB_K=3, D_HEADS=8
// BT = 768. Effective GCN channels = 64 (channel 0 is identically zero).

// -------------------- static device scratch --------------------------------
static __device__ float g_Arm[512*512];            // A row-major (f32, for S2 build)
static __device__ __half g_Ahf [512*512];          // fp16 support B operands
static __device__ __half g_S2hf[512*512];
static __device__ float g_kb [64*512*64];
static __device__ float g_vb [64*512*64];
static __device__ float g_xq [64*512*64];
static __device__ float g_xw0[64*512*64];
static __device__ float g_aq [64*12*64];
static __device__ float g_ak [64*64];
static __device__ float g_av [64*64];
static __device__ float g_sm [64*512*12*8];
static __device__ float g_de [768*64*512];         // de f32 (channel-major)
static __device__ __half g_xg1[768*192*512];       // fp16 [bt][j][n] j:0-63 de,64-127 A@,128-191 S2@
static __device__ __half g_xg2[768*192*512];       // same for cand
static __device__ __half g_W1hf[768*128*192];      // W' [bt][o][k] fp16
static __device__ __half g_W2hf[768*64*192];
static __device__ float g_b1 [768*128];
static __device__ float g_b2 [768*64];
static __device__ float g_wp1[32*128*192];         // packed [d][o][k]
static __device__ float g_w1b[128*192];
static __device__ float g_wp2[32*64*192];
static __device__ float g_w2b[64*192];
static __device__ float g_rg [768*64*512];         // pre-sigmoid rg, channel-major

// -------------------- helpers ----------------------------------------------
__device__ __forceinline__ uint32_t smem_u32p(const void* p){
    uint32_t a;
    asm("{ .reg .u64 t; cvta.to.shared.u64 t, %1; cvt.u32.u64 %0, t; }" : "=r"(a) : "l"(p));
    return a;
}
__device__ __forceinline__ void cp16(void* dst, const void* src){
    uint32_t d = smem_u32p(dst);
    asm volatile("cp.async.cg.shared.global [%0], [%1], 16;" :: "r"(d), "l"(src));
}
__device__ __forceinline__ void mma_f16(float* c, const uint32_t* a, const uint32_t* b){
    asm volatile(
        "mma.sync.aligned.m16n8k16.row.col.f32.f16.f16.f32 "
        "{%0,%1,%2,%3}, {%4,%5,%6,%7}, {%8,%9}, {%0,%1,%2,%3};"
        : "+f"(c[0]),"+f"(c[1]),"+f"(c[2]),"+f"(c[3])
        : "r"(a[0]),"r"(a[1]),"r"(a[2]),"r"(a[3]), "r"(b[0]),"r"(b[1]));
}
__device__ __forceinline__ void ldmx4t(uint32_t* r, uint32_t addr){
    asm volatile("ldmatrix.sync.aligned.m8n8.x4.trans.shared.b16 {%0,%1,%2,%3}, [%4];"
        : "=r"(r[0]),"=r"(r[1]),"=r"(r[2]),"=r"(r[3]) : "r"(addr));
}
__device__ __forceinline__ uint32_t packh2(float x, float y){
    __half2 h = __floats2half2_rn(x, y);
    return *(uint32_t*)&h;
}

// -------------------- fused dual support GEMM (fp16 HMMA) ------------------
__global__ void __launch_bounds__(256) k_supp2_hmma(
    const __half* __restrict__ xhf,
    const __half* __restrict__ B1hf,
    const __half* __restrict__ B2hf,
    __half* __restrict__ out1,
    __half* __restrict__ out2)
{
    constexpr int LD = 20;
    extern __shared__ uint32_t sh[];
    uint32_t* As  = sh;
    uint32_t* B1s = sh + 2*128*LD;
    uint32_t* B2s = sh + 4*128*LD;
    const int tid = threadIdx.x, wid = tid>>5, lane = tid&31;
    const int g = lane>>2, tg = lane&3;
    const int p = blockIdx.y, n0 = blockIdx.x*128;
    const int wm = wid & 1, wn = wid >> 1;
    const int mbase = wm*64, nbase = wn*32;

    float c[2][4][4][4];
#pragma unroll
    for (int s=0;s<2;s++)
#pragma unroll
        for (int i=0;i<4;i++)
#pragma unroll
            for (int j=0;j<4;j++)
#pragma unroll
                for (int q=0;q<4;q++) c[s][i][j][q]=0.f;

    auto load = [&](int ch, int sel){
        uint32_t* a  = As  + sel*128*LD;
        uint32_t* b1 = B1s + sel*128*LD;
        uint32_t* b2 = B2s + sel*128*LD;
        const int k0 = ch*32;
#pragma unroll
        for (int it = 0; it < 2; it++){
            int lin = tid + it*256;
            int r = lin >> 2, q = lin & 3;
            cp16(a  + r*LD + q*4,
                 xhf + (size_t)(2*p + (r>>6))*98304 + (size_t)(r&63)*512 + k0 + q*8);
            cp16(b1 + r*LD + q*4, B1hf + (size_t)(n0 + r)*512 + k0 + q*8);
            cp16(b2 + r*LD + q*4, B2hf + (size_t)(n0 + r)*512 + k0 + q*8);
        }
        asm volatile("cp.async.commit_group;" ::: "memory");
    };

    load(0, 0);
    for (int i = 0; i < 16; i++){
        const int cur = i & 1;
        if (i + 1 < 16){
            load(i+1, cur^1);
            asm volatile("cp.async.wait_group 1;" ::: "memory");
        } else {
            asm volatile("cp.async.wait_group 0;" ::: "memory");
        }
        __syncthreads();
        const uint32_t* a  = As  + cur*128*LD;
        const uint32_t* b1 = B1s + cur*128*LD;
        const uint32_t* b2 = B2s + cur*128*LD;
#pragma unroll
        for (int ks = 0; ks < 2; ks++){
            uint32_t af[4][4], bf1[4][2], bf2[4][2];
#pragma unroll
            for (int mt = 0; mt < 4; mt++){
                int row = mbase + mt*16 + g;
                af[mt][0] = a[ row   *LD + ks*8 + tg    ];
                af[mt][1] = a[(row+8)*LD + ks*8 + tg    ];
                af[mt][2] = a[ row   *LD + ks*8 + tg + 4];
                af[mt][3] = a[(row+8)*LD + ks*8 + tg + 4];
            }
#pragma unroll
            for (int nt = 0; nt < 4; nt++){
                int nr = nbase + nt*8 + g;
                bf1[nt][0] = b1[nr*LD + ks*8 + tg    ];
                bf1[nt][1] = b1[nr*LD + ks*8 + tg + 4];
                bf2[nt][0] = b2[nr*LD + ks*8 + tg    ];
                bf2[nt][1] = b2[nr*LD + ks*8 + tg + 4];
            }
#pragma unroll
            for (int mt = 0; mt < 4; mt++)
#pragma unroll
                for (int nt = 0; nt < 4; nt++){
                    mma_f16(c[0][mt][nt], af[mt], bf1[nt]);
                    mma_f16(c[1][mt][nt], af[mt], bf2[nt]);
                }
        }
        __syncthreads();
    }

#pragma unroll
    for (int s = 0; s < 2; s++){
        __half* outp = s ? out2 : out1;
#pragma unroll
        for (int mt = 0; mt < 4; mt++){
            int r0 = mbase + mt*16 + g;
#pragma unroll
            for (int half = 0; half < 2; half++){
                int r = r0 + half*8;
                __half* orow = outp + (size_t)(2*p + (r>>6))*98304
                             + (size_t)(r&63)*512 + n0 + nbase;
#pragma unroll
                for (int nt = 0; nt < 4; nt++){
                    uint32_t u = packh2(c[s][mt][nt][half*2+0], c[s][mt][nt][half*2+1]);
                    *(uint32_t*)(orow + nt*8 + tg*2) = u;
                }
            }
        }
    }
}

// -------------------- ctr1: contraction + fused gate -----------------------
// zr[n][o] = sum_k xg1[k][n]*W1'[o][k] + b1[o]
// o<64  : cand = sigmoid(zr)*de  -> xg2 fp16 (channel-major)
// o>=64 : rg (pre-sigmoid)       -> rg f32 (channel-major)
__global__ void __launch_bounds__(256) k_ctr1_fused(
    const __half* __restrict__ xhf,     // xg1
    const __half* __restrict__ Whf,     // [768][128][192]
    const float* __restrict__ bias,     // [768][128]
    const float* __restrict__ de,       // [768][64][512]
    __half* __restrict__ cand,          // xg2 base
    float* __restrict__ rg)             // [768][64][512]
{
    constexpr int BN = 128, MT = 4, NTT = 4, WARPS_M = 2;
    constexpr int LDA = 136, LDB = 200, NC = 6;
    extern __shared__ __half shh[];
    __half* Bs = shh;
    __half* As = shh + BN*LDB;
    const int tid = threadIdx.x, wid = tid>>5, lane = tid&31;
    const int g = lane>>2, tg = lane&3;
    const int bt = blockIdx.y, m0 = blockIdx.x*128;
    const int wm = wid % WARPS_M, wn = wid / WARPS_M;
    const int mbase = wm*(MT*16), nbase = wn*(NTT*8);
    const __half* Ab = xhf + (size_t)bt*98304 + m0;
    const __half* Bb = Whf + (size_t)bt*BN*192;
    const uint32_t aBase = smem_u32p(shh) + (uint32_t)(BN*LDB*2);

    float c[MT][NTT][4];
#pragma unroll
    for (int i=0;i<MT;i++)
#pragma unroll
        for (int j=0;j<NTT;j++)
#pragma unroll
            for (int q=0;q<4;q++) c[i][j][q]=0.f;

    {
        const int nch = BN*24;
#pragma unroll
        for (int it = 0; it < nch/256; it++){
            int lin = tid + it*256;
            int o = lin / 24, q = lin % 24;
            cp16(Bs + o*LDB + q*8, Bb + (size_t)o*192 + q*8);
        }
        asm volatile("cp.async.commit_group;" ::: "memory");
    }
    auto loadA = [&](int ch, int sel){
        __half* a = As + sel*32*LDA;
        const int k0 = ch*32;
#pragma unroll
        for (int it = 0; it < 2; it++){
            int lin = tid + it*256;
            int kr = lin >> 4, q = lin & 15;
            cp16(a + kr*LDA + q*8, Ab + (size_t)(k0+kr)*512 + q*8);
        }
        asm volatile("cp.async.commit_group;" ::: "memory");
    };

    loadA(0, 0);
    for (int i = 0; i < NC; i++){
        const int cur = i & 1;
        if (i + 1 < NC){
            loadA(i+1, cur^1);
            asm volatile("cp.async.wait_group 1;" ::: "memory");
        } else {
            asm volatile("cp.async.wait_group 0;" ::: "memory");
        }
        __syncthreads();
        const uint32_t aBuf = aBase + (uint32_t)(cur*32*LDA*2);
        const int kabs = i*32;
#pragma unroll
        for (int ks = 0; ks < 2; ks++){
            uint32_t af[MT][4], bf[NTT][2];
            const int krow = ks*16 + ((lane>>4)&1)*8 + (lane&7);
            const int cof  = ((lane>>3)&1)*8;
#pragma unroll
            for (int mt = 0; mt < MT; mt++){
                uint32_t addr = aBuf + (uint32_t)((krow*LDA + mbase + mt*16 + cof)*2);
                ldmx4t(af[mt], addr);
            }
#pragma unroll
            for (int nt = 0; nt < NTT; nt++){
                const __half* brow = Bs + (size_t)(nbase + nt*8 + g)*LDB + kabs + ks*16;
                bf[nt][0] = *(const uint32_t*)(brow + tg*2);
                bf[nt][1] = *(const uint32_t*)(brow + 8 + tg*2);
            }
#pragma unroll
            for (int mt = 0; mt < MT; mt++)
#pragma unroll
                for (int nt = 0; nt < NTT; nt++)
                    mma_f16(c[mt][nt], af[mt], bf[nt]);
        }
        __syncthreads();
    }

    // ---- stage de tile [64][132] into smem (reuse) ----
    float* de_s = (float*)shh;
    {
        const float* deb = de + (size_t)bt*32768 + m0;
        for (int idx = tid; idx < 64*32; idx += 256){
            int cc = idx >> 5, j = idx & 31;
            *(float4*)(de_s + cc*132 + j*4) = *(const float4*)(deb + (size_t)cc*512 + j*4);
        }
    }
    __syncthreads();

#pragma unroll
    for (int mt = 0; mt < MT; mt++){
#pragma unroll
        for (int half = 0; half < 2; half++){
            int nl = mbase + mt*16 + half*8 + g;
            int n_ = m0 + nl;
#pragma unroll
            for (int nt = 0; nt < NTT; nt++){
                int o = nbase + nt*8 + tg*2;
                float v0 = c[mt][nt][half*2+0] + bias[bt*128 + o];
                float v1 = c[mt][nt][half*2+1] + bias[bt*128 + o + 1];
                if (nbase < 64){
                    float z0 = 1.f/(1.f + expf(-v0));
                    float z1 = 1.f/(1.f + expf(-v1));
                    __half* xo = cand + (size_t)bt*98304 + (size_t)o*512 + n_;
                    xo[0]   = __float2half(z0 * de_s[o*132 + nl]);
                    xo[512] = __float2half(z1 * de_s[(o+1)*132 + nl]);
                } else {
                    float* ro = rg + (size_t)bt*32768 + (size_t)(o-64)*512 + n_;
                    ro[0]   = v0;
                    ro[512] = v1;
                }
            }
        }
    }
}

// -------------------- ctr2: contraction + fused final blend + head ---------
// hc[n][o] = sum_k xg2[k][n]*W2'[o][k] + b2[o]
// st = sigmoid(rg)*de + (1-sigmoid(rg))*tanh(hc); out[n] = sum_o st*out_w[tt][o] + out_b[tt]
__global__ void __launch_bounds__(256) k_ctr2_fused(
    const __half* __restrict__ xhf,     // xg2
    const __half* __restrict__ Whf,     // [768][64][192]
    const float* __restrict__ bias,     // [768][64]
    const float* __restrict__ de,       // [768][64][512]
    const float* __restrict__ rg,       // [768][64][512]
    const float* __restrict__ out_w,    // [12][64]
    const float* __restrict__ out_b,    // [12]
    float* __restrict__ outp)           // [768][512]
{
    constexpr int BN = 64, MT = 2, NTT = 4, WARPS_M = 4;
    constexpr int LDA = 136, LDB = 200, NC = 6;
    extern __shared__ __half shh[];
    __half* Bs = shh;
    __half* As = shh + BN*LDB;
    const int tid = threadIdx.x, wid = tid>>5, lane = tid&31;
    const int g = lane>>2, tg = lane&3;
    const int bt = blockIdx.y, m0 = blockIdx.x*128;
    const int wm = wid % WARPS_M, wn = wid / WARPS_M;
    const int mbase = wm*(MT*16), nbase = wn*(NTT*8);
    const __half* Ab = xhf + (size_t)bt*98304 + m0;
    const __half* Bb = Whf + (size_t)bt*BN*192;
    const uint32_t aBase = smem_u32p(shh) + (uint32_t)(BN*LDB*2);

    float c[MT][NTT][4];
#pragma unroll
    for (int i=0;i<MT;i++)
#pragma unroll
        for (int j=0;j<NTT;j++)
#pragma unroll
            for (int q=0;q<4;q++) c[i][j][q]=0.f;

    {
        const int nch = BN*24;
#pragma unroll
        for (int it = 0; it < nch/256; it++){
            int lin = tid + it*256;
            int o = lin / 24, q = lin % 24;
            cp16(Bs + o*LDB + q*8, Bb + (size_t)o*192 + q*8);
        }
        asm volatile("cp.async.commit_group;" ::: "memory");
    }
    auto loadA = [&](int ch, int sel){
        __half* a = As + sel*32*LDA;
        const int k0 = ch*32;
#pragma unroll
        for (int it = 0; it < 2; it++){
            int lin = tid + it*256;
            int kr = lin >> 4, q = lin & 15;
            cp16(a + kr*LDA + q*8, Ab + (size_t)(k0+kr)*512 + q*8);
        }
        asm volatile("cp.async.commit_group;" ::: "memory");
    };

    loadA(0, 0);
    for (int i = 0; i < NC; i++){
        const int cur = i & 1;
        if (i + 1 < NC){
            loadA(i+1, cur^1);
            asm volatile("cp.async.wait_group 1;" ::: "memory");
        } else {
            asm volatile("cp.async.wait_group 0;" ::: "memory");
        }
        __syncthreads();
        const uint32_t aBuf = aBase + (uint32_t)(cur*32*LDA*2);
        const int kabs = i*32;
#pragma unroll
        for (int ks = 0; ks < 2; ks++){
            uint32_t af[MT][4], bf[NTT][2];
            const int krow = ks*16 + ((lane>>4)&1)*8 + (lane&7);
            const int cof  = ((lane>>3)&1)*8;
#pragma unroll
            for (int mt = 0; mt < MT; mt++){
                uint32_t addr = aBuf + (uint32_t)((krow*LDA + mbase + mt*16 + cof)*2);
                ldmx4t(af[mt], addr);
            }
#pragma unroll
            for (int nt = 0; nt < NTT; nt++){
                const __half* brow = Bs + (size_t)(nbase + nt*8 + g)*LDB + kabs + ks*16;
                bf[nt][0] = *(const uint32_t*)(brow + tg*2);
                bf[nt][1] = *(const uint32_t*)(brow + 8 + tg*2);
            }
#pragma unroll
            for (int mt = 0; mt < MT; mt++)
#pragma unroll
                for (int nt = 0; nt < NTT; nt++)
                    mma_f16(c[mt][nt], af[mt], bf[nt]);
        }
        __syncthreads();
    }

    // ---- stage de + rg tiles [64][132] each, then fused blend + head ------
    float* de_s = (float*)shh;
    float* rg_s = de_s + 64*132;
    float* red  = rg_s + 64*132;        // [2][128]
    {
        const float* deb = de + (size_t)bt*32768 + m0;
        const float* rgb = rg + (size_t)bt*32768 + m0;
        for (int idx = tid; idx < 64*32; idx += 256){
            int cc = idx >> 5, j = idx & 31;
            *(float4*)(de_s + cc*132 + j*4) = *(const float4*)(deb + (size_t)cc*512 + j*4);
            *(float4*)(rg_s + cc*132 + j*4) = *(const float4*)(rgb + (size_t)cc*512 + j*4);
        }
    }
    __syncthreads();
    const int tt = bt % 12;
    float bo[NTT][2], wv[NTT][2];
#pragma unroll
    for (int nt = 0; nt < NTT; nt++){
        int o = nbase + nt*8 + tg*2;
        bo[nt][0] = bias[bt*64 + o];   bo[nt][1] = bias[bt*64 + o + 1];
        wv[nt][0] = out_w[tt*64 + o];  wv[nt][1] = out_w[tt*64 + o + 1];
    }
#pragma unroll
    for (int mt = 0; mt < MT; mt++){
#pragma unroll
        for (int half = 0; half < 2; half++){
            int nl = mbase + mt*16 + half*8 + g;
            float p = 0.f;
#pragma unroll
            for (int nt = 0; nt < NTT; nt++){
                int o = nbase + nt*8 + tg*2;
#pragma unroll
                for (int q = 0; q < 2; q++){
                    float v   = c[mt][nt][half*2+q] + bo[nt][q];
                    float hcv = tanhf(v);
                    float r   = 1.f/(1.f + expf(-rg_s[(o+q)*132 + nl]));
                    float st  = r*de_s[(o+q)*132 + nl] + (1.f - r)*hcv;
                    p += st * wv[nt][q];
                }
            }
            p += __shfl_xor_sync(0xffffffffu, p, 1);
            p += __shfl_xor_sync(0xffffffffu, p, 2);
            if (tg == 0) red[wn*128 + nl] = p;
        }
    }
    __syncthreads();
    if (tid < 128)
        outp[(size_t)bt*512 + m0 + tid] = red[tid] + red[128 + tid] + out_b[tt];
}

// -------------------- adjacency: A row-major + fp16 ------------------------
__global__ void k_A(const float* __restrict__ E, float* __restrict__ Arm,
                    __half* __restrict__ Ahf)
{
    __shared__ float Es[512*16];
    __shared__ float red[512];
    const int tid = threadIdx.x;
    const int n   = blockIdx.x;
    for (int i = tid; i < 512*16; i += 512) Es[i] = E[i];
    __syncthreads();
    float acc = 0.f;
#pragma unroll
    for (int d = 0; d < 16; d++) acc += Es[n*16+d]*Es[tid*16+d];
    acc = fmaxf(acc, 0.f);
    red[tid] = acc; __syncthreads();
    for (int s = 256; s > 0; s >>= 1){ if (tid < s) red[tid] = fmaxf(red[tid], red[tid+s]); __syncthreads(); }
    float mx = red[0]; __syncthreads();
    float e = expf(acc - mx);
    red[tid] = e; __syncthreads();
    for (int s = 256; s > 0; s >>= 1){ if (tid < s) red[tid] += red[tid+s]; __syncthreads(); }
    float v = e / red[0];
    Arm[n*512 + tid] = v;
    Ahf[n*512 + tid] = __float2half(v);
}

__global__ void k_fixdiag_h(__half* __restrict__ S)
{
    int i = threadIdx.x;
    S[i*513] = __hsub(S[i*513], __float2half(1.f));
}

// -------------------- generic SGEMM, A row-major ---------------------------
// OUTMODE: 0 = f32 out, 2 = fp16 out
template<int BM,int BN,int BK,int TM,int TN,int NT,int OUTMODE>
__global__ void __launch_bounds__(NT) gemm_rr_k(
    const float* __restrict__ Abase, long aStr,
    const float* __restrict__ Bbase, long bStr,
    void* __restrict__ Cbase, long cStr,
    int lda, int ldb, int ldc, int K,
    const float* __restrict__ colBias, float alpha)
{
    __shared__ float As[BK][BM];
    __shared__ float Bs[BK][BN];
    const int tid = threadIdx.x;
    const int bz  = blockIdx.z;
    const int m0  = blockIdx.y*BM;
    const int n0  = blockIdx.x*BN;
    const float* A = Abase + (long)bz*aStr + (long)m0*lda;
    const float* B = Bbase + (long)bz*bStr + n0;
    const int tx = tid % (BN/TN);
    const int ty = tid / (BN/TN);
    float acc[TM][TN];
#pragma unroll
    for (int i=0;i<TM;i++)
#pragma unroll
        for (int j=0;j<TN;j++) acc[i][j]=0.f;

    for (int k0 = 0; k0 < K; k0 += BK){
        for (int li = tid; li < BM*BK/4; li += NT){
            int m  = li/(BK/4), kv = li%(BK/4);
            float4 v = *(const float4*)(A + (long)m*lda + k0 + kv*4);
            As[kv*4+0][m]=v.x; As[kv*4+1][m]=v.y; As[kv*4+2][m]=v.z; As[kv*4+3][m]=v.w;
        }
        for (int li = tid; li < BN*BK/4; li += NT){
            int k  = li/(BN/4), nv = li%(BN/4);
            *(float4*)&Bs[k][nv*4] = *(const float4*)(B + (long)(k0+k)*ldb + nv*4);
        }
        __syncthreads();
#pragma unroll
        for (int kk = 0; kk < BK; kk++){
            float a[TM], bb[TN];
#pragma unroll
            for (int i=0;i<TM;i+=4) *(float4*)&a[i]  = *(const float4*)&As[kk][ty*TM+i];
#pragma unroll
            for (int j=0;j<TN;j+=4) *(float4*)&bb[j] = *(const float4*)&Bs[kk][tx*TN+j];
#pragma unroll
            for (int i=0;i<TM;i++)
#pragma unroll
                for (int j=0;j<TN;j++) acc[i][j] += a[i]*bb[j];
        }
        __syncthreads();
    }
#pragma unroll
    for (int i=0;i<TM;i++){
#pragma unroll
        for (int j=0;j<TN;j+=4){
            float4 v;
            v.x=acc[i][j+0]*alpha; v.y=acc[i][j+1]*alpha;
            v.z=acc[i][j+2]*alpha; v.w=acc[i][j+3]*alpha;
            if (colBias){
                const float* cb = colBias + n0 + tx*TN + j;
                v.x+=cb[0]; v.y+=cb[1]; v.z+=cb[2]; v.w+=cb[3];
            }
            long coff = (long)bz*cStr + (long)(m0+ty*TM+i)*ldc + n0 + tx*TN + j;
            if (OUTMODE == 0){
                *(float4*)((float*)Cbase + coff) = v;
            } else {
                uint2 u;
                u.x = packh2(v.x, v.y);
                u.y = packh2(v.z, v.w);
                *(uint2*)((__half*)Cbase + coff) = u;
            }
        }
    }
}

// -------------------- pack gwp/uwp (drop channel 0, [d][o][k] layout) ------
__global__ void k_pack(const float* __restrict__ wp, const float* __restrict__ w,
                       float* __restrict__ pwp, float* __restrict__ pw, int O)
{
    int idx = blockIdx.x*blockDim.x + threadIdx.x;
    if (blockIdx.y == 0){
        if (idx < 32*192*O){
            int r = idx % 192;
            int rem = idx / 192;
            int o = rem % O, d = rem / O;
            int c = r % 64, k = r / 64;
            pwp[idx] = wp[(((d*3 + k)*65) + (c+1))*O + o];
        }
    } else {
        if (idx < 192*O){
            int r = idx % 192;
            int o = idx / 192;
            int c = r % 64, k = r / 64;
            pw[idx] = w[((k*65) + (c+1))*O + o];
        }
    }
}

// -------------------- bias vectors: temb@bp + b0 ---------------------------
__global__ void k_bvec(const float* __restrict__ temb, const float* __restrict__ bp,
                       const float* __restrict__ b0, float* __restrict__ out, int O)
{
    int bt = blockIdx.x; int o = threadIdx.x;
    float acc = b0[o];
#pragma unroll
    for (int d = 0; d < 32; d++) acc += temb[bt*32+d]*bp[d*O+o];
    out[bt*O+o] = acc;
}

// -------------------- small STE projections --------------------------------
__global__ void k_small(const float* __restrict__ ne1, const float* __restrict__ ne2,
                        const float* __restrict__ Wq, const float* __restrict__ bq,
                        const float* __restrict__ Wk, const float* __restrict__ bk,
                        const float* __restrict__ Wv, const float* __restrict__ bv,
                        float* __restrict__ aq, float* __restrict__ ak, float* __restrict__ av)
{
    int b = blockIdx.x, y = blockIdx.y, h = threadIdx.x;
    const float *src, *W, *bias; float* out;
    if (y < 12)      { src = ne2 + (b*12+y)*32;  W = Wq; bias = bq; out = aq + (b*12+y)*64; }
    else if (y == 12){ src = ne1 + (b*12+11)*32; W = Wk; bias = bk; out = ak + b*64; }
    else             { src = ne1 + (b*12+11)*32; W = Wv; bias = bv; out = av + b*64; }
    float acc = bias[h];
#pragma unroll
    for (int d = 0; d < 32; d++) acc += src[d]*W[d*64+h];
    out[h] = acc;
}

// -------------------- X projections (xq, k, v, xw0) ------------------------
__global__ void __launch_bounds__(256) k_proj(
    const float* __restrict__ X,
    const float* __restrict__ Wq, const float* __restrict__ Wk,
    const float* __restrict__ Wv, const float* __restrict__ taw,
    const float* __restrict__ ak, const float* __restrict__ av,
    float* __restrict__ xq, float* __restrict__ kb,
    float* __restrict__ vb, float* __restrict__ xw0)
{
    __shared__ float Xs[64][64];
    __shared__ float Ws[64][64];
    const int tid  = threadIdx.x;
    const int mode = blockIdx.y;
    const int m0   = blockIdx.x*64;
    const int b    = m0 >> 9;
    const float* W = (mode==0)? Wq+2048 : (mode==1)? Wk+2048 : (mode==2)? Wv+2048 : taw;
    for (int li = tid; li < 1024; li += 256){
        int m = li>>4, kv = li&15;
        float4 v = *(const float4*)(X + (long)(m0+m)*64 + kv*4);
        Xs[kv*4+0][m]=v.x; Xs[kv*4+1][m]=v.y; Xs[kv*4+2][m]=v.z; Xs[kv*4+3][m]=v.w;
        *(float4*)&Ws[m][kv*4] = *(const float4*)(W + m*64 + kv*4);
    }
    __syncthreads();
    const int tx = tid&15, ty = tid>>4;
    float acc[4][4];
#pragma unroll
    for (int i=0;i<4;i++)
#pragma unroll
        for (int j=0;j<4;j++) acc[i][j]=0.f;
#pragma unroll
    for (int kk = 0; kk < 64; kk++){
        float a[4], bb[4];
        *(float4*)a  = *(const float4*)&Xs[kk][ty*4];
        *(float4*)bb = *(const float4*)&Ws[kk][tx*4];
#pragma unroll
        for (int i=0;i<4;i++)
#pragma unroll
            for (int j=0;j<4;j++) acc[i][j] += a[i]*bb[j];
    }
    float* outp = (mode==0)? xq : (mode==1)? kb : (mode==2)? vb : xw0;
#pragma unroll
    for (int i=0;i<4;i++){
        int m = m0 + ty*4 + i;
        float4 r;
        if (mode==1 || mode==2){
            const float* bias = ((mode==1)? ak:av) + b*64 + tx*4;
            r.x=fmaxf(acc[i][0]+bias[0],0.f); r.y=fmaxf(acc[i][1]+bias[1],0.f);
            r.z=fmaxf(acc[i][2]+bias[2],0.f); r.w=fmaxf(acc[i][3]+bias[3],0.f);
        } else {
            r.x=acc[i][0]; r.y=acc[i][1]; r.z=acc[i][2]; r.w=acc[i][3];
        }
        *(float4*)(outp + (long)m*64 + tx*4) = r;
    }
}

// -------------------- attention scores + softmax ---------------------------
__global__ void __launch_bounds__(256) k_attn(
    const float* __restrict__ aq, const float* __restrict__ xq,
    const float* __restrict__ kb, float* __restrict__ sm_out)
{
    __shared__ float aq_s[768];
    const int b = blockIdx.y;
    const int tid = threadIdx.x, lane = tid&31, w = tid>>5;
    for (int i = tid; i < 768; i += 256) aq_s[i] = aq[b*768 + i];
    __syncthreads();
    const int n0 = blockIdx.x*32 + w*4;
    for (int j = 0; j < 4; j++){
        int bn = b*512 + n0 + j;
        float xq0 = xq[bn*64 + lane],      xq1 = xq[bn*64 + 32 + lane];
        float k0  = kb[bn*64 + lane],      k1  = kb[bn*64 + 32 + lane];
        float sc0[12], sc1[12];
#pragma unroll
        for (int t = 0; t < 12; t++){
            float q0 = fmaxf(aq_s[t*64 + lane] + xq0, 0.f);
            float q1 = fmaxf(aq_s[t*64 + 32 + lane] + xq1, 0.f);
            float p0 = q0*k0, p1 = q1*k1;
#pragma unroll
            for (int o = 1; o < 8; o <<= 1){
                p0 += __shfl_xor_sync(0xffffffffu, p0, o);
                p1 += __shfl_xor_sync(0xffffffffu, p1, o);
            }
            sc0[t] = p0; sc1[t] = p1;
        }
        float m0 = -1e30f, m1 = -1e30f;
#pragma unroll
        for (int t = 0; t < 12; t++){ m0 = fmaxf(m0, sc0[t]); m1 = fmaxf(m1, sc1[t]); }
        float s0 = 0.f, s1 = 0.f;
#pragma unroll
        for (int t = 0; t < 12; t++){ sc0[t] = expf(sc0[t]-m0); s0 += sc0[t];
                                      sc1[t] = expf(sc1[t]-m1); s1 += sc1[t]; }
        float r0 = 1.f/s0, r1 = 1.f/s1;
        if ((lane & 7) == 0){
            int d = lane >> 3;
#pragma unroll
            for (int t = 0; t < 12; t++){
                sm_out[bn*96 + t*8 + d]     = sc0[t]*r0;
                sm_out[bn*96 + t*8 + 4 + d] = sc1[t]*r1;
            }
        }
    }
}

// -------------------- build de (f32 + fp16 into xg rows 0-63) --------------
__global__ void __launch_bounds__(256) k_debuild(
    const float* __restrict__ sm, const float* __restrict__ vb,
    const float* __restrict__ xw0, const float* __restrict__ taw,
    const float* __restrict__ tab, float* __restrict__ de,
    __half* __restrict__ dehf)
{
    __shared__ float taw1s[64][64];
    __shared__ float wvT[64][33];
    __shared__ float xw0s[64][33];
    const int b = blockIdx.z, t = blockIdx.y, n0 = blockIdx.x*32;
    const int tid = threadIdx.x;
    for (int i = tid; i < 4096; i += 256)
        taw1s[i>>6][i&63] = taw[4096 + i];
    for (int idx = tid; idx < 2048; idx += 256){
        int nl = idx >> 6, i = idx & 63;
        int bn = b*512 + n0 + nl;
        float s = sm[bn*96 + t*8 + (i>>3)];
        wvT[i][nl]  = s * vb[bn*64 + i];
        xw0s[i][nl] = xw0[bn*64 + i];
    }
    __syncthreads();
    const int tx = tid & 15, ty = tid >> 4;
    float acc[4][2] = {};
#pragma unroll
    for (int i = 0; i < 64; i++){
        float4 a = *(const float4*)&taw1s[i][ty*4];
        float b0 = wvT[i][tx*2], b1 = wvT[i][tx*2+1];
        acc[0][0]+=a.x*b0; acc[0][1]+=a.x*b1;
        acc[1][0]+=a.y*b0; acc[1][1]+=a.y*b1;
        acc[2][0]+=a.z*b0; acc[2][1]+=a.z*b1;
        acc[3][0]+=a.w*b0; acc[3][1]+=a.w*b1;
    }
    const int bt = b*12 + t;
    long baseD = (long)bt*32768;
    long baseH = (long)bt*98304;
#pragma unroll
    for (int oi = 0; oi < 4; oi++){
        int o = ty*4 + oi;
        float bias = tab[o];
        float2 v;
        v.x = acc[oi][0] + xw0s[o][tx*2]   + bias;
        v.y = acc[oi][1] + xw0s[o][tx*2+1] + bias;
        *(float2*)&de[baseD + (long)o*512 + n0 + tx*2] = v;
        uint32_t u = packh2(v.x, v.y);
        *(uint32_t*)&dehf[baseH + (long)o*512 + n0 + tx*2] = u;
    }
}

// ===========================================================================
extern "C" void kernel_launch(void* const* d_in, const int* in_sizes, int n_in,
                              void* d_out, int out_size)
{
    const float* h_n  = (const float*)d_in[2];
    const float* ne1  = (const float*)d_in[3];
    const float* ne2  = (const float*)d_in[4];
    const float* E    = (const float*)d_in[5];
    const float* Wq   = (const float*)d_in[6];
    const float* bq   = (const float*)d_in[7];
    const float* Wk   = (const float*)d_in[8];
    const float* bk   = (const float*)d_in[9];
    const float* Wv   = (const float*)d_in[10];
    const float* bv   = (const float*)d_in[11];
    const float* taw  = (const float*)d_in[12];
    const float* tab  = (const float*)d_in[13];
    const float* gwp  = (const float*)d_in[14];
    const float* gw   = (const float*)d_in[15];
    const float* gbp  = (const float*)d_in[16];
    const float* gb   = (const float*)d_in[17];
    const float* uwp  = (const float*)d_in[18];
    const float* uw   = (const float*)d_in[19];
    const float* ubp  = (const float*)d_in[20];
    const float* ub   = (const float*)d_in[21];
    const float* outw = (const float*)d_in[22];
    const float* outb = (const float*)d_in[23];
    float* out = (float*)d_out;

    float *Arm, *kb2, *vb2, *xq, *xw0, *aq, *ak, *av, *sm, *de;
    float *b1, *b2, *wp1, *w1b, *wp2, *w2b, *rg;
    __half *Ahf, *S2hf, *xg1, *xg2, *W1hf, *W2hf;
    cudaGetSymbolAddress((void**)&Arm,  g_Arm);
    cudaGetSymbolAddress((void**)&Ahf,  g_Ahf);
    cudaGetSymbolAddress((void**)&S2hf, g_S2hf);
    cudaGetSymbolAddress((void**)&kb2,  g_kb);
    cudaGetSymbolAddress((void**)&vb2,  g_vb);
    cudaGetSymbolAddress((void**)&xq,   g_xq);
    cudaGetSymbolAddress((void**)&xw0,  g_xw0);
    cudaGetSymbolAddress((void**)&aq,   g_aq);
    cudaGetSymbolAddress((void**)&ak,   g_ak);
    cudaGetSymbolAddress((void**)&av,   g_av);
    cudaGetSymbolAddress((void**)&sm,   g_sm);
    cudaGetSymbolAddress((void**)&de,   g_de);
    cudaGetSymbolAddress((void**)&xg1,  g_xg1);
    cudaGetSymbolAddress((void**)&xg2,  g_xg2);
    cudaGetSymbolAddress((void**)&W1hf, g_W1hf);
    cudaGetSymbolAddress((void**)&W2hf, g_W2hf);
    cudaGetSymbolAddress((void**)&b1,   g_b1);
    cudaGetSymbolAddress((void**)&b2,   g_b2);
    cudaGetSymbolAddress((void**)&wp1,  g_wp1);
    cudaGetSymbolAddress((void**)&w1b,  g_w1b);
    cudaGetSymbolAddress((void**)&wp2,  g_wp2);
    cudaGetSymbolAddress((void**)&w2b,  g_w2b);
    cudaGetSymbolAddress((void**)&rg,   g_rg);

    const int SUPP2_SMEM = 6*128*20*4;                       // 61440
    const int CTR1_SMEM  = 128*200*2 + 2*32*136*2;           // 68608
    const int CTR2_SMEM  = 64*132*4*2 + 2*128*4;             // 68608
    cudaFuncSetAttribute(k_supp2_hmma, cudaFuncAttributeMaxDynamicSharedMemorySize, SUPP2_SMEM);
    cudaFuncSetAttribute(k_ctr1_fused, cudaFuncAttributeMaxDynamicSharedMemorySize, CTR1_SMEM);
    cudaFuncSetAttribute(k_ctr2_fused, cudaFuncAttributeMaxDynamicSharedMemorySize, CTR2_SMEM);

    // ---- adjacency & supports ----
    k_A<<<512, 512>>>(E, Arm, Ahf);
    gemm_rr_k<64,64,16,4,4,256,2><<<dim3(8,8,1), 256>>>(      // S2hf = 2*A@A (fp16 direct)
        Arm, 0, Arm, 0, S2hf, 0, 512, 512, 512, 512, nullptr, 2.f);
    k_fixdiag_h<<<1, 512>>>(S2hf);

    // ---- pack GCN weights ([d][o][k]), build per-bt W' fp16 + bias ----
    k_pack<<<dim3(3072,2), 256>>>(gwp, gw, wp1, w1b, 128);
    k_pack<<<dim3(1536,2), 256>>>(uwp, uw, wp2, w2b, 64);
    k_bvec<<<768, 128>>>(ne2, gbp, gb, b1, 128);
    k_bvec<<<768, 64 >>>(ne2, ubp, ub, b2, 64);
    gemm_rr_k<64,64,16,4,4,256,2><<<dim3(384,12,1), 256>>>(   // W1' fp16 [bt][o][k]
        ne2, 0, wp1, 0, W1hf, 0, 32, 24576, 24576, 32, w1b, 1.f);
    gemm_rr_k<64,64,16,4,4,256,2><<<dim3(192,12,1), 256>>>(   // W2' fp16
        ne2, 0, wp2, 0, W2hf, 0, 32, 12288, 12288, 32, w2b, 1.f);

    // ---- attention path ----
    k_small<<<dim3(64,14), 64>>>(ne1, ne2, Wq, bq, Wk, bk, Wv, bv, aq, ak, av);
    k_proj<<<dim3(512,4), 256>>>(h_n, Wq, Wk, Wv, taw, ak, av, xq, kb2, vb2, xw0);
    k_attn<<<dim3(16,64), 256>>>(aq, xq, kb2, sm);
    k_debuild<<<dim3(16,12,64), 256>>>(sm, vb2, xw0, taw, tab, de, xg1);

    // ---- GCN1: supports + fused contraction/gate ----
    k_supp2_hmma<<<dim3(4,384), 256, SUPP2_SMEM>>>(xg1, Ahf, S2hf,
                                                   xg1 + 64*512, xg1 + 128*512);
    k_ctr1_fused<<<dim3(4,768), 256, CTR1_SMEM>>>(xg1, W1hf, b1, de, xg2, rg);

    // ---- GCN2: supports + fused contraction/blend/head ----
    k_supp2_hmma<<<dim3(4,384), 256, SUPP2_SMEM>>>(xg2, Ahf, S2hf,
                                                   xg2 + 64*512, xg2 + 128*512);
    k_ctr2_fused<<<dim3(4,768), 256, CTR2_SMEM>>>(xg2, W2hf, b2, de, rg,
                                                  outw, outb, out);
}

// round 16
// speedup vs baseline: 3.9371x; 1.0333x over previous
#include <cuda_runtime.h>
#include <cuda_fp16.h>
#include <math.h>
#include <stdint.h>

// Problem constants: B=64, T=12, N=512, H=64, TD=32, ED=16, CHEB_K=3, D_HEADS=8
// BT = 768. Effective GCN channels = 64 (channel 0 is identically zero).

// -------------------- static device scratch --------------------------------
static __device__ float g_Arm[512*512];            // A row-major (f32, for S2 build)
static __device__ __half g_Ahf [512*512];          // fp16 support B operands
static __device__ __half g_S2hf[512*512];
static __device__ float g_kb [64*512*64];
static __device__ float g_vb [64*512*64];
static __device__ float g_xq [64*512*64];
static __device__ float g_xw0[64*512*64];
static __device__ float g_aq [64*12*64];
static __device__ float g_ak [64*64];
static __device__ float g_av [64*64];
static __device__ float g_sm [64*512*12*8];
static __device__ __half g_xg1[768*192*512];       // fp16 [bt][j][n] j:0-63 de,64-127 A@,128-191 S2@
static __device__ __half g_xg2[768*192*512];       // same for cand
static __device__ __half g_W1hf[768*128*192];      // W' [bt][o][k] fp16
static __device__ __half g_W2hf[768*64*192];
static __device__ float g_b1 [768*128];
static __device__ float g_b2 [768*64];
static __device__ float g_wp1[32*128*192];         // packed [d][o][k]
static __device__ float g_w1b[128*192];
static __device__ float g_wp2[32*64*192];
static __device__ float g_w2b[64*192];
static __device__ float g_rg [768*64*512];         // pre-sigmoid rg, channel-major

// -------------------- helpers ----------------------------------------------
__device__ __forceinline__ uint32_t smem_u32p(const void* p){
    uint32_t a;
    asm("{ .reg .u64 t; cvta.to.shared.u64 t, %1; cvt.u32.u64 %0, t; }" : "=r"(a) : "l"(p));
    return a;
}
__device__ __forceinline__ void cp16(void* dst, const void* src){
    uint32_t d = smem_u32p(dst);
    asm volatile("cp.async.cg.shared.global [%0], [%1], 16;" :: "r"(d), "l"(src));
}
__device__ __forceinline__ void mma_f16(float* c, const uint32_t* a, const uint32_t* b){
    asm volatile(
        "mma.sync.aligned.m16n8k16.row.col.f32.f16.f16.f32 "
        "{%0,%1,%2,%3}, {%4,%5,%6,%7}, {%8,%9}, {%0,%1,%2,%3};"
        : "+f"(c[0]),"+f"(c[1]),"+f"(c[2]),"+f"(c[3])
        : "r"(a[0]),"r"(a[1]),"r"(a[2]),"r"(a[3]), "r"(b[0]),"r"(b[1]));
}
__device__ __forceinline__ void ldmx4t(uint32_t* r, uint32_t addr){
    asm volatile("ldmatrix.sync.aligned.m8n8.x4.trans.shared.b16 {%0,%1,%2,%3}, [%4];"
        : "=r"(r[0]),"=r"(r[1]),"=r"(r[2]),"=r"(r[3]) : "r"(addr));
}
__device__ __forceinline__ uint32_t packh2(float x, float y){
    __half2 h = __floats2half2_rn(x, y);
    return *(uint32_t*)&h;
}
// stage a [64 x 128] fp16 tile (row stride 512) into f32 smem [64][132]
__device__ __forceinline__ void stage_h2f(const __half* __restrict__ src,
                                          float* __restrict__ dst, int tid){
    for (int idx = tid; idx < 2048; idx += 256){
        int cc = idx >> 5, j = idx & 31;
        uint2 u = *(const uint2*)(src + (size_t)cc*512 + j*4);
        __half2 h0 = *(__half2*)&u.x, h1 = *(__half2*)&u.y;
        float2 f0 = __half22float2(h0), f1 = __half22float2(h1);
        float* d = dst + cc*132 + j*4;
        d[0] = f0.x; d[1] = f0.y; d[2] = f1.x; d[3] = f1.y;
    }
}

// -------------------- fused dual support GEMM (fp16 HMMA) ------------------
__global__ void __launch_bounds__(256) k_supp2_hmma(
    const __half* __restrict__ xhf,
    const __half* __restrict__ B1hf,
    const __half* __restrict__ B2hf,
    __half* __restrict__ out1,
    __half* __restrict__ out2)
{
    constexpr int LD = 20;
    extern __shared__ uint32_t sh[];
    uint32_t* As  = sh;
    uint32_t* B1s = sh + 2*128*LD;
    uint32_t* B2s = sh + 4*128*LD;
    const int tid = threadIdx.x, wid = tid>>5, lane = tid&31;
    const int g = lane>>2, tg = lane&3;
    const int p = blockIdx.y, n0 = blockIdx.x*128;
    const int wm = wid & 1, wn = wid >> 1;
    const int mbase = wm*64, nbase = wn*32;

    float c[2][4][4][4];
#pragma unroll
    for (int s=0;s<2;s++)
#pragma unroll
        for (int i=0;i<4;i++)
#pragma unroll
            for (int j=0;j<4;j++)
#pragma unroll
                for (int q=0;q<4;q++) c[s][i][j][q]=0.f;

    auto load = [&](int ch, int sel){
        uint32_t* a  = As  + sel*128*LD;
        uint32_t* b1 = B1s + sel*128*LD;
        uint32_t* b2 = B2s + sel*128*LD;
        const int k0 = ch*32;
#pragma unroll
        for (int it = 0; it < 2; it++){
            int lin = tid + it*256;
            int r = lin >> 2, q = lin & 3;
            cp16(a  + r*LD + q*4,
                 xhf + (size_t)(2*p + (r>>6))*98304 + (size_t)(r&63)*512 + k0 + q*8);
            cp16(b1 + r*LD + q*4, B1hf + (size_t)(n0 + r)*512 + k0 + q*8);
            cp16(b2 + r*LD + q*4, B2hf + (size_t)(n0 + r)*512 + k0 + q*8);
        }
        asm volatile("cp.async.commit_group;" ::: "memory");
    };

    load(0, 0);
    for (int i = 0; i < 16; i++){
        const int cur = i & 1;
        if (i + 1 < 16){
            load(i+1, cur^1);
            asm volatile("cp.async.wait_group 1;" ::: "memory");
        } else {
            asm volatile("cp.async.wait_group 0;" ::: "memory");
        }
        __syncthreads();
        const uint32_t* a  = As  + cur*128*LD;
        const uint32_t* b1 = B1s + cur*128*LD;
        const uint32_t* b2 = B2s + cur*128*LD;
#pragma unroll
        for (int ks = 0; ks < 2; ks++){
            uint32_t af[4][4], bf1[4][2], bf2[4][2];
#pragma unroll
            for (int mt = 0; mt < 4; mt++){
                int row = mbase + mt*16 + g;
                af[mt][0] = a[ row   *LD + ks*8 + tg    ];
                af[mt][1] = a[(row+8)*LD + ks*8 + tg    ];
                af[mt][2] = a[ row   *LD + ks*8 + tg + 4];
                af[mt][3] = a[(row+8)*LD + ks*8 + tg + 4];
            }
#pragma unroll
            for (int nt = 0; nt < 4; nt++){
                int nr = nbase + nt*8 + g;
                bf1[nt][0] = b1[nr*LD + ks*8 + tg    ];
                bf1[nt][1] = b1[nr*LD + ks*8 + tg + 4];
                bf2[nt][0] = b2[nr*LD + ks*8 + tg    ];
                bf2[nt][1] = b2[nr*LD + ks*8 + tg + 4];
            }
#pragma unroll
            for (int mt = 0; mt < 4; mt++)
#pragma unroll
                for (int nt = 0; nt < 4; nt++){
                    mma_f16(c[0][mt][nt], af[mt], bf1[nt]);
                    mma_f16(c[1][mt][nt], af[mt], bf2[nt]);
                }
        }
        __syncthreads();
    }

#pragma unroll
    for (int s = 0; s < 2; s++){
        __half* outp = s ? out2 : out1;
#pragma unroll
        for (int mt = 0; mt < 4; mt++){
            int r0 = mbase + mt*16 + g;
#pragma unroll
            for (int half = 0; half < 2; half++){
                int r = r0 + half*8;
                __half* orow = outp + (size_t)(2*p + (r>>6))*98304
                             + (size_t)(r&63)*512 + n0 + nbase;
#pragma unroll
                for (int nt = 0; nt < 4; nt++){
                    uint32_t u = packh2(c[s][mt][nt][half*2+0], c[s][mt][nt][half*2+1]);
                    *(uint32_t*)(orow + nt*8 + tg*2) = u;
                }
            }
        }
    }
}

// -------------------- ctr1: contraction + fused gate -----------------------
// zr[n][o] = sum_k xg1[k][n]*W1'[o][k] + b1[o]
// o<64  : cand = sigmoid(zr)*de  -> xg2 fp16 (channel-major)
// o>=64 : rg (pre-sigmoid)       -> rg f32 (channel-major)
// de read from xg1 rows 0-63 (fp16).
__global__ void __launch_bounds__(256) k_ctr1_fused(
    const __half* __restrict__ xhf,     // xg1
    const __half* __restrict__ Whf,     // [768][128][192]
    const float* __restrict__ bias,     // [768][128]
    __half* __restrict__ cand,          // xg2 base
    float* __restrict__ rg)             // [768][64][512]
{
    constexpr int BN = 128, MT = 4, NTT = 4, WARPS_M = 2;
    constexpr int LDA = 136, LDB = 200, NC = 6;
    extern __shared__ __half shh[];
    __half* Bs = shh;
    __half* As = shh + BN*LDB;
    const int tid = threadIdx.x, wid = tid>>5, lane = tid&31;
    const int g = lane>>2, tg = lane&3;
    const int bt = blockIdx.y, m0 = blockIdx.x*128;
    const int wm = wid % WARPS_M, wn = wid / WARPS_M;
    const int mbase = wm*(MT*16), nbase = wn*(NTT*8);
    const __half* Ab = xhf + (size_t)bt*98304 + m0;
    const __half* Bb = Whf + (size_t)bt*BN*192;
    const uint32_t aBase = smem_u32p(shh) + (uint32_t)(BN*LDB*2);

    float c[MT][NTT][4];
#pragma unroll
    for (int i=0;i<MT;i++)
#pragma unroll
        for (int j=0;j<NTT;j++)
#pragma unroll
            for (int q=0;q<4;q++) c[i][j][q]=0.f;

    {
        const int nch = BN*24;
#pragma unroll
        for (int it = 0; it < nch/256; it++){
            int lin = tid + it*256;
            int o = lin / 24, q = lin % 24;
            cp16(Bs + o*LDB + q*8, Bb + (size_t)o*192 + q*8);
        }
        asm volatile("cp.async.commit_group;" ::: "memory");
    }
    auto loadA = [&](int ch, int sel){
        __half* a = As + sel*32*LDA;
        const int k0 = ch*32;
#pragma unroll
        for (int it = 0; it < 2; it++){
            int lin = tid + it*256;
            int kr = lin >> 4, q = lin & 15;
            cp16(a + kr*LDA + q*8, Ab + (size_t)(k0+kr)*512 + q*8);
        }
        asm volatile("cp.async.commit_group;" ::: "memory");
    };

    loadA(0, 0);
    for (int i = 0; i < NC; i++){
        const int cur = i & 1;
        if (i + 1 < NC){
            loadA(i+1, cur^1);
            asm volatile("cp.async.wait_group 1;" ::: "memory");
        } else {
            asm volatile("cp.async.wait_group 0;" ::: "memory");
        }
        __syncthreads();
        const uint32_t aBuf = aBase + (uint32_t)(cur*32*LDA*2);
        const int kabs = i*32;
#pragma unroll
        for (int ks = 0; ks < 2; ks++){
            uint32_t af[MT][4], bf[NTT][2];
            const int krow = ks*16 + ((lane>>4)&1)*8 + (lane&7);
            const int cof  = ((lane>>3)&1)*8;
#pragma unroll
            for (int mt = 0; mt < MT; mt++){
                uint32_t addr = aBuf + (uint32_t)((krow*LDA + mbase + mt*16 + cof)*2);
                ldmx4t(af[mt], addr);
            }
#pragma unroll
            for (int nt = 0; nt < NTT; nt++){
                const __half* brow = Bs + (size_t)(nbase + nt*8 + g)*LDB + kabs + ks*16;
                bf[nt][0] = *(const uint32_t*)(brow + tg*2);
                bf[nt][1] = *(const uint32_t*)(brow + 8 + tg*2);
            }
#pragma unroll
            for (int mt = 0; mt < MT; mt++)
#pragma unroll
                for (int nt = 0; nt < NTT; nt++)
                    mma_f16(c[mt][nt], af[mt], bf[nt]);
        }
        __syncthreads();
    }

    // ---- stage de tile [64][132] from xg1 rows 0-63 (fp16) ----
    float* de_s = (float*)shh;
    stage_h2f(Ab, de_s, tid);
    __syncthreads();

#pragma unroll
    for (int mt = 0; mt < MT; mt++){
#pragma unroll
        for (int half = 0; half < 2; half++){
            int nl = mbase + mt*16 + half*8 + g;
            int n_ = m0 + nl;
#pragma unroll
            for (int nt = 0; nt < NTT; nt++){
                int o = nbase + nt*8 + tg*2;
                float v0 = c[mt][nt][half*2+0] + bias[bt*128 + o];
                float v1 = c[mt][nt][half*2+1] + bias[bt*128 + o + 1];
                if (nbase < 64){
                    float z0 = 1.f/(1.f + expf(-v0));
                    float z1 = 1.f/(1.f + expf(-v1));
                    __half* xo = cand + (size_t)bt*98304 + (size_t)o*512 + n_;
                    xo[0]   = __float2half(z0 * de_s[o*132 + nl]);
                    xo[512] = __float2half(z1 * de_s[(o+1)*132 + nl]);
                } else {
                    float* ro = rg + (size_t)bt*32768 + (size_t)(o-64)*512 + n_;
                    ro[0]   = v0;
                    ro[512] = v1;
                }
            }
        }
    }
}

// -------------------- ctr2: contraction + fused final blend + head ---------
// hc[n][o] = sum_k xg2[k][n]*W2'[o][k] + b2[o]
// st = sigmoid(rg)*de + (1-sigmoid(rg))*tanh(hc); out[n] = sum_o st*out_w[tt][o] + out_b[tt]
// de read from xg1 rows 0-63 (fp16).
__global__ void __launch_bounds__(256) k_ctr2_fused(
    const __half* __restrict__ xhf,     // xg2
    const __half* __restrict__ Whf,     // [768][64][192]
    const float* __restrict__ bias,     // [768][64]
    const __half* __restrict__ dehf,    // xg1 base
    const float* __restrict__ rg,       // [768][64][512]
    const float* __restrict__ out_w,    // [12][64]
    const float* __restrict__ out_b,    // [12]
    float* __restrict__ outp)           // [768][512]
{
    constexpr int BN = 64, MT = 2, NTT = 4, WARPS_M = 4;
    constexpr int LDA = 136, LDB = 200, NC = 6;
    extern __shared__ __half shh[];
    __half* Bs = shh;
    __half* As = shh + BN*LDB;
    const int tid = threadIdx.x, wid = tid>>5, lane = tid&31;
    const int g = lane>>2, tg = lane&3;
    const int bt = blockIdx.y, m0 = blockIdx.x*128;
    const int wm = wid % WARPS_M, wn = wid / WARPS_M;
    const int mbase = wm*(MT*16), nbase = wn*(NTT*8);
    const __half* Ab = xhf + (size_t)bt*98304 + m0;
    const __half* Bb = Whf + (size_t)bt*BN*192;
    const uint32_t aBase = smem_u32p(shh) + (uint32_t)(BN*LDB*2);

    float c[MT][NTT][4];
#pragma unroll
    for (int i=0;i<MT;i++)
#pragma unroll
        for (int j=0;j<NTT;j++)
#pragma unroll
            for (int q=0;q<4;q++) c[i][j][q]=0.f;

    {
        const int nch = BN*24;
#pragma unroll
        for (int it = 0; it < nch/256; it++){
            int lin = tid + it*256;
            int o = lin / 24, q = lin % 24;
            cp16(Bs + o*LDB + q*8, Bb + (size_t)o*192 + q*8);
        }
        asm volatile("cp.async.commit_group;" ::: "memory");
    }
    auto loadA = [&](int ch, int sel){
        __half* a = As + sel*32*LDA;
        const int k0 = ch*32;
#pragma unroll
        for (int it = 0; it < 2; it++){
            int lin = tid + it*256;
            int kr = lin >> 4, q = lin & 15;
            cp16(a + kr*LDA + q*8, Ab + (size_t)(k0+kr)*512 + q*8);
        }
        asm volatile("cp.async.commit_group;" ::: "memory");
    };

    loadA(0, 0);
    for (int i = 0; i < NC; i++){
        const int cur = i & 1;
        if (i + 1 < NC){
            loadA(i+1, cur^1);
            asm volatile("cp.async.wait_group 1;" ::: "memory");
        } else {
            asm volatile("cp.async.wait_group 0;" ::: "memory");
        }
        __syncthreads();
        const uint32_t aBuf = aBase + (uint32_t)(cur*32*LDA*2);
        const int kabs = i*32;
#pragma unroll
        for (int ks = 0; ks < 2; ks++){
            uint32_t af[MT][4], bf[NTT][2];
            const int krow = ks*16 + ((lane>>4)&1)*8 + (lane&7);
            const int cof  = ((lane>>3)&1)*8;
#pragma unroll
            for (int mt = 0; mt < MT; mt++){
                uint32_t addr = aBuf + (uint32_t)((krow*LDA + mbase + mt*16 + cof)*2);
                ldmx4t(af[mt], addr);
            }
#pragma unroll
            for (int nt = 0; nt < NTT; nt++){
                const __half* brow = Bs + (size_t)(nbase + nt*8 + g)*LDB + kabs + ks*16;
                bf[nt][0] = *(const uint32_t*)(brow + tg*2);
                bf[nt][1] = *(const uint32_t*)(brow + 8 + tg*2);
            }
#pragma unroll
            for (int mt = 0; mt < MT; mt++)
#pragma unroll
                for (int nt = 0; nt < NTT; nt++)
                    mma_f16(c[mt][nt], af[mt], bf[nt]);
        }
        __syncthreads();
    }

    // ---- stage de (fp16 from xg1) + rg (f32) tiles, fused blend + head ----
    float* de_s = (float*)shh;
    float* rg_s = de_s + 64*132;
    float* red  = rg_s + 64*132;        // [2][128]
    stage_h2f(dehf + (size_t)bt*98304 + m0, de_s, tid);
    {
        const float* rgb = rg + (size_t)bt*32768 + m0;
        for (int idx = tid; idx < 64*32; idx += 256){
            int cc = idx >> 5, j = idx & 31;
            *(float4*)(rg_s + cc*132 + j*4) = *(const float4*)(rgb + (size_t)cc*512 + j*4);
        }
    }
    __syncthreads();
    const int tt = bt % 12;
    float bo[NTT][2], wv[NTT][2];
#pragma unroll
    for (int nt = 0; nt < NTT; nt++){
        int o = nbase + nt*8 + tg*2;
        bo[nt][0] = bias[bt*64 + o];   bo[nt][1] = bias[bt*64 + o + 1];
        wv[nt][0] = out_w[tt*64 + o];  wv[nt][1] = out_w[tt*64 + o + 1];
    }
#pragma unroll
    for (int mt = 0; mt < MT; mt++){
#pragma unroll
        for (int half = 0; half < 2; half++){
            int nl = mbase + mt*16 + half*8 + g;
            float p = 0.f;
#pragma unroll
            for (int nt = 0; nt < NTT; nt++){
                int o = nbase + nt*8 + tg*2;
#pragma unroll
                for (int q = 0; q < 2; q++){
                    float v   = c[mt][nt][half*2+q] + bo[nt][q];
                    float hcv = tanhf(v);
                    float r   = 1.f/(1.f + expf(-rg_s[(o+q)*132 + nl]));
                    float st  = r*de_s[(o+q)*132 + nl] + (1.f - r)*hcv;
                    p += st * wv[nt][q];
                }
            }
            p += __shfl_xor_sync(0xffffffffu, p, 1);
            p += __shfl_xor_sync(0xffffffffu, p, 2);
            if (tg == 0) red[wn*128 + nl] = p;
        }
    }
    __syncthreads();
    if (tid < 128)
        outp[(size_t)bt*512 + m0 + tid] = red[tid] + red[128 + tid] + out_b[tt];
}

// -------------------- adjacency: A row-major + fp16 ------------------------
__global__ void k_A(const float* __restrict__ E, float* __restrict__ Arm,
                    __half* __restrict__ Ahf)
{
    __shared__ float Es[512*16];
    __shared__ float red[512];
    const int tid = threadIdx.x;
    const int n   = blockIdx.x;
    for (int i = tid; i < 512*16; i += 512) Es[i] = E[i];
    __syncthreads();
    float acc = 0.f;
#pragma unroll
    for (int d = 0; d < 16; d++) acc += Es[n*16+d]*Es[tid*16+d];
    acc = fmaxf(acc, 0.f);
    red[tid] = acc; __syncthreads();
    for (int s = 256; s > 0; s >>= 1){ if (tid < s) red[tid] = fmaxf(red[tid], red[tid+s]); __syncthreads(); }
    float mx = red[0]; __syncthreads();
    float e = expf(acc - mx);
    red[tid] = e; __syncthreads();
    for (int s = 256; s > 0; s >>= 1){ if (tid < s) red[tid] += red[tid+s]; __syncthreads(); }
    float v = e / red[0];
    Arm[n*512 + tid] = v;
    Ahf[n*512 + tid] = __float2half(v);
}

__global__ void k_fixdiag_h(__half* __restrict__ S)
{
    int i = threadIdx.x;
    S[i*513] = __hsub(S[i*513], __float2half(1.f));
}

// -------------------- generic SGEMM, A row-major ---------------------------
// OUTMODE: 0 = f32 out, 2 = fp16 out
template<int BM,int BN,int BK,int TM,int TN,int NT,int OUTMODE>
__global__ void __launch_bounds__(NT) gemm_rr_k(
    const float* __restrict__ Abase, long aStr,
    const float* __restrict__ Bbase, long bStr,
    void* __restrict__ Cbase, long cStr,
    int lda, int ldb, int ldc, int K,
    const float* __restrict__ colBias, float alpha)
{
    __shared__ float As[BK][BM];
    __shared__ float Bs[BK][BN];
    const int tid = threadIdx.x;
    const int bz  = blockIdx.z;
    const int m0  = blockIdx.y*BM;
    const int n0  = blockIdx.x*BN;
    const float* A = Abase + (long)bz*aStr + (long)m0*lda;
    const float* B = Bbase + (long)bz*bStr + n0;
    const int tx = tid % (BN/TN);
    const int ty = tid / (BN/TN);
    float acc[TM][TN];
#pragma unroll
    for (int i=0;i<TM;i++)
#pragma unroll
        for (int j=0;j<TN;j++) acc[i][j]=0.f;

    for (int k0 = 0; k0 < K; k0 += BK){
        for (int li = tid; li < BM*BK/4; li += NT){
            int m  = li/(BK/4), kv = li%(BK/4);
            float4 v = *(const float4*)(A + (long)m*lda + k0 + kv*4);
            As[kv*4+0][m]=v.x; As[kv*4+1][m]=v.y; As[kv*4+2][m]=v.z; As[kv*4+3][m]=v.w;
        }
        for (int li = tid; li < BN*BK/4; li += NT){
            int k  = li/(BN/4), nv = li%(BN/4);
            *(float4*)&Bs[k][nv*4] = *(const float4*)(B + (long)(k0+k)*ldb + nv*4);
        }
        __syncthreads();
#pragma unroll
        for (int kk = 0; kk < BK; kk++){
            float a[TM], bb[TN];
#pragma unroll
            for (int i=0;i<TM;i+=4) *(float4*)&a[i]  = *(const float4*)&As[kk][ty*TM+i];
#pragma unroll
            for (int j=0;j<TN;j+=4) *(float4*)&bb[j] = *(const float4*)&Bs[kk][tx*TN+j];
#pragma unroll
            for (int i=0;i<TM;i++)
#pragma unroll
                for (int j=0;j<TN;j++) acc[i][j] += a[i]*bb[j];
        }
        __syncthreads();
    }
#pragma unroll
    for (int i=0;i<TM;i++){
#pragma unroll
        for (int j=0;j<TN;j+=4){
            float4 v;
            v.x=acc[i][j+0]*alpha; v.y=acc[i][j+1]*alpha;
            v.z=acc[i][j+2]*alpha; v.w=acc[i][j+3]*alpha;
            if (colBias){
                const float* cb = colBias + n0 + tx*TN + j;
                v.x+=cb[0]; v.y+=cb[1]; v.z+=cb[2]; v.w+=cb[3];
            }
            long coff = (long)bz*cStr + (long)(m0+ty*TM+i)*ldc + n0 + tx*TN + j;
            if (OUTMODE == 0){
                *(float4*)((float*)Cbase + coff) = v;
            } else {
                uint2 u;
                u.x = packh2(v.x, v.y);
                u.y = packh2(v.z, v.w);
                *(uint2*)((__half*)Cbase + coff) = u;
            }
        }
    }
}

// -------------------- pack gwp/uwp (drop channel 0, [d][o][k] layout) ------
__global__ void k_pack(const float* __restrict__ wp, const float* __restrict__ w,
                       float* __restrict__ pwp, float* __restrict__ pw, int O)
{
    int idx = blockIdx.x*blockDim.x + threadIdx.x;
    if (blockIdx.y == 0){
        if (idx < 32*192*O){
            int r = idx % 192;
            int rem = idx / 192;
            int o = rem % O, d = rem / O;
            int c = r % 64, k = r / 64;
            pwp[idx] = wp[(((d*3 + k)*65) + (c+1))*O + o];
        }
    } else {
        if (idx < 192*O){
            int r = idx % 192;
            int o = idx / 192;
            int c = r % 64, k = r / 64;
            pw[idx] = w[((k*65) + (c+1))*O + o];
        }
    }
}

// -------------------- bias vectors: temb@bp + b0 ---------------------------
__global__ void k_bvec(const float* __restrict__ temb, const float* __restrict__ bp,
                       const float* __restrict__ b0, float* __restrict__ out, int O)
{
    int bt = blockIdx.x; int o = threadIdx.x;
    float acc = b0[o];
#pragma unroll
    for (int d = 0; d < 32; d++) acc += temb[bt*32+d]*bp[d*O+o];
    out[bt*O+o] = acc;
}

// -------------------- small STE projections --------------------------------
__global__ void k_small(const float* __restrict__ ne1, const float* __restrict__ ne2,
                        const float* __restrict__ Wq, const float* __restrict__ bq,
                        const float* __restrict__ Wk, const float* __restrict__ bk,
                        const float* __restrict__ Wv, const float* __restrict__ bv,
                        float* __restrict__ aq, float* __restrict__ ak, float* __restrict__ av)
{
    int b = blockIdx.x, y = blockIdx.y, h = threadIdx.x;
    const float *src, *W, *bias; float* out;
    if (y < 12)      { src = ne2 + (b*12+y)*32;  W = Wq; bias = bq; out = aq + (b*12+y)*64; }
    else if (y == 12){ src = ne1 + (b*12+11)*32; W = Wk; bias = bk; out = ak + b*64; }
    else             { src = ne1 + (b*12+11)*32; W = Wv; bias = bv; out = av + b*64; }
    float acc = bias[h];
#pragma unroll
    for (int d = 0; d < 32; d++) acc += src[d]*W[d*64+h];
    out[h] = acc;
}

// -------------------- X projections (xq, k, v, xw0) ------------------------
__global__ void __launch_bounds__(256) k_proj(
    const float* __restrict__ X,
    const float* __restrict__ Wq, const float* __restrict__ Wk,
    const float* __restrict__ Wv, const float* __restrict__ taw,
    const float* __restrict__ ak, const float* __restrict__ av,
    float* __restrict__ xq, float* __restrict__ kb,
    float* __restrict__ vb, float* __restrict__ xw0)
{
    __shared__ float Xs[64][64];
    __shared__ float Ws[64][64];
    const int tid  = threadIdx.x;
    const int mode = blockIdx.y;
    const int m0   = blockIdx.x*64;
    const int b    = m0 >> 9;
    const float* W = (mode==0)? Wq+2048 : (mode==1)? Wk+2048 : (mode==2)? Wv+2048 : taw;
    for (int li = tid; li < 1024; li += 256){
        int m = li>>4, kv = li&15;
        float4 v = *(const float4*)(X + (long)(m0+m)*64 + kv*4);
        Xs[kv*4+0][m]=v.x; Xs[kv*4+1][m]=v.y; Xs[kv*4+2][m]=v.z; Xs[kv*4+3][m]=v.w;
        *(float4*)&Ws[m][kv*4] = *(const float4*)(W + m*64 + kv*4);
    }
    __syncthreads();
    const int tx = tid&15, ty = tid>>4;
    float acc[4][4];
#pragma unroll
    for (int i=0;i<4;i++)
#pragma unroll
        for (int j=0;j<4;j++) acc[i][j]=0.f;
#pragma unroll
    for (int kk = 0; kk < 64; kk++){
        float a[4], bb[4];
        *(float4*)a  = *(const float4*)&Xs[kk][ty*4];
        *(float4*)bb = *(const float4*)&Ws[kk][tx*4];
#pragma unroll
        for (int i=0;i<4;i++)
#pragma unroll
            for (int j=0;j<4;j++) acc[i][j] += a[i]*bb[j];
    }
    float* outp = (mode==0)? xq : (mode==1)? kb : (mode==2)? vb : xw0;
#pragma unroll
    for (int i=0;i<4;i++){
        int m = m0 + ty*4 + i;
        float4 r;
        if (mode==1 || mode==2){
            const float* bias = ((mode==1)? ak:av) + b*64 + tx*4;
            r.x=fmaxf(acc[i][0]+bias[0],0.f); r.y=fmaxf(acc[i][1]+bias[1],0.f);
            r.z=fmaxf(acc[i][2]+bias[2],0.f); r.w=fmaxf(acc[i][3]+bias[3],0.f);
        } else {
            r.x=acc[i][0]; r.y=acc[i][1]; r.z=acc[i][2]; r.w=acc[i][3];
        }
        *(float4*)(outp + (long)m*64 + tx*4) = r;
    }
}

// -------------------- attention scores + softmax ---------------------------
__global__ void __launch_bounds__(256) k_attn(
    const float* __restrict__ aq, const float* __restrict__ xq,
    const float* __restrict__ kb, float* __restrict__ sm_out)
{
    __shared__ float aq_s[768];
    const int b = blockIdx.y;
    const int tid = threadIdx.x, lane = tid&31, w = tid>>5;
    for (int i = tid; i < 768; i += 256) aq_s[i] = aq[b*768 + i];
    __syncthreads();
    const int n0 = blockIdx.x*32 + w*4;
    for (int j = 0; j < 4; j++){
        int bn = b*512 + n0 + j;
        float xq0 = xq[bn*64 + lane],      xq1 = xq[bn*64 + 32 + lane];
        float k0  = kb[bn*64 + lane],      k1  = kb[bn*64 + 32 + lane];
        float sc0[12], sc1[12];
#pragma unroll
        for (int t = 0; t < 12; t++){
            float q0 = fmaxf(aq_s[t*64 + lane] + xq0, 0.f);
            float q1 = fmaxf(aq_s[t*64 + 32 + lane] + xq1, 0.f);
            float p0 = q0*k0, p1 = q1*k1;
#pragma unroll
            for (int o = 1; o < 8; o <<= 1){
                p0 += __shfl_xor_sync(0xffffffffu, p0, o);
                p1 += __shfl_xor_sync(0xffffffffu, p1, o);
            }
            sc0[t] = p0; sc1[t] = p1;
        }
        float m0 = -1e30f, m1 = -1e30f;
#pragma unroll
        for (int t = 0; t < 12; t++){ m0 = fmaxf(m0, sc0[t]); m1 = fmaxf(m1, sc1[t]); }
        float s0 = 0.f, s1 = 0.f;
#pragma unroll
        for (int t = 0; t < 12; t++){ sc0[t] = expf(sc0[t]-m0); s0 += sc0[t];
                                      sc1[t] = expf(sc1[t]-m1); s1 += sc1[t]; }
        float r0 = 1.f/s0, r1 = 1.f/s1;
        if ((lane & 7) == 0){
            int d = lane >> 3;
#pragma unroll
            for (int t = 0; t < 12; t++){
                sm_out[bn*96 + t*8 + d]     = sc0[t]*r0;
                sm_out[bn*96 + t*8 + 4 + d] = sc1[t]*r1;
            }
        }
    }
}

// -------------------- build de (fp16 into xg1 rows 0-63) -------------------
// grid (64,12): one block per (b,t), taw loaded ONCE per block.
__global__ void __launch_bounds__(256) k_debuild(
    const float* __restrict__ sm, const float* __restrict__ vb,
    const float* __restrict__ xw0, const float* __restrict__ taw,
    const float* __restrict__ tab, __half* __restrict__ dehf)
{
    __shared__ float taw1s[64][64];
    __shared__ float wvT[64][33];
    __shared__ float xw0s[64][33];
    const int b = blockIdx.x, t = blockIdx.y;
    const int tid = threadIdx.x;
    for (int i = tid; i < 4096; i += 256)
        taw1s[i>>6][i&63] = taw[4096 + i];
    const int bt = b*12 + t;
    const long baseH = (long)bt*98304;
    const int tx = tid & 15, ty = tid >> 4;

    for (int chunk = 0; chunk < 16; chunk++){
        const int n0 = chunk*32;
        __syncthreads();                 // previous chunk's compute done
        for (int idx = tid; idx < 2048; idx += 256){
            int nl = idx >> 6, i = idx & 63;
            int bn = b*512 + n0 + nl;
            float s = sm[bn*96 + t*8 + (i>>3)];
            wvT[i][nl]  = s * vb[bn*64 + i];
            xw0s[i][nl] = xw0[bn*64 + i];
        }
        __syncthreads();
        float acc[4][2] = {};
#pragma unroll
        for (int i = 0; i < 64; i++){
            float4 a = *(const float4*)&taw1s[i][ty*4];
            float b0 = wvT[i][tx*2], b1 = wvT[i][tx*2+1];
            acc[0][0]+=a.x*b0; acc[0][1]+=a.x*b1;
            acc[1][0]+=a.y*b0; acc[1][1]+=a.y*b1;
            acc[2][0]+=a.z*b0; acc[2][1]+=a.z*b1;
            acc[3][0]+=a.w*b0; acc[3][1]+=a.w*b1;
        }
#pragma unroll
        for (int oi = 0; oi < 4; oi++){
            int o = ty*4 + oi;
            float bias = tab[o];
            float vx = acc[oi][0] + xw0s[o][tx*2]   + bias;
            float vy = acc[oi][1] + xw0s[o][tx*2+1] + bias;
            uint32_t u = packh2(vx, vy);
            *(uint32_t*)&dehf[baseH + (long)o*512 + n0 + tx*2] = u;
        }
    }
}

// ===========================================================================
extern "C" void kernel_launch(void* const* d_in, const int* in_sizes, int n_in,
                              void* d_out, int out_size)
{
    const float* h_n  = (const float*)d_in[2];
    const float* ne1  = (const float*)d_in[3];
    const float* ne2  = (const float*)d_in[4];
    const float* E    = (const float*)d_in[5];
    const float* Wq   = (const float*)d_in[6];
    const float* bq   = (const float*)d_in[7];
    const float* Wk   = (const float*)d_in[8];
    const float* bk   = (const float*)d_in[9];
    const float* Wv   = (const float*)d_in[10];
    const float* bv   = (const float*)d_in[11];
    const float* taw  = (const float*)d_in[12];
    const float* tab  = (const float*)d_in[13];
    const float* gwp  = (const float*)d_in[14];
    const float* gw   = (const float*)d_in[15];
    const float* gbp  = (const float*)d_in[16];
    const float* gb   = (const float*)d_in[17];
    const float* uwp  = (const float*)d_in[18];
    const float* uw   = (const float*)d_in[19];
    const float* ubp  = (const float*)d_in[20];
    const float* ub   = (const float*)d_in[21];
    const float* outw = (const float*)d_in[22];
    const float* outb = (const float*)d_in[23];
    float* out = (float*)d_out;

    float *Arm, *kb2, *vb2, *xq, *xw0, *aq, *ak, *av, *sm;
    float *b1, *b2, *wp1, *w1b, *wp2, *w2b, *rg;
    __half *Ahf, *S2hf, *xg1, *xg2, *W1hf, *W2hf;
    cudaGetSymbolAddress((void**)&Arm,  g_Arm);
    cudaGetSymbolAddress((void**)&Ahf,  g_Ahf);
    cudaGetSymbolAddress((void**)&S2hf, g_S2hf);
    cudaGetSymbolAddress((void**)&kb2,  g_kb);
    cudaGetSymbolAddress((void**)&vb2,  g_vb);
    cudaGetSymbolAddress((void**)&xq,   g_xq);
    cudaGetSymbolAddress((void**)&xw0,  g_xw0);
    cudaGetSymbolAddress((void**)&aq,   g_aq);
    cudaGetSymbolAddress((void**)&ak,   g_ak);
    cudaGetSymbolAddress((void**)&av,   g_av);
    cudaGetSymbolAddress((void**)&sm,   g_sm);
    cudaGetSymbolAddress((void**)&xg1,  g_xg1);
    cudaGetSymbolAddress((void**)&xg2,  g_xg2);
    cudaGetSymbolAddress((void**)&W1hf, g_W1hf);
    cudaGetSymbolAddress((void**)&W2hf, g_W2hf);
    cudaGetSymbolAddress((void**)&b1,   g_b1);
    cudaGetSymbolAddress((void**)&b2,   g_b2);
    cudaGetSymbolAddress((void**)&wp1,  g_wp1);
    cudaGetSymbolAddress((void**)&w1b,  g_w1b);
    cudaGetSymbolAddress((void**)&wp2,  g_wp2);
    cudaGetSymbolAddress((void**)&w2b,  g_w2b);
    cudaGetSymbolAddress((void**)&rg,   g_rg);

    const int SUPP2_SMEM = 6*128*20*4;                       // 61440
    const int CTR1_SMEM  = 128*200*2 + 2*32*136*2;           // 68608
    const int CTR2_SMEM  = 64*132*4*2 + 2*128*4;             // 68608
    cudaFuncSetAttribute(k_supp2_hmma, cudaFuncAttributeMaxDynamicSharedMemorySize, SUPP2_SMEM);
    cudaFuncSetAttribute(k_ctr1_fused, cudaFuncAttributeMaxDynamicSharedMemorySize, CTR1_SMEM);
    cudaFuncSetAttribute(k_ctr2_fused, cudaFuncAttributeMaxDynamicSharedMemorySize, CTR2_SMEM);

    // ---- adjacency & supports ----
    k_A<<<512, 512>>>(E, Arm, Ahf);
    gemm_rr_k<64,64,16,4,4,256,2><<<dim3(8,8,1), 256>>>(      // S2hf = 2*A@A (fp16 direct)
        Arm, 0, Arm, 0, S2hf, 0, 512, 512, 512, 512, nullptr, 2.f);
    k_fixdiag_h<<<1, 512>>>(S2hf);

    // ---- pack GCN weights ([d][o][k]), build per-bt W' fp16 + bias ----
    k_pack<<<dim3(3072,2), 256>>>(gwp, gw, wp1, w1b, 128);
    k_pack<<<dim3(1536,2), 256>>>(uwp, uw, wp2, w2b, 64);
    k_bvec<<<768, 128>>>(ne2, gbp, gb, b1, 128);
    k_bvec<<<768, 64 >>>(ne2, ubp, ub, b2, 64);
    gemm_rr_k<64,64,16,4,4,256,2><<<dim3(384,12,1), 256>>>(   // W1' fp16 [bt][o][k]
        ne2, 0, wp1, 0, W1hf, 0, 32, 24576, 24576, 32, w1b, 1.f);
    gemm_rr_k<64,64,16,4,4,256,2><<<dim3(192,12,1), 256>>>(   // W2' fp16
        ne2, 0, wp2, 0, W2hf, 0, 32, 12288, 12288, 32, w2b, 1.f);

    // ---- attention path ----
    k_small<<<dim3(64,14), 64>>>(ne1, ne2, Wq, bq, Wk, bk, Wv, bv, aq, ak, av);
    k_proj<<<dim3(512,4), 256>>>(h_n, Wq, Wk, Wv, taw, ak, av, xq, kb2, vb2, xw0);
    k_attn<<<dim3(16,64), 256>>>(aq, xq, kb2, sm);
    k_debuild<<<dim3(64,12), 256>>>(sm, vb2, xw0, taw, tab, xg1);

    // ---- GCN1: supports + fused contraction/gate ----
    k_supp2_hmma<<<dim3(4,384), 256, SUPP2_SMEM>>>(xg1, Ahf, S2hf,
                                                   xg1 + 64*512, xg1 + 128*512);
    k_ctr1_fused<<<dim3(4,768), 256, CTR1_SMEM>>>(xg1, W1hf, b1, xg2, rg);

    // ---- GCN2: supports + fused contraction/blend/head ----
    k_supp2_hmma<<<dim3(4,384), 256, SUPP2_SMEM>>>(xg2, Ahf, S2hf,
                                                   xg2 + 64*512, xg2 + 128*512);
    k_ctr2_fused<<<dim3(4,768), 256, CTR2_SMEM>>>(xg2, W2hf, b2, xg1, rg,
                                                  outw, outb, out);
}

// round 17
// speedup vs baseline: 4.3020x; 1.0927x over previous
#include <cuda_runtime.h>
#include <cuda_fp16.h>
#include <math.h>
#include <stdint.h>

// Problem constants: B=64, T=12, N=512, H=64, TD=32, ED=16, CHEB_K=3, D_HEADS=8
// BT = 768. Effective GCN channels = 64 (channel 0 is identically zero).

// -------------------- static device scratch --------------------------------
static __device__ float g_Arm[512*512];            // A row-major (f32, for S2 build)
static __device__ __half g_Ahf [512*512];          // fp16 support B operands
static __device__ __half g_S2hf[512*512];
static __device__ float g_kb [64*512*64];
static __device__ float g_vb [64*512*64];
static __device__ float g_xq [64*512*64];
static __device__ float g_xw0[64*512*64];
static __device__ float g_sm [64*512*12*8];
static __device__ __half g_xg1[768*192*512];       // fp16 [bt][j][n] j:0-63 de,64-127 A@,128-191 S2@
static __device__ __half g_xg2[768*192*512];       // same for cand
static __device__ __half g_W1hf[768*128*192];      // W' [bt][o][k] fp16
static __device__ __half g_W2hf[768*64*192];
static __device__ float g_b1 [768*128];
static __device__ float g_b2 [768*64];
static __device__ float g_wp1[32*128*192];         // packed [d][o][k]
static __device__ float g_w1b[128*192];
static __device__ float g_wp2[32*64*192];
static __device__ float g_w2b[64*192];
static __device__ __half g_rgs[768*64*512];        // sigmoid(rg) fp16, channel-major

// -------------------- helpers ----------------------------------------------
__device__ __forceinline__ uint32_t smem_u32p(const void* p){
    uint32_t a;
    asm("{ .reg .u64 t; cvta.to.shared.u64 t, %1; cvt.u32.u64 %0, t; }" : "=r"(a) : "l"(p));
    return a;
}
__device__ __forceinline__ void cp16(void* dst, const void* src){
    uint32_t d = smem_u32p(dst);
    asm volatile("cp.async.cg.shared.global [%0], [%1], 16;" :: "r"(d), "l"(src));
}
__device__ __forceinline__ void mma_f16(float* c, const uint32_t* a, const uint32_t* b){
    asm volatile(
        "mma.sync.aligned.m16n8k16.row.col.f32.f16.f16.f32 "
        "{%0,%1,%2,%3}, {%4,%5,%6,%7}, {%8,%9}, {%0,%1,%2,%3};"
        : "+f"(c[0]),"+f"(c[1]),"+f"(c[2]),"+f"(c[3])
        : "r"(a[0]),"r"(a[1]),"r"(a[2]),"r"(a[3]), "r"(b[0]),"r"(b[1]));
}
__device__ __forceinline__ void ldmx4t(uint32_t* r, uint32_t addr){
    asm volatile("ldmatrix.sync.aligned.m8n8.x4.trans.shared.b16 {%0,%1,%2,%3}, [%4];"
        : "=r"(r[0]),"=r"(r[1]),"=r"(r[2]),"=r"(r[3]) : "r"(addr));
}
__device__ __forceinline__ uint32_t packh2(float x, float y){
    __half2 h = __floats2half2_rn(x, y);
    return *(uint32_t*)&h;
}
// stage a [64 x 128] fp16 tile (row stride 512) into f32 smem [64][132]
__device__ __forceinline__ void stage_h2f(const __half* __restrict__ src,
                                          float* __restrict__ dst, int tid){
    for (int idx = tid; idx < 2048; idx += 256){
        int cc = idx >> 5, j = idx & 31;
        uint2 u = *(const uint2*)(src + (size_t)cc*512 + j*4);
        __half2 h0 = *(__half2*)&u.x, h1 = *(__half2*)&u.y;
        float2 f0 = __half22float2(h0), f1 = __half22float2(h1);
        float* d = dst + cc*132 + j*4;
        d[0] = f0.x; d[1] = f0.y; d[2] = f1.x; d[3] = f1.y;
    }
}

// -------------------- fused dual support GEMM (fp16 HMMA, K-chunk 64) ------
__global__ void __launch_bounds__(256) k_supp2_hmma(
    const __half* __restrict__ xhf,
    const __half* __restrict__ B1hf,
    const __half* __restrict__ B2hf,
    __half* __restrict__ out1,
    __half* __restrict__ out2)
{
    constexpr int LD = 36;              // 32 data uints (64 halves) + 4 pad
    extern __shared__ uint32_t sh[];
    uint32_t* As  = sh;                 // [2][128*36]
    uint32_t* B1s = sh + 2*128*LD;
    uint32_t* B2s = sh + 4*128*LD;
    const int tid = threadIdx.x, wid = tid>>5, lane = tid&31;
    const int g = lane>>2, tg = lane&3;
    const int p = blockIdx.y, n0 = blockIdx.x*128;
    const int wm = wid & 1, wn = wid >> 1;
    const int mbase = wm*64, nbase = wn*32;

    float c[2][4][4][4];
#pragma unroll
    for (int s=0;s<2;s++)
#pragma unroll
        for (int i=0;i<4;i++)
#pragma unroll
            for (int j=0;j<4;j++)
#pragma unroll
                for (int q=0;q<4;q++) c[s][i][j][q]=0.f;

    auto load = [&](int ch, int sel){
        uint32_t* a  = As  + sel*128*LD;
        uint32_t* b1 = B1s + sel*128*LD;
        uint32_t* b2 = B2s + sel*128*LD;
        const int k0 = ch*64;           // halves
#pragma unroll
        for (int it = 0; it < 4; it++){
            int lin = tid + it*256;
            int r = lin >> 3, q = lin & 7;
            cp16(a  + r*LD + q*4,
                 xhf + (size_t)(2*p + (r>>6))*98304 + (size_t)(r&63)*512 + k0 + q*8);
            cp16(b1 + r*LD + q*4, B1hf + (size_t)(n0 + r)*512 + k0 + q*8);
            cp16(b2 + r*LD + q*4, B2hf + (size_t)(n0 + r)*512 + k0 + q*8);
        }
        asm volatile("cp.async.commit_group;" ::: "memory");
    };

    load(0, 0);
    for (int i = 0; i < 8; i++){
        const int cur = i & 1;
        if (i + 1 < 8){
            load(i+1, cur^1);
            asm volatile("cp.async.wait_group 1;" ::: "memory");
        } else {
            asm volatile("cp.async.wait_group 0;" ::: "memory");
        }
        __syncthreads();
        const uint32_t* a  = As  + cur*128*LD;
        const uint32_t* b1 = B1s + cur*128*LD;
        const uint32_t* b2 = B2s + cur*128*LD;
#pragma unroll
        for (int ks = 0; ks < 4; ks++){     // 4 x k16 per 64-half chunk
            uint32_t af[4][4], bf1[4][2], bf2[4][2];
#pragma unroll
            for (int mt = 0; mt < 4; mt++){
                int row = mbase + mt*16 + g;
                af[mt][0] = a[ row   *LD + ks*8 + tg    ];
                af[mt][1] = a[(row+8)*LD + ks*8 + tg    ];
                af[mt][2] = a[ row   *LD + ks*8 + tg + 4];
                af[mt][3] = a[(row+8)*LD + ks*8 + tg + 4];
            }
#pragma unroll
            for (int nt = 0; nt < 4; nt++){
                int nr = nbase + nt*8 + g;
                bf1[nt][0] = b1[nr*LD + ks*8 + tg    ];
                bf1[nt][1] = b1[nr*LD + ks*8 + tg + 4];
                bf2[nt][0] = b2[nr*LD + ks*8 + tg    ];
                bf2[nt][1] = b2[nr*LD + ks*8 + tg + 4];
            }
#pragma unroll
            for (int mt = 0; mt < 4; mt++)
#pragma unroll
                for (int nt = 0; nt < 4; nt++){
                    mma_f16(c[0][mt][nt], af[mt], bf1[nt]);
                    mma_f16(c[1][mt][nt], af[mt], bf2[nt]);
                }
        }
        __syncthreads();
    }

#pragma unroll
    for (int s = 0; s < 2; s++){
        __half* outp = s ? out2 : out1;
#pragma unroll
        for (int mt = 0; mt < 4; mt++){
            int r0 = mbase + mt*16 + g;
#pragma unroll
            for (int half = 0; half < 2; half++){
                int r = r0 + half*8;
                __half* orow = outp + (size_t)(2*p + (r>>6))*98304
                             + (size_t)(r&63)*512 + n0 + nbase;
#pragma unroll
                for (int nt = 0; nt < 4; nt++){
                    uint32_t u = packh2(c[s][mt][nt][half*2+0], c[s][mt][nt][half*2+1]);
                    *(uint32_t*)(orow + nt*8 + tg*2) = u;
                }
            }
        }
    }
}

// -------------------- ctr1: contraction + fused gate -----------------------
// o<64  : cand = sigmoid(zr)*de -> xg2 fp16 ; o>=64 : sigmoid(rg) -> rgs fp16
__global__ void __launch_bounds__(256) k_ctr1_fused(
    const __half* __restrict__ xhf,     // xg1
    const __half* __restrict__ Whf,     // [768][128][192]
    const float* __restrict__ bias,     // [768][128]
    __half* __restrict__ cand,          // xg2 base
    __half* __restrict__ rgs)           // [768][64][512]
{
    constexpr int BN = 128, MT = 4, NTT = 4, WARPS_M = 2;
    constexpr int LDA = 136, LDB = 200, NC = 6;
    extern __shared__ __half shh[];
    __half* Bs = shh;
    __half* As = shh + BN*LDB;
    const int tid = threadIdx.x, wid = tid>>5, lane = tid&31;
    const int g = lane>>2, tg = lane&3;
    const int bt = blockIdx.y, m0 = blockIdx.x*128;
    const int wm = wid % WARPS_M, wn = wid / WARPS_M;
    const int mbase = wm*(MT*16), nbase = wn*(NTT*8);
    const __half* Ab = xhf + (size_t)bt*98304 + m0;
    const __half* Bb = Whf + (size_t)bt*BN*192;
    const uint32_t aBase = smem_u32p(shh) + (uint32_t)(BN*LDB*2);

    float c[MT][NTT][4];
#pragma unroll
    for (int i=0;i<MT;i++)
#pragma unroll
        for (int j=0;j<NTT;j++)
#pragma unroll
            for (int q=0;q<4;q++) c[i][j][q]=0.f;

    {
        const int nch = BN*24;
#pragma unroll
        for (int it = 0; it < nch/256; it++){
            int lin = tid + it*256;
            int o = lin / 24, q = lin % 24;
            cp16(Bs + o*LDB + q*8, Bb + (size_t)o*192 + q*8);
        }
        asm volatile("cp.async.commit_group;" ::: "memory");
    }
    auto loadA = [&](int ch, int sel){
        __half* a = As + sel*32*LDA;
        const int k0 = ch*32;
#pragma unroll
        for (int it = 0; it < 2; it++){
            int lin = tid + it*256;
            int kr = lin >> 4, q = lin & 15;
            cp16(a + kr*LDA + q*8, Ab + (size_t)(k0+kr)*512 + q*8);
        }
        asm volatile("cp.async.commit_group;" ::: "memory");
    };

    loadA(0, 0);
    for (int i = 0; i < NC; i++){
        const int cur = i & 1;
        if (i + 1 < NC){
            loadA(i+1, cur^1);
            asm volatile("cp.async.wait_group 1;" ::: "memory");
        } else {
            asm volatile("cp.async.wait_group 0;" ::: "memory");
        }
        __syncthreads();
        const uint32_t aBuf = aBase + (uint32_t)(cur*32*LDA*2);
        const int kabs = i*32;
#pragma unroll
        for (int ks = 0; ks < 2; ks++){
            uint32_t af[MT][4], bf[NTT][2];
            const int krow = ks*16 + ((lane>>4)&1)*8 + (lane&7);
            const int cof  = ((lane>>3)&1)*8;
#pragma unroll
            for (int mt = 0; mt < MT; mt++){
                uint32_t addr = aBuf + (uint32_t)((krow*LDA + mbase + mt*16 + cof)*2);
                ldmx4t(af[mt], addr);
            }
#pragma unroll
            for (int nt = 0; nt < NTT; nt++){
                const __half* brow = Bs + (size_t)(nbase + nt*8 + g)*LDB + kabs + ks*16;
                bf[nt][0] = *(const uint32_t*)(brow + tg*2);
                bf[nt][1] = *(const uint32_t*)(brow + 8 + tg*2);
            }
#pragma unroll
            for (int mt = 0; mt < MT; mt++)
#pragma unroll
                for (int nt = 0; nt < NTT; nt++)
                    mma_f16(c[mt][nt], af[mt], bf[nt]);
        }
        __syncthreads();
    }

    // ---- stage de tile [64][132] from xg1 rows 0-63 (fp16) ----
    float* de_s = (float*)shh;
    stage_h2f(Ab, de_s, tid);
    __syncthreads();

#pragma unroll
    for (int mt = 0; mt < MT; mt++){
#pragma unroll
        for (int half = 0; half < 2; half++){
            int nl = mbase + mt*16 + half*8 + g;
            int n_ = m0 + nl;
#pragma unroll
            for (int nt = 0; nt < NTT; nt++){
                int o = nbase + nt*8 + tg*2;
                float v0 = c[mt][nt][half*2+0] + bias[bt*128 + o];
                float v1 = c[mt][nt][half*2+1] + bias[bt*128 + o + 1];
                float z0 = 1.f/(1.f + expf(-v0));
                float z1 = 1.f/(1.f + expf(-v1));
                if (nbase < 64){
                    __half* xo = cand + (size_t)bt*98304 + (size_t)o*512 + n_;
                    xo[0]   = __float2half(z0 * de_s[o*132 + nl]);
                    xo[512] = __float2half(z1 * de_s[(o+1)*132 + nl]);
                } else {
                    __half* ro = rgs + (size_t)bt*32768 + (size_t)(o-64)*512 + n_;
                    ro[0]   = __float2half(z0);
                    ro[512] = __float2half(z1);
                }
            }
        }
    }
}

// -------------------- ctr2: contraction + fused final blend + head ---------
__global__ void __launch_bounds__(256) k_ctr2_fused(
    const __half* __restrict__ xhf,     // xg2
    const __half* __restrict__ Whf,     // [768][64][192]
    const float* __restrict__ bias,     // [768][64]
    const __half* __restrict__ dehf,    // xg1 base
    const __half* __restrict__ rgs,     // [768][64][512] sigmoid(rg) fp16
    const float* __restrict__ out_w,    // [12][64]
    const float* __restrict__ out_b,    // [12]
    float* __restrict__ outp)           // [768][512]
{
    constexpr int BN = 64, MT = 2, NTT = 4, WARPS_M = 4;
    constexpr int LDA = 136, LDB = 200, NC = 6;
    extern __shared__ __half shh[];
    __half* Bs = shh;
    __half* As = shh + BN*LDB;
    const int tid = threadIdx.x, wid = tid>>5, lane = tid&31;
    const int g = lane>>2, tg = lane&3;
    const int bt = blockIdx.y, m0 = blockIdx.x*128;
    const int wm = wid % WARPS_M, wn = wid / WARPS_M;
    const int mbase = wm*(MT*16), nbase = wn*(NTT*8);
    const __half* Ab = xhf + (size_t)bt*98304 + m0;
    const __half* Bb = Whf + (size_t)bt*BN*192;
    const uint32_t aBase = smem_u32p(shh) + (uint32_t)(BN*LDB*2);

    float c[MT][NTT][4];
#pragma unroll
    for (int i=0;i<MT;i++)
#pragma unroll
        for (int j=0;j<NTT;j++)
#pragma unroll
            for (int q=0;q<4;q++) c[i][j][q]=0.f;

    {
        const int nch = BN*24;
#pragma unroll
        for (int it = 0; it < nch/256; it++){
            int lin = tid + it*256;
            int o = lin / 24, q = lin % 24;
            cp16(Bs + o*LDB + q*8, Bb + (size_t)o*192 + q*8);
        }
        asm volatile("cp.async.commit_group;" ::: "memory");
    }
    auto loadA = [&](int ch, int sel){
        __half* a = As + sel*32*LDA;
        const int k0 = ch*32;
#pragma unroll
        for (int it = 0; it < 2; it++){
            int lin = tid + it*256;
            int kr = lin >> 4, q = lin & 15;
            cp16(a + kr*LDA + q*8, Ab + (size_t)(k0+kr)*512 + q*8);
        }
        asm volatile("cp.async.commit_group;" ::: "memory");
    };

    loadA(0, 0);
    for (int i = 0; i < NC; i++){
        const int cur = i & 1;
        if (i + 1 < NC){
            loadA(i+1, cur^1);
            asm volatile("cp.async.wait_group 1;" ::: "memory");
        } else {
            asm volatile("cp.async.wait_group 0;" ::: "memory");
        }
        __syncthreads();
        const uint32_t aBuf = aBase + (uint32_t)(cur*32*LDA*2);
        const int kabs = i*32;
#pragma unroll
        for (int ks = 0; ks < 2; ks++){
            uint32_t af[MT][4], bf[NTT][2];
            const int krow = ks*16 + ((lane>>4)&1)*8 + (lane&7);
            const int cof  = ((lane>>3)&1)*8;
#pragma unroll
            for (int mt = 0; mt < MT; mt++){
                uint32_t addr = aBuf + (uint32_t)((krow*LDA + mbase + mt*16 + cof)*2);
                ldmx4t(af[mt], addr);
            }
#pragma unroll
            for (int nt = 0; nt < NTT; nt++){
                const __half* brow = Bs + (size_t)(nbase + nt*8 + g)*LDB + kabs + ks*16;
                bf[nt][0] = *(const uint32_t*)(brow + tg*2);
                bf[nt][1] = *(const uint32_t*)(brow + 8 + tg*2);
            }
#pragma unroll
            for (int mt = 0; mt < MT; mt++)
#pragma unroll
                for (int nt = 0; nt < NTT; nt++)
                    mma_f16(c[mt][nt], af[mt], bf[nt]);
        }
        __syncthreads();
    }

    // ---- stage de + sigmoid(rg) tiles, fused blend + head -----------------
    float* de_s = (float*)shh;
    float* rg_s = de_s + 64*132;
    float* red  = rg_s + 64*132;        // [2][128]
    stage_h2f(dehf + (size_t)bt*98304 + m0, de_s, tid);
    stage_h2f(rgs  + (size_t)bt*32768 + m0, rg_s, tid);
    __syncthreads();
    const int tt = bt % 12;
    float bo[NTT][2], wv[NTT][2];
#pragma unroll
    for (int nt = 0; nt < NTT; nt++){
        int o = nbase + nt*8 + tg*2;
        bo[nt][0] = bias[bt*64 + o];   bo[nt][1] = bias[bt*64 + o + 1];
        wv[nt][0] = out_w[tt*64 + o];  wv[nt][1] = out_w[tt*64 + o + 1];
    }
#pragma unroll
    for (int mt = 0; mt < MT; mt++){
#pragma unroll
        for (int half = 0; half < 2; half++){
            int nl = mbase + mt*16 + half*8 + g;
            float p = 0.f;
#pragma unroll
            for (int nt = 0; nt < NTT; nt++){
                int o = nbase + nt*8 + tg*2;
#pragma unroll
                for (int q = 0; q < 2; q++){
                    float v   = c[mt][nt][half*2+q] + bo[nt][q];
                    float hcv = tanhf(v);
                    float r   = rg_s[(o+q)*132 + nl];
                    float st  = r*de_s[(o+q)*132 + nl] + (1.f - r)*hcv;
                    p += st * wv[nt][q];
                }
            }
            p += __shfl_xor_sync(0xffffffffu, p, 1);
            p += __shfl_xor_sync(0xffffffffu, p, 2);
            if (tg == 0) red[wn*128 + nl] = p;
        }
    }
    __syncthreads();
    if (tid < 128)
        outp[(size_t)bt*512 + m0 + tid] = red[tid] + red[128 + tid] + out_b[tt];
}

// -------------------- adjacency: A row-major + fp16 ------------------------
__global__ void k_A(const float* __restrict__ E, float* __restrict__ Arm,
                    __half* __restrict__ Ahf)
{
    __shared__ float Es[512*16];
    __shared__ float red[512];
    const int tid = threadIdx.x;
    const int n   = blockIdx.x;
    for (int i = tid; i < 512*16; i += 512) Es[i] = E[i];
    __syncthreads();
    float acc = 0.f;
#pragma unroll
    for (int d = 0; d < 16; d++) acc += Es[n*16+d]*Es[tid*16+d];
    acc = fmaxf(acc, 0.f);
    red[tid] = acc; __syncthreads();
    for (int s = 256; s > 0; s >>= 1){ if (tid < s) red[tid] = fmaxf(red[tid], red[tid+s]); __syncthreads(); }
    float mx = red[0]; __syncthreads();
    float e = expf(acc - mx);
    red[tid] = e; __syncthreads();
    for (int s = 256; s > 0; s >>= 1){ if (tid < s) red[tid] += red[tid+s]; __syncthreads(); }
    float v = e / red[0];
    Arm[n*512 + tid] = v;
    Ahf[n*512 + tid] = __float2half(v);
}

// -------------------- generic SGEMM, A row-major ---------------------------
// OUTMODE: 0 = f32, 2 = fp16.  DIAG: subtract 1.0 on the global diagonal.
template<int BM,int BN,int BK,int TM,int TN,int NT,int OUTMODE,int DIAG>
__global__ void __launch_bounds__(NT) gemm_rr_k(
    const float* __restrict__ Abase, long aStr,
    const float* __restrict__ Bbase, long bStr,
    void* __restrict__ Cbase, long cStr,
    int lda, int ldb, int ldc, int K,
    const float* __restrict__ colBias, float alpha)
{
    __shared__ float As[BK][BM];
    __shared__ float Bs[BK][BN];
    const int tid = threadIdx.x;
    const int bz  = blockIdx.z;
    const int m0  = blockIdx.y*BM;
    const int n0  = blockIdx.x*BN;
    const float* A = Abase + (long)bz*aStr + (long)m0*lda;
    const float* B = Bbase + (long)bz*bStr + n0;
    const int tx = tid % (BN/TN);
    const int ty = tid / (BN/TN);
    float acc[TM][TN];
#pragma unroll
    for (int i=0;i<TM;i++)
#pragma unroll
        for (int j=0;j<TN;j++) acc[i][j]=0.f;

    for (int k0 = 0; k0 < K; k0 += BK){
        for (int li = tid; li < BM*BK/4; li += NT){
            int m  = li/(BK/4), kv = li%(BK/4);
            float4 v = *(const float4*)(A + (long)m*lda + k0 + kv*4);
            As[kv*4+0][m]=v.x; As[kv*4+1][m]=v.y; As[kv*4+2][m]=v.z; As[kv*4+3][m]=v.w;
        }
        for (int li = tid; li < BN*BK/4; li += NT){
            int k  = li/(BN/4), nv = li%(BN/4);
            *(float4*)&Bs[k][nv*4] = *(const float4*)(B + (long)(k0+k)*ldb + nv*4);
        }
        __syncthreads();
#pragma unroll
        for (int kk = 0; kk < BK; kk++){
            float a[TM], bb[TN];
#pragma unroll
            for (int i=0;i<TM;i+=4) *(float4*)&a[i]  = *(const float4*)&As[kk][ty*TM+i];
#pragma unroll
            for (int j=0;j<TN;j+=4) *(float4*)&bb[j] = *(const float4*)&Bs[kk][tx*TN+j];
#pragma unroll
            for (int i=0;i<TM;i++)
#pragma unroll
                for (int j=0;j<TN;j++) acc[i][j] += a[i]*bb[j];
        }
        __syncthreads();
    }
#pragma unroll
    for (int i=0;i<TM;i++){
        int row = m0 + ty*TM + i;
#pragma unroll
        for (int j=0;j<TN;j+=4){
            int col = n0 + tx*TN + j;
            float4 v;
            v.x=acc[i][j+0]*alpha; v.y=acc[i][j+1]*alpha;
            v.z=acc[i][j+2]*alpha; v.w=acc[i][j+3]*alpha;
            if (DIAG){
                if (col   == row) v.x -= 1.f;
                if (col+1 == row) v.y -= 1.f;
                if (col+2 == row) v.z -= 1.f;
                if (col+3 == row) v.w -= 1.f;
            }
            if (colBias){
                const float* cb = colBias + col;
                v.x+=cb[0]; v.y+=cb[1]; v.z+=cb[2]; v.w+=cb[3];
            }
            long coff = (long)bz*cStr + (long)row*ldc + col;
            if (OUTMODE == 0){
                *(float4*)((float*)Cbase + coff) = v;
            } else {
                uint2 u;
                u.x = packh2(v.x, v.y);
                u.y = packh2(v.z, v.w);
                *(uint2*)((__half*)Cbase + coff) = u;
            }
        }
    }
}

// -------------------- pack gwp/uwp (drop channel 0, [d][o][k] layout) ------
__global__ void k_pack(const float* __restrict__ wp, const float* __restrict__ w,
                       float* __restrict__ pwp, float* __restrict__ pw, int O)
{
    int idx = blockIdx.x*blockDim.x + threadIdx.x;
    if (blockIdx.y == 0){
        if (idx < 32*192*O){
            int r = idx % 192;
            int rem = idx / 192;
            int o = rem % O, d = rem / O;
            int c = r % 64, k = r / 64;
            pwp[idx] = wp[(((d*3 + k)*65) + (c+1))*O + o];
        }
    } else {
        if (idx < 192*O){
            int r = idx % 192;
            int o = idx / 192;
            int c = r % 64, k = r / 64;
            pw[idx] = w[((k*65) + (c+1))*O + o];
        }
    }
}

// -------------------- bias vectors: temb@bp + b0 ---------------------------
__global__ void k_bvec(const float* __restrict__ temb, const float* __restrict__ bp,
                       const float* __restrict__ b0, float* __restrict__ out, int O)
{
    int bt = blockIdx.x; int o = threadIdx.x;
    float acc = b0[o];
#pragma unroll
    for (int d = 0; d < 32; d++) acc += temb[bt*32+d]*bp[d*O+o];
    out[bt*O+o] = acc;
}

// -------------------- X projections (k/v bias computed inline) -------------
__global__ void __launch_bounds__(256) k_proj(
    const float* __restrict__ X,   const float* __restrict__ ne1,
    const float* __restrict__ Wq,  const float* __restrict__ Wk,
    const float* __restrict__ Wv,  const float* __restrict__ taw,
    const float* __restrict__ bk,  const float* __restrict__ bv,
    float* __restrict__ xq, float* __restrict__ kb,
    float* __restrict__ vb, float* __restrict__ xw0)
{
    __shared__ float Xs[64][64];
    __shared__ float Ws[64][64];
    __shared__ float bias_s[64];
    const int tid  = threadIdx.x;
    const int mode = blockIdx.y;
    const int m0   = blockIdx.x*64;
    const int b    = m0 >> 9;
    const float* W = (mode==0)? Wq+2048 : (mode==1)? Wk+2048 : (mode==2)? Wv+2048 : taw;
    for (int li = tid; li < 1024; li += 256){
        int m = li>>4, kv = li&15;
        float4 v = *(const float4*)(X + (long)(m0+m)*64 + kv*4);
        Xs[kv*4+0][m]=v.x; Xs[kv*4+1][m]=v.y; Xs[kv*4+2][m]=v.z; Xs[kv*4+3][m]=v.w;
        *(float4*)&Ws[m][kv*4] = *(const float4*)(W + m*64 + kv*4);
    }
    if ((mode == 1 || mode == 2) && tid < 64){
        const float* src = ne1 + (b*12+11)*32;
        const float* Wx  = (mode==1)? Wk : Wv;
        float acc = (mode==1)? bk[tid] : bv[tid];
#pragma unroll
        for (int d = 0; d < 32; d++) acc += src[d]*Wx[d*64+tid];
        bias_s[tid] = acc;
    }
    __syncthreads();
    const int tx = tid&15, ty = tid>>4;
    float acc[4][4];
#pragma unroll
    for (int i=0;i<4;i++)
#pragma unroll
        for (int j=0;j<4;j++) acc[i][j]=0.f;
#pragma unroll
    for (int kk = 0; kk < 64; kk++){
        float a[4], bb[4];
        *(float4*)a  = *(const float4*)&Xs[kk][ty*4];
        *(float4*)bb = *(const float4*)&Ws[kk][tx*4];
#pragma unroll
        for (int i=0;i<4;i++)
#pragma unroll
            for (int j=0;j<4;j++) acc[i][j] += a[i]*bb[j];
    }
    float* outp = (mode==0)? xq : (mode==1)? kb : (mode==2)? vb : xw0;
#pragma unroll
    for (int i=0;i<4;i++){
        int m = m0 + ty*4 + i;
        float4 r;
        if (mode==1 || mode==2){
            const float* bias = bias_s + tx*4;
            r.x=fmaxf(acc[i][0]+bias[0],0.f); r.y=fmaxf(acc[i][1]+bias[1],0.f);
            r.z=fmaxf(acc[i][2]+bias[2],0.f); r.w=fmaxf(acc[i][3]+bias[3],0.f);
        } else {
            r.x=acc[i][0]; r.y=acc[i][1]; r.z=acc[i][2]; r.w=acc[i][3];
        }
        *(float4*)(outp + (long)m*64 + tx*4) = r;
    }
}

// -------------------- attention scores + softmax (aq computed inline) ------
__global__ void __launch_bounds__(256) k_attn(
    const float* __restrict__ ne2, const float* __restrict__ Wq,
    const float* __restrict__ bq,  const float* __restrict__ xq,
    const float* __restrict__ kb,  float* __restrict__ sm_out)
{
    __shared__ float aq_s[768];
    const int b = blockIdx.y;
    const int tid = threadIdx.x, lane = tid&31, w = tid>>5;
    for (int i = tid; i < 768; i += 256){
        int t = i >> 6, h = i & 63;
        const float* src = ne2 + (b*12+t)*32;
        float acc = bq[h];
#pragma unroll
        for (int d = 0; d < 32; d++) acc += src[d]*Wq[d*64+h];
        aq_s[i] = acc;
    }
    __syncthreads();
    const int n0 = blockIdx.x*32 + w*4;
    for (int j = 0; j < 4; j++){
        int bn = b*512 + n0 + j;
        float xq0 = xq[bn*64 + lane],      xq1 = xq[bn*64 + 32 + lane];
        float k0  = kb[bn*64 + lane],      k1  = kb[bn*64 + 32 + lane];
        float sc0[12], sc1[12];
#pragma unroll
        for (int t = 0; t < 12; t++){
            float q0 = fmaxf(aq_s[t*64 + lane] + xq0, 0.f);
            float q1 = fmaxf(aq_s[t*64 + 32 + lane] + xq1, 0.f);
            float p0 = q0*k0, p1 = q1*k1;
#pragma unroll
            for (int o = 1; o < 8; o <<= 1){
                p0 += __shfl_xor_sync(0xffffffffu, p0, o);
                p1 += __shfl_xor_sync(0xffffffffu, p1, o);
            }
            sc0[t] = p0; sc1[t] = p1;
        }
        float m0 = -1e30f, m1 = -1e30f;
#pragma unroll
        for (int t = 0; t < 12; t++){ m0 = fmaxf(m0, sc0[t]); m1 = fmaxf(m1, sc1[t]); }
        float s0 = 0.f, s1 = 0.f;
#pragma unroll
        for (int t = 0; t < 12; t++){ sc0[t] = expf(sc0[t]-m0); s0 += sc0[t];
                                      sc1[t] = expf(sc1[t]-m1); s1 += sc1[t]; }
        float r0 = 1.f/s0, r1 = 1.f/s1;
        if ((lane & 7) == 0){
            int d = lane >> 3;
#pragma unroll
            for (int t = 0; t < 12; t++){
                sm_out[bn*96 + t*8 + d]     = sc0[t]*r0;
                sm_out[bn*96 + t*8 + 4 + d] = sc1[t]*r1;
            }
        }
    }
}

// -------------------- build de (fp16 into xg1 rows 0-63) -------------------
__global__ void __launch_bounds__(256) k_debuild(
    const float* __restrict__ sm, const float* __restrict__ vb,
    const float* __restrict__ xw0, const float* __restrict__ taw,
    const float* __restrict__ tab, __half* __restrict__ dehf)
{
    __shared__ float taw1s[64][64];
    __shared__ float wvT[64][33];
    __shared__ float xw0s[64][33];
    const int b = blockIdx.x, t = blockIdx.y;
    const int tid = threadIdx.x;
    for (int i = tid; i < 4096; i += 256)
        taw1s[i>>6][i&63] = taw[4096 + i];
    const int bt = b*12 + t;
    const long baseH = (long)bt*98304;
    const int tx = tid & 15, ty = tid >> 4;

    for (int chunk = 0; chunk < 16; chunk++){
        const int n0 = chunk*32;
        __syncthreads();
        for (int idx = tid; idx < 2048; idx += 256){
            int nl = idx >> 6, i = idx & 63;
            int bn = b*512 + n0 + nl;
            float s = sm[bn*96 + t*8 + (i>>3)];
            wvT[i][nl]  = s * vb[bn*64 + i];
            xw0s[i][nl] = xw0[bn*64 + i];
        }
        __syncthreads();
        float acc[4][2] = {};
#pragma unroll
        for (int i = 0; i < 64; i++){
            float4 a = *(const float4*)&taw1s[i][ty*4];
            float b0 = wvT[i][tx*2], b1 = wvT[i][tx*2+1];
            acc[0][0]+=a.x*b0; acc[0][1]+=a.x*b1;
            acc[1][0]+=a.y*b0; acc[1][1]+=a.y*b1;
            acc[2][0]+=a.z*b0; acc[2][1]+=a.z*b1;
            acc[3][0]+=a.w*b0; acc[3][1]+=a.w*b1;
        }
#pragma unroll
        for (int oi = 0; oi < 4; oi++){
            int o = ty*4 + oi;
            float bias = tab[o];
            float vx = acc[oi][0] + xw0s[o][tx*2]   + bias;
            float vy = acc[oi][1] + xw0s[o][tx*2+1] + bias;
            uint32_t u = packh2(vx, vy);
            *(uint32_t*)&dehf[baseH + (long)o*512 + n0 + tx*2] = u;
        }
    }
}

// ===========================================================================
extern "C" void kernel_launch(void* const* d_in, const int* in_sizes, int n_in,
                              void* d_out, int out_size)
{
    const float* h_n  = (const float*)d_in[2];
    const float* ne1  = (const float*)d_in[3];
    const float* ne2  = (const float*)d_in[4];
    const float* E    = (const float*)d_in[5];
    const float* Wq   = (const float*)d_in[6];
    const float* bq   = (const float*)d_in[7];
    const float* Wk   = (const float*)d_in[8];
    const float* bk   = (const float*)d_in[9];
    const float* Wv   = (const float*)d_in[10];
    const float* bv   = (const float*)d_in[11];
    const float* taw  = (const float*)d_in[12];
    const float* tab  = (const float*)d_in[13];
    const float* gwp  = (const float*)d_in[14];
    const float* gw   = (const float*)d_in[15];
    const float* gbp  = (const float*)d_in[16];
    const float* gb   = (const float*)d_in[17];
    const float* uwp  = (const float*)d_in[18];
    const float* uw   = (const float*)d_in[19];
    const float* ubp  = (const float*)d_in[20];
    const float* ub   = (const float*)d_in[21];
    const float* outw = (const float*)d_in[22];
    const float* outb = (const float*)d_in[23];
    float* out = (float*)d_out;

    float *Arm, *kb2, *vb2, *xq, *xw0, *sm;
    float *b1, *b2, *wp1, *w1b, *wp2, *w2b;
    __half *Ahf, *S2hf, *xg1, *xg2, *W1hf, *W2hf, *rgs;
    cudaGetSymbolAddress((void**)&Arm,  g_Arm);
    cudaGetSymbolAddress((void**)&Ahf,  g_Ahf);
    cudaGetSymbolAddress((void**)&S2hf, g_S2hf);
    cudaGetSymbolAddress((void**)&kb2,  g_kb);
    cudaGetSymbolAddress((void**)&vb2,  g_vb);
    cudaGetSymbolAddress((void**)&xq,   g_xq);
    cudaGetSymbolAddress((void**)&xw0,  g_xw0);
    cudaGetSymbolAddress((void**)&sm,   g_sm);
    cudaGetSymbolAddress((void**)&xg1,  g_xg1);
    cudaGetSymbolAddress((void**)&xg2,  g_xg2);
    cudaGetSymbolAddress((void**)&W1hf, g_W1hf);
    cudaGetSymbolAddress((void**)&W2hf, g_W2hf);
    cudaGetSymbolAddress((void**)&b1,   g_b1);
    cudaGetSymbolAddress((void**)&b2,   g_b2);
    cudaGetSymbolAddress((void**)&wp1,  g_wp1);
    cudaGetSymbolAddress((void**)&w1b,  g_w1b);
    cudaGetSymbolAddress((void**)&wp2,  g_wp2);
    cudaGetSymbolAddress((void**)&w2b,  g_w2b);
    cudaGetSymbolAddress((void**)&rgs,  g_rgs);

    const int SUPP2_SMEM = 6*128*36*4;                       // 110592
    const int CTR1_SMEM  = 128*200*2 + 2*32*136*2;           // 68608
    const int CTR2_SMEM  = 64*132*4*2 + 2*128*4;             // 68608
    cudaFuncSetAttribute(k_supp2_hmma, cudaFuncAttributeMaxDynamicSharedMemorySize, SUPP2_SMEM);
    cudaFuncSetAttribute(k_ctr1_fused, cudaFuncAttributeMaxDynamicSharedMemorySize, CTR1_SMEM);
    cudaFuncSetAttribute(k_ctr2_fused, cudaFuncAttributeMaxDynamicSharedMemorySize, CTR2_SMEM);

    // 1. adjacency
    k_A<<<512, 512>>>(E, Arm, Ahf);
    // 2. S2 = 2*A@A - I (fp16, diag fused)
    gemm_rr_k<64,64,16,4,4,256,2,1><<<dim3(8,8,1), 256>>>(
        Arm, 0, Arm, 0, S2hf, 0, 512, 512, 512, 512, nullptr, 2.f);
    // 3. X projections (k/v bias computed inline)
    k_proj<<<dim3(512,4), 256>>>(h_n, ne1, Wq, Wk, Wv, taw, bk, bv,
                                 xq, kb2, vb2, xw0);
    // 4. attention softmax (aq computed inline)
    k_attn<<<dim3(16,64), 256>>>(ne2, Wq, bq, xq, kb2, sm);
    // 5. de build -> xg1 rows 0-63
    k_debuild<<<dim3(64,12), 256>>>(sm, vb2, xw0, taw, tab, xg1);
    // 6. GCN1 supports  <-- ncu -s 5 captures this launch
    k_supp2_hmma<<<dim3(4,384), 256, SUPP2_SMEM>>>(xg1, Ahf, S2hf,
                                                   xg1 + 64*512, xg1 + 128*512);
    // 7-12. weight packing / per-bt W build (independent of supports)
    k_pack<<<dim3(3072,2), 256>>>(gwp, gw, wp1, w1b, 128);
    k_pack<<<dim3(1536,2), 256>>>(uwp, uw, wp2, w2b, 64);
    k_bvec<<<768, 128>>>(ne2, gbp, gb, b1, 128);
    k_bvec<<<768, 64 >>>(ne2, ubp, ub, b2, 64);
    gemm_rr_k<64,64,16,4,4,256,2,0><<<dim3(384,12,1), 256>>>(
        ne2, 0, wp1, 0, W1hf, 0, 32, 24576, 24576, 32, w1b, 1.f);
    gemm_rr_k<64,64,16,4,4,256,2,0><<<dim3(192,12,1), 256>>>(
        ne2, 0, wp2, 0, W2hf, 0, 32, 12288, 12288, 32, w2b, 1.f);
    // 13. GCN1 contraction + gate
    k_ctr1_fused<<<dim3(4,768), 256, CTR1_SMEM>>>(xg1, W1hf, b1, xg2, rgs);
    // 14. GCN2 supports
    k_supp2_hmma<<<dim3(4,384), 256, SUPP2_SMEM>>>(xg2, Ahf, S2hf,
                                                   xg2 + 64*512, xg2 + 128*512);
    // 15. GCN2 contraction + blend + output head
    k_ctr2_fused<<<dim3(4,768), 256, CTR2_SMEM>>>(xg2, W2hf, b2, xg1, rgs,
                                                  outw, outb, out);
}